// round 7
// baseline (speedup 1.0000x reference)
#include <cuda_runtime.h>

#define NN 16384
#define NE 65536
#define NG 64
#define NZ 10
#define CH 128

typedef unsigned long long u64;

// ---------------- scratch (device globals; no allocations) ----------------
__device__ __align__(16) float d_sh[NE * 16];
__device__ __align__(16) float d_rad[NE * 8];
__device__ __align__(16) float d_tpw[(size_t)NE * 512];
__device__ __align__(16) float d_up[NN * CH];
__device__ __align__(16) float d_scb[NN * CH];
__device__ __align__(16) float d_msg[(size_t)NN * 16 * CH];
__device__ __align__(16) float d_Amat[(size_t)NN * 16 * CH];
__device__ __align__(16) float d_nfA[NN * CH];
__device__ __align__(16) float d_nfB[NN * CH];
__device__ int   d_species[NN];
__device__ int   d_count[NN];
__device__ int   d_offsets[NN + 1];
__device__ int   d_cursor[NN];
__device__ int   d_perm[NE];
__device__ int   d_scount[NZ];
__device__ int   d_soff[NZ + 1];
__device__ int   d_scursor[NZ];
__device__ int   d_sperm[NN];
__device__ float d_gcnt[NG];

__device__ __forceinline__ float silu(float x) {
    return x / (1.f + __expf(-x));
}

// ---- f32x2 packed math helpers ----
__device__ __forceinline__ u64 pk2(float a, float b) {
    u64 r; asm("mov.b64 %0, {%1, %2};" : "=l"(r) : "f"(a), "f"(b)); return r;
}
__device__ __forceinline__ void fma2(u64 &d, u64 a, u64 b) {
    asm("fma.rn.f32x2 %0, %1, %2, %0;" : "+l"(d) : "l"(a), "l"(b));
}
__device__ __forceinline__ u64 mul2(u64 a, u64 b) {
    u64 r; asm("mul.rn.f32x2 %0, %1, %2;" : "=l"(r) : "l"(a), "l"(b)); return r;
}
__device__ __forceinline__ float2 unpk(u64 v) {
    float2 r; asm("mov.b64 {%0, %1}, %2;" : "=f"(r.x), "=f"(r.y) : "l"(v)); return r;
}
__device__ __forceinline__ float hsum2(u64 v) {
    float2 s = unpk(v); return s.x + s.y;
}

// Conflict-free pair-interleave staging:
// Wp[pp*256 + 2k + c01] = W[2pp + c01][k]  (read side: LDS.64 at [pp*256+2k])
// Writer: float4 op -> pp = op>>6, j = op&63:
//   (W[2pp][2j], W[2pp+1][2j], W[2pp][2j+1], W[2pp+1][2j+1])
// LDG.64 coalesced, STS.128 consecutive -> zero bank conflicts.
__device__ __forceinline__ void load_w_pairs(float* Wp, const float* W, int tid, int nthr) {
    for (int op = tid; op < 4096; op += nthr) {
        int pp = op >> 6, j = op & 63;
        float2 a = *(const float2*)&W[(2 * pp) * CH + 2 * j];
        float2 b = *(const float2*)&W[(2 * pp + 1) * CH + 2 * j];
        ((float4*)Wp)[op] = make_float4(a.x, b.x, a.y, b.y);
    }
}

// same for 64-wide matrices (rows x 64), nfl4 = rows*64/4
__device__ __forceinline__ void load_w_pairs64(float* Wp, const float* W, int nfl4,
                                               int tid, int nthr) {
    for (int op = tid; op < nfl4; op += nthr) {
        int pp = op >> 5, j = op & 31;
        float2 a = *(const float2*)&W[(2 * pp) * 64 + 2 * j];
        float2 b = *(const float2*)&W[(2 * pp + 1) * 64 + 2 * j];
        ((float4*)Wp)[op] = make_float4(a.x, b.x, a.y, b.y);
    }
}

// ---------------- init / zero ----------------
__global__ void k_zero() {
    int i = blockIdx.x * blockDim.x + threadIdx.x;
    if (i < NN) d_count[i] = 0;
    if (i < NZ) d_scount[i] = 0;
    if (i < NG) d_gcnt[i] = 0.f;
}

__global__ void k_node_init(const float* __restrict__ x,
                            const float* __restrict__ W_embed) {
    int tid = blockIdx.x * blockDim.x + threadIdx.x;
    if (tid >= NN * CH) return;
    int n = tid >> 7, k = tid & 127;
    const float* xr = x + n * NZ;
    int s = 0;
    float best = xr[0];
#pragma unroll
    for (int z = 1; z < NZ; z++) {
        float v = xr[z];
        if (v > best) { best = v; s = z; }
    }
    if (k == 0) {
        d_species[n] = s;
        atomicAdd(&d_scount[s], 1);
    }
    d_nfA[tid] = W_embed[s * CH + k] * 0.31622776601683794f;
}

// ---------------- edge geometry: SH + radial basis ----------------
__global__ void k_edge_geom(const float* __restrict__ pos,
                            const int* __restrict__ edge_index) {
    int e = blockIdx.x * blockDim.x + threadIdx.x;
    if (e >= NE) return;
    int j = edge_index[e];
    int i = edge_index[NE + e];
    float dx = pos[j * 3 + 0] - pos[i * 3 + 0];
    float dy = pos[j * 3 + 1] - pos[i * 3 + 1];
    float dz = pos[j * 3 + 2] - pos[i * 3 + 2];
    float r2 = dx * dx + dy * dy + dz * dz + 1e-12f;
    float r = sqrtf(r2);
    float inv = 1.f / r;
    float X = dx * inv, Y = dy * inv, Z = dz * inv;
    float x2 = X * X, y2 = Y * Y, z2 = Z * Z;

    const float s3 = 1.7320508075688772f;
    const float s15 = 3.872983346207417f;
    const float s5 = 2.23606797749979f;
    const float s35_8 = 2.091650066335189f;
    const float s105 = 10.246950765959598f;
    const float s21_8 = 1.6201851746019651f;
    const float s7 = 2.6457513110645907f;

    float sh[16];
    sh[0] = 1.f;
    sh[1] = s3 * X; sh[2] = s3 * Y; sh[3] = s3 * Z;
    sh[4] = s15 * X * Y;
    sh[5] = s15 * Y * Z;
    sh[6] = 0.5f * s5 * (3.f * z2 - 1.f);
    sh[7] = s15 * X * Z;
    sh[8] = 0.5f * s15 * (x2 - y2);
    sh[9] = s35_8 * Y * (3.f * x2 - y2);
    sh[10] = s105 * X * Y * Z;
    sh[11] = s21_8 * Y * (5.f * z2 - 1.f);
    sh[12] = 0.5f * s7 * Z * (5.f * z2 - 3.f);
    sh[13] = s21_8 * X * (5.f * z2 - 1.f);
    sh[14] = 0.5f * s105 * Z * (x2 - y2);
    sh[15] = s35_8 * X * (x2 - 3.f * y2);
#pragma unroll
    for (int q = 0; q < 4; q++)
        *(float4*)&d_sh[e * 16 + q * 4] = *(float4*)&sh[q * 4];

    float u = r * 0.2f;
    float u2 = u * u;
    float u5 = u2 * u2 * u;
    float f = 1.f - 21.f * u5 + 35.f * u5 * u - 15.f * u5 * u2;
    if (u >= 1.f) f = 0.f;
    float coef = 0.6324555320336759f * inv * f;
    float rad[8];
#pragma unroll
    for (int nb = 1; nb <= 8; nb++)
        rad[nb - 1] = coef * sinpif((float)nb * u);
    *(float4*)&d_rad[e * 8] = *(float4*)&rad[0];
    *(float4*)&d_rad[e * 8 + 4] = *(float4*)&rad[4];
}

// ---------------- CSR build ----------------
__global__ void k_hist(const int* __restrict__ edge_index) {
    int e = blockIdx.x * blockDim.x + threadIdx.x;
    if (e >= NE) return;
    atomicAdd(&d_count[edge_index[NE + e]], 1);
}

__global__ void k_scan() {
    __shared__ int sh[1024];
    int T = threadIdx.x;
    int base = T * 16;
    int loc[16];
    int s = 0;
#pragma unroll
    for (int q = 0; q < 16; q++) { loc[q] = d_count[base + q]; s += loc[q]; }
    sh[T] = s;
    __syncthreads();
    for (int off = 1; off < 1024; off <<= 1) {
        int v = (T >= off) ? sh[T - off] : 0;
        __syncthreads();
        sh[T] += v;
        __syncthreads();
    }
    int excl = sh[T] - s;
#pragma unroll
    for (int q = 0; q < 16; q++) {
        d_offsets[base + q] = excl;
        d_cursor[base + q] = excl;
        excl += loc[q];
    }
    if (T == 1023) d_offsets[NN] = sh[1023];
    if (T == 0) {
        int a = 0;
        for (int z = 0; z < NZ; z++) {
            d_soff[z] = a; d_scursor[z] = a; a += d_scount[z];
        }
        d_soff[NZ] = a;
    }
}

__global__ void k_scatter(const int* __restrict__ edge_index) {
    int e = blockIdx.x * blockDim.x + threadIdx.x;
    if (e >= NE) return;
    int i = edge_index[NE + e];
    int p = atomicAdd(&d_cursor[i], 1);
    d_perm[p] = e;
}

__global__ void k_sscatter() {
    int n = blockIdx.x * blockDim.x + threadIdx.x;
    if (n >= NN) return;
    int s = d_species[n];
    int p = atomicAdd(&d_scursor[s], 1);
    d_sperm[p] = n;
}

// ---------------- up = nf @ W_up / sqrt(128) ----------------
__global__ void __launch_bounds__(256) k_up(int t, const float* __restrict__ W_up) {
    extern __shared__ float sm[];
    float* Wsh = sm;           // 16384 pair-interleaved
    float* msh = sm + 16384;   // 32 rows x 128
    int tid = threadIdx.x;
    int k = tid & 127, h = tid >> 7;
    load_w_pairs(Wsh, W_up + t * CH * CH, tid, 256);
    const float* nf = t ? d_nfB : d_nfA;
    int n0 = blockIdx.x * 32;
    for (int i = tid; i < 1024; i += 256)
        ((float4*)msh)[i] = ((const float4*)nf)[n0 * 32 + i];
    __syncthreads();
    u64 acc[16];
#pragma unroll
    for (int q = 0; q < 16; q++) acc[q] = 0ull;
    for (int pp = 0; pp < 64; pp += 2) {
        u64 w01 = *(const u64*)&Wsh[pp * 256 + 2 * k];
        u64 w23 = *(const u64*)&Wsh[(pp + 1) * 256 + 2 * k];
#pragma unroll
        for (int q = 0; q < 16; q++) {
            ulonglong2 mv = *(const ulonglong2*)&msh[(h * 16 + q) * CH + 2 * pp];
            fma2(acc[q], mv.x, w01);
            fma2(acc[q], mv.y, w23);
        }
    }
#pragma unroll
    for (int q = 0; q < 16; q++)
        d_up[(n0 + h * 16 + q) * CH + k] = hsum2(acc[q]) * 0.08838834764831845f;
}

// ---------------- sc (species-bucketed skip) ----------------
__global__ void __launch_bounds__(128) k_sc(int t, const float* __restrict__ W_skip) {
    int z = blockIdx.y;
    int lo = d_soff[z], hi = d_soff[z + 1];
    int n0 = lo + blockIdx.x * 16;
    if (n0 >= hi) return;
    extern __shared__ float sm[];
    float* Wsh = sm;
    float* msh = sm + 16384;
    __shared__ int offs[16];
    int k = threadIdx.x;
    load_w_pairs(Wsh, W_skip + ((size_t)t * NZ + z) * CH * CH, k, 128);
    int cnt = min(16, hi - n0);
    if (k < cnt) offs[k] = d_sperm[n0 + k] * CH;
    __syncthreads();
    const float* nf = t ? d_nfB : d_nfA;
    for (int i = k; i < cnt * 32; i += 128) {
        int r = i >> 5;
        ((float4*)msh)[i] = *(const float4*)(nf + offs[r] + ((i & 31) << 2));
    }
    __syncthreads();
    u64 acc[16];
#pragma unroll
    for (int q = 0; q < 16; q++) acc[q] = 0ull;
    for (int pp = 0; pp < 64; pp += 2) {
        u64 w01 = *(const u64*)&Wsh[pp * 256 + 2 * k];
        u64 w23 = *(const u64*)&Wsh[(pp + 1) * 256 + 2 * k];
#pragma unroll
        for (int q = 0; q < 16; q++) {
            ulonglong2 mv = *(const ulonglong2*)&msh[q * CH + 2 * pp];
            fma2(acc[q], mv.x, w01);
            fma2(acc[q], mv.y, w23);
        }
    }
    for (int q = 0; q < cnt; q++)
        d_scb[offs[q] + k] = hsum2(acc[q]) * 0.027950849718747372f;
}

// ---------------- radial MLP: 512 threads, 32-edge tiles ----------------
// smem floats: w0p 512 | w1p 4096 | w2p 4096 | w3 32768 | radT 256 |
//              hA 2048 | hB 2048 | hdup 64*72=4608  -> 50432 fl = 197 KB
__global__ void __launch_bounds__(512) k_radial(
    int t, const float* __restrict__ Wr0, const float* __restrict__ Wr1,
    const float* __restrict__ Wr2, const float* __restrict__ Wr3) {
    extern __shared__ float sm[];
    float* w0p  = sm;             // 512
    float* w1p  = w0p + 512;      // 4096
    float* w2p  = w1p + 4096;     // 4096
    float* w3   = w2p + 4096;     // 32768
    float* radT = w3 + 32768;     // 256
    float* hA   = radT + 256;     // 2048
    float* hB   = hA + 2048;      // 2048
    float* hdup = hB + 2048;      // 4608 (stride 72 per c-row)

    const float* W0 = Wr0 + t * 8 * 64;
    const float* W1 = Wr1 + t * 64 * 64;
    const float* W2 = Wr2 + t * 64 * 64;
    const float* W3 = Wr3 + t * 64 * 512;
    int tid = threadIdx.x;

    load_w_pairs64(w0p, W0, 128, tid, 512);
    load_w_pairs64(w1p, W1, 1024, tid, 512);
    load_w_pairs64(w2p, W2, 1024, tid, 512);
    for (int i = tid; i < 8192; i += 512)
        ((float4*)w3)[i] = ((const float4*)W3)[i];

    int o  = tid & 63;            // layers 0-2: output column
    int eg = tid >> 6;            // 0..7 -> local edges 4eg..4eg+3
    int le = tid & 31;            // layer 3: lane = local edge
    int oq = tid >> 5;            // 0..15 -> outputs oq*32..+31
    const u64 scale2 = pk2(0.125f, 0.125f);

    for (int tile = 0; tile < 4; tile++) {
        int ebase = blockIdx.x * 128 + tile * 32;
        // stage radial features (32 edges x 8 = 256 floats)
        if (tid < 64)
            ((float4*)radT)[tid] = ((const float4*)(d_rad + (size_t)ebase * 8))[tid];
        __syncthreads();
        // layer 0: 8 -> 64 (4 edges per thread)
        {
            u64 a0 = 0ull, a1 = 0ull, a2 = 0ull, a3 = 0ull;
#pragma unroll
            for (int cp = 0; cp < 4; cp++) {
                u64 w = *(const u64*)&w0p[cp * 128 + 2 * o];
                fma2(a0, *(const u64*)&radT[(4 * eg + 0) * 8 + 2 * cp], w);
                fma2(a1, *(const u64*)&radT[(4 * eg + 1) * 8 + 2 * cp], w);
                fma2(a2, *(const u64*)&radT[(4 * eg + 2) * 8 + 2 * cp], w);
                fma2(a3, *(const u64*)&radT[(4 * eg + 3) * 8 + 2 * cp], w);
            }
            hA[(4 * eg + 0) * 64 + o] = silu(hsum2(a0) * 0.3535533905932738f);
            hA[(4 * eg + 1) * 64 + o] = silu(hsum2(a1) * 0.3535533905932738f);
            hA[(4 * eg + 2) * 64 + o] = silu(hsum2(a2) * 0.3535533905932738f);
            hA[(4 * eg + 3) * 64 + o] = silu(hsum2(a3) * 0.3535533905932738f);
        }
        __syncthreads();
        // layer 1: 64 -> 64
        {
            u64 a0 = 0ull, a1 = 0ull, a2 = 0ull, a3 = 0ull;
#pragma unroll 8
            for (int cp = 0; cp < 32; cp++) {
                u64 w = *(const u64*)&w1p[cp * 128 + 2 * o];
                fma2(a0, *(const u64*)&hA[(4 * eg + 0) * 64 + 2 * cp], w);
                fma2(a1, *(const u64*)&hA[(4 * eg + 1) * 64 + 2 * cp], w);
                fma2(a2, *(const u64*)&hA[(4 * eg + 2) * 64 + 2 * cp], w);
                fma2(a3, *(const u64*)&hA[(4 * eg + 3) * 64 + 2 * cp], w);
            }
            hB[(4 * eg + 0) * 64 + o] = silu(hsum2(a0) * 0.125f);
            hB[(4 * eg + 1) * 64 + o] = silu(hsum2(a1) * 0.125f);
            hB[(4 * eg + 2) * 64 + o] = silu(hsum2(a2) * 0.125f);
            hB[(4 * eg + 3) * 64 + o] = silu(hsum2(a3) * 0.125f);
        }
        __syncthreads();
        // layer 2: 64 -> 64, write DUPLICATED transposed: hdup[o][2e]=(v,v)
        {
            u64 a0 = 0ull, a1 = 0ull, a2 = 0ull, a3 = 0ull;
#pragma unroll 8
            for (int cp = 0; cp < 32; cp++) {
                u64 w = *(const u64*)&w2p[cp * 128 + 2 * o];
                fma2(a0, *(const u64*)&hB[(4 * eg + 0) * 64 + 2 * cp], w);
                fma2(a1, *(const u64*)&hB[(4 * eg + 1) * 64 + 2 * cp], w);
                fma2(a2, *(const u64*)&hB[(4 * eg + 2) * 64 + 2 * cp], w);
                fma2(a3, *(const u64*)&hB[(4 * eg + 3) * 64 + 2 * cp], w);
            }
            float v0 = silu(hsum2(a0) * 0.125f);
            float v1 = silu(hsum2(a1) * 0.125f);
            float v2 = silu(hsum2(a2) * 0.125f);
            float v3 = silu(hsum2(a3) * 0.125f);
            *(u64*)&hdup[o * 72 + 2 * (4 * eg + 0)] = pk2(v0, v0);
            *(u64*)&hdup[o * 72 + 2 * (4 * eg + 1)] = pk2(v1, v1);
            *(u64*)&hdup[o * 72 + 2 * (4 * eg + 2)] = pk2(v2, v2);
            *(u64*)&hdup[o * 72 + 2 * (4 * eg + 3)] = pk2(v3, v3);
        }
        __syncthreads();
        // layer 3: 64 -> 512; thread = (edge le, 32 outputs oq*32..+31)
        // w3 loads broadcast across warp; h is one LDS.64 (pre-duplicated pair)
        {
            u64 acc[16];
#pragma unroll
            for (int q = 0; q < 16; q++) acc[q] = 0ull;
#pragma unroll 2
            for (int c = 0; c < 64; c++) {
                u64 h = *(const u64*)&hdup[c * 72 + 2 * le];
                const float* wr = &w3[c * 512 + oq * 32];
#pragma unroll
                for (int q = 0; q < 8; q++) {
                    ulonglong2 w = *(const ulonglong2*)&wr[q * 4];
                    fma2(acc[2 * q + 0], h, w.x);
                    fma2(acc[2 * q + 1], h, w.y);
                }
            }
            size_t gbase = (size_t)(ebase + le) * 512 + oq * 32;
#pragma unroll
            for (int q = 0; q < 8; q++) {
                ulonglong2 ov;
                ov.x = mul2(acc[2 * q + 0], scale2);
                ov.y = mul2(acc[2 * q + 1], scale2);
                *(ulonglong2*)&d_tpw[gbase + q * 4] = ov;
            }
        }
        __syncthreads();
    }
}

// ---------------- gather: msg[n,m,k] (CSR, staged headers) --------
__global__ void __launch_bounds__(128) k_gather(const int* __restrict__ edge_index) {
    int n = blockIdx.x;
    int k = threadIdx.x, lane = k & 31;
    int lo = d_offsets[n], hi = d_offsets[n + 1];
    __shared__ int se[32];
    __shared__ int sj[32];
    float acc[16];
#pragma unroll
    for (int m = 0; m < 16; m++) acc[m] = 0.f;
    for (int base = lo; base < hi; base += 32) {
        int cnt = min(32, hi - base);
        if (k < cnt) {
            int e = d_perm[base + k];
            se[k] = e;
            sj[k] = edge_index[e];
        }
        __syncthreads();
#pragma unroll 2
        for (int p = 0; p < cnt; p++) {
            int e = se[p];
            int j = sj[p];
            float shl = (lane < 16) ? d_sh[e * 16 + lane] : 0.f;
            float u = d_up[j * CH + k];
            const float* tp = d_tpw + (size_t)e * 512;
            float v0 = u * tp[k];
            float v1 = u * tp[CH + k];
            float v2 = u * tp[2 * CH + k];
            float v3 = u * tp[3 * CH + k];
            acc[0] += __shfl_sync(0xffffffffu, shl, 0) * v0;
#pragma unroll
            for (int m = 1; m < 4; m++) acc[m] += __shfl_sync(0xffffffffu, shl, m) * v1;
#pragma unroll
            for (int m = 4; m < 9; m++) acc[m] += __shfl_sync(0xffffffffu, shl, m) * v2;
#pragma unroll
            for (int m = 9; m < 16; m++) acc[m] += __shfl_sync(0xffffffffu, shl, m) * v3;
        }
        __syncthreads();
    }
#pragma unroll
    for (int m = 0; m < 16; m++)
        d_msg[((size_t)n * 16 + m) * CH + k] = acc[m] * 0.1f;
}

// ---------------- A = msg @ W_lin[L(m)] / sqrt(128) ----------------
__global__ void __launch_bounds__(256) k_wlin(int t, const float* __restrict__ W_lin) {
    int l = blockIdx.y;
    const int ms = (l == 0) ? 0 : (l == 1) ? 1 : (l == 2) ? 4 : 9;
    const int nm = (l == 0) ? 1 : (l == 1) ? 3 : (l == 2) ? 5 : 7;
    extern __shared__ float sm[];
    float* Wsh = sm;
    float* msh = sm + 16384;
    __shared__ int offs[56];
    int tid = threadIdx.x;
    int k = tid & 127, h = tid >> 7;
    load_w_pairs(Wsh, W_lin + ((size_t)(t * 4 + l)) * CH * CH, tid, 256);
    int n0 = blockIdx.x * 8;
    int rows = 8 * nm;
    if (tid < rows)
        offs[tid] = ((n0 + tid / nm) * 16 + ms + tid % nm) * CH;
    __syncthreads();
    for (int i = tid; i < rows * 32; i += 256) {
        int r = i >> 5;
        ((float4*)msh)[i] = *(const float4*)(d_msg + offs[r] + ((i & 31) << 2));
    }
    __syncthreads();
    for (int rb = h * 8; rb < rows; rb += 16) {
        u64 acc[8];
#pragma unroll
        for (int q = 0; q < 8; q++) acc[q] = 0ull;
        for (int pp = 0; pp < 64; pp += 2) {
            u64 w01 = *(const u64*)&Wsh[pp * 256 + 2 * k];
            u64 w23 = *(const u64*)&Wsh[(pp + 1) * 256 + 2 * k];
#pragma unroll
            for (int q = 0; q < 8; q++) {
                ulonglong2 mv = *(const ulonglong2*)&msh[(rb + q) * CH + 2 * pp];
                fma2(acc[q], mv.x, w01);
                fma2(acc[q], mv.y, w23);
            }
        }
#pragma unroll
        for (int q = 0; q < 8; q++)
            d_Amat[offs[rb + q] + k] = hsum2(acc[q]) * 0.08838834764831845f;
    }
}

// ---------------- nonlinearity + prodlin + skip -> new node feats ----------
__global__ void __launch_bounds__(256) k_final(int t, const float* __restrict__ Wp1,
                        const float* __restrict__ Wp2,
                        const float* __restrict__ Wp3,
                        const float* __restrict__ W_prodlin) {
    extern __shared__ float sm[];
    float* Wsh = sm;          // 16384 pair-interleaved
    float* bsh = sm + 16384;  // 16*128
    int tid = threadIdx.x;
    int k = tid & 127, h = tid >> 7;
    load_w_pairs(Wsh, W_prodlin + t * CH * CH, tid, 256);
    int n0 = blockIdx.x * 16;
    for (int rr = 0; rr < 8; rr++) {
        int r = h * 8 + rr;
        int n = n0 + r;
        const float* Ar = d_Amat + (size_t)n * 16 * CH;
        float A0 = Ar[k];
        float i0 = A0 * A0, i1 = 0.f, i2 = 0.f, i3 = 0.f;
#pragma unroll
        for (int m = 1; m < 4; m++) { float a = Ar[m * CH + k]; i1 += a * a; }
#pragma unroll
        for (int m = 4; m < 9; m++) { float a = Ar[m * CH + k]; i2 += a * a; }
#pragma unroll
        for (int m = 9; m < 16; m++) { float a = Ar[m * CH + k]; i3 += a * a; }
        int s = d_species[n];
        const float* p1 = Wp1 + ((size_t)t * NZ + s) * CH;
        const float* p2 = Wp2 + ((size_t)t * NZ + s) * 4 * CH;
        const float* p3 = Wp3 + ((size_t)t * NZ + s) * 4 * CH;
        float s2 = p2[k] * i0 + p2[CH + k] * i1 + p2[2 * CH + k] * i2 + p2[3 * CH + k] * i3;
        float s3v = p3[k] * i0 + p3[CH + k] * i1 + p3[2 * CH + k] * i2 + p3[3 * CH + k] * i3;
        bsh[r * CH + k] = p1[k] * A0 + s2 + s3v * A0;
    }
    __syncthreads();
    u64 acc[8];
#pragma unroll
    for (int q = 0; q < 8; q++) acc[q] = 0ull;
    for (int pp = 0; pp < 64; pp += 2) {
        u64 w01 = *(const u64*)&Wsh[pp * 256 + 2 * k];
        u64 w23 = *(const u64*)&Wsh[(pp + 1) * 256 + 2 * k];
#pragma unroll
        for (int q = 0; q < 8; q++) {
            ulonglong2 mv = *(const ulonglong2*)&bsh[(h * 8 + q) * CH + 2 * pp];
            fma2(acc[q], mv.x, w01);
            fma2(acc[q], mv.y, w23);
        }
    }
    float* nfo = (t == 0) ? d_nfB : d_nfA;
#pragma unroll
    for (int q = 0; q < 8; q++)
        nfo[(n0 + h * 8 + q) * CH + k] = hsum2(acc[q]) * 0.08838834764831845f +
                                         d_scb[(n0 + h * 8 + q) * CH + k];
}

// ---------------- graph mean pooling ----------------
__global__ void k_env(const int* __restrict__ batch_idx, float* __restrict__ out) {
    int tid = blockIdx.x * blockDim.x + threadIdx.x;
    if (tid >= NN * CH) return;
    int n = tid >> 7, k = tid & 127;
    int g = batch_idx[n];
    atomicAdd(&out[g * CH + k], d_nfA[tid]);
    if (k == 0) atomicAdd(&d_gcnt[g], 1.f);
}

__global__ void k_div(float* __restrict__ out) {
    int i = blockIdx.x * blockDim.x + threadIdx.x;
    if (i >= NG * CH) return;
    int g = i >> 7;
    out[i] /= fmaxf(d_gcnt[g], 1.f);
}

// ---------------- launcher ----------------
extern "C" void kernel_launch(void* const* d_in, const int* in_sizes, int n_in,
                              void* d_out, int out_size) {
    const float* x        = (const float*)d_in[0];
    const float* pos      = (const float*)d_in[1];
    const float* W_embed  = (const float*)d_in[2];
    const float* W_up     = (const float*)d_in[3];
    const float* Wr0      = (const float*)d_in[4];
    const float* Wr1      = (const float*)d_in[5];
    const float* Wr2      = (const float*)d_in[6];
    const float* Wr3      = (const float*)d_in[7];
    const float* W_lin    = (const float*)d_in[8];
    const float* W_skip   = (const float*)d_in[9];
    const float* Wp1      = (const float*)d_in[10];
    const float* Wp2      = (const float*)d_in[11];
    const float* Wp3      = (const float*)d_in[12];
    const float* W_prodlin= (const float*)d_in[13];
    const int*   edge_index = (const int*)d_in[14];
    const int*   batch_idx  = (const int*)d_in[15];
    float* out = (float*)d_out;

    const int SM_UP    = (16384 + 4096) * 4;
    const int SM_SC    = (16384 + 2048) * 4;
    const int SM_RAD   = 50432 * 4;  // 197 KB
    const int SM_WLIN  = (16384 + 56 * CH) * 4;
    const int SM_FINAL = (16384 + 2048) * 4;
    cudaFuncSetAttribute(k_up,     cudaFuncAttributeMaxDynamicSharedMemorySize, SM_UP);
    cudaFuncSetAttribute(k_sc,     cudaFuncAttributeMaxDynamicSharedMemorySize, SM_SC);
    cudaFuncSetAttribute(k_radial, cudaFuncAttributeMaxDynamicSharedMemorySize, SM_RAD);
    cudaFuncSetAttribute(k_wlin,   cudaFuncAttributeMaxDynamicSharedMemorySize, SM_WLIN);
    cudaFuncSetAttribute(k_final,  cudaFuncAttributeMaxDynamicSharedMemorySize, SM_FINAL);

    k_zero<<<(NN + 255) / 256, 256>>>();
    k_node_init<<<(NN * CH) / 256, 256>>>(x, W_embed);
    k_edge_geom<<<NE / 256, 256>>>(pos, edge_index);
    // radial t=0 placed 4th so ncu profiles it
    k_radial<<<NE / 128, 512, SM_RAD>>>(0, Wr0, Wr1, Wr2, Wr3);
    k_hist<<<NE / 256, 256>>>(edge_index);
    k_scan<<<1, 1024>>>();
    k_scatter<<<NE / 256, 256>>>(edge_index);
    k_sscatter<<<NN / 256, 256>>>();

    for (int t = 0; t < 2; t++) {
        k_up<<<NN / 32, 256, SM_UP>>>(t, W_up);
        k_sc<<<dim3(NN / 16, NZ), 128, SM_SC>>>(t, W_skip);
        if (t == 1)
            k_radial<<<NE / 128, 512, SM_RAD>>>(t, Wr0, Wr1, Wr2, Wr3);
        k_gather<<<NN, 128>>>(edge_index);
        k_wlin<<<dim3(NN / 8, 4), 256, SM_WLIN>>>(t, W_lin);
        k_final<<<NN / 16, 256, SM_FINAL>>>(t, Wp1, Wp2, Wp3, W_prodlin);
    }

    cudaMemsetAsync(d_out, 0, (size_t)out_size * sizeof(float));
    k_env<<<(NN * CH) / 256, 256>>>(batch_idx, out);
    k_div<<<(NG * CH + 255) / 256, 256>>>(out);
}

// round 10
// speedup vs baseline: 1.0397x; 1.0397x over previous
#include <cuda_runtime.h>

#define NN 16384
#define NE 65536
#define NG 64
#define NZ 10
#define CH 128

typedef unsigned long long u64;

// ---------------- scratch (device globals; no allocations) ----------------
__device__ __align__(16) float d_sh[NE * 16];
__device__ __align__(16) float d_rad[NE * 8];
__device__ __align__(16) float d_tpw[(size_t)NE * 512];
__device__ __align__(16) float d_up[NN * CH];
__device__ __align__(16) float d_scb[NN * CH];
__device__ __align__(16) float d_nfA[NN * CH];
__device__ __align__(16) float d_nfB[NN * CH];
__device__ int   d_species[NN];
__device__ int   d_count[NN];
__device__ int   d_offsets[NN + 1];
__device__ int   d_cursor[NN];
__device__ int   d_perm[NE];
__device__ int   d_scount[NZ];
__device__ int   d_soff[NZ + 1];
__device__ int   d_scursor[NZ];
__device__ int   d_sperm[NN];
__device__ float d_gcnt[NG];

__device__ __forceinline__ float silu(float x) {
    return x / (1.f + __expf(-x));
}

// ---- f32x2 packed math helpers ----
__device__ __forceinline__ u64 pk2(float a, float b) {
    u64 r; asm("mov.b64 %0, {%1, %2};" : "=l"(r) : "f"(a), "f"(b)); return r;
}
__device__ __forceinline__ void fma2(u64 &d, u64 a, u64 b) {
    asm("fma.rn.f32x2 %0, %1, %2, %0;" : "+l"(d) : "l"(a), "l"(b));
}
__device__ __forceinline__ u64 mul2(u64 a, u64 b) {
    u64 r; asm("mul.rn.f32x2 %0, %1, %2;" : "=l"(r) : "l"(a), "l"(b)); return r;
}
__device__ __forceinline__ float2 unpk(u64 v) {
    float2 r; asm("mov.b64 {%0, %1}, %2;" : "=f"(r.x), "=f"(r.y) : "l"(v)); return r;
}
__device__ __forceinline__ float hsum2(u64 v) {
    float2 s = unpk(v); return s.x + s.y;
}

// Conflict-free pair-interleave staging of a 128x128 weight matrix:
// Wp[pp*256 + 2k + c01] = W[2pp + c01][k]
__device__ __forceinline__ void load_w_pairs(float* Wp, const float* W, int tid, int nthr) {
    for (int op = tid; op < 4096; op += nthr) {
        int pp = op >> 6, j = op & 63;
        float2 a = *(const float2*)&W[(2 * pp) * CH + 2 * j];
        float2 b = *(const float2*)&W[(2 * pp + 1) * CH + 2 * j];
        ((float4*)Wp)[op] = make_float4(a.x, b.x, a.y, b.y);
    }
}

// same for 64-wide matrices (rows x 64), nfl4 = rows*64/4
__device__ __forceinline__ void load_w_pairs64(float* Wp, const float* W, int nfl4,
                                               int tid, int nthr) {
    for (int op = tid; op < nfl4; op += nthr) {
        int pp = op >> 5, j = op & 31;
        float2 a = *(const float2*)&W[(2 * pp) * 64 + 2 * j];
        float2 b = *(const float2*)&W[(2 * pp + 1) * 64 + 2 * j];
        ((float4*)Wp)[op] = make_float4(a.x, b.x, a.y, b.y);
    }
}

// ---------------- init / zero ----------------
__global__ void k_zero() {
    int i = blockIdx.x * blockDim.x + threadIdx.x;
    if (i < NN) d_count[i] = 0;
    if (i < NZ) d_scount[i] = 0;
    if (i < NG) d_gcnt[i] = 0.f;
}

__global__ void k_node_init(const float* __restrict__ x,
                            const float* __restrict__ W_embed) {
    int tid = blockIdx.x * blockDim.x + threadIdx.x;
    if (tid >= NN * CH) return;
    int n = tid >> 7, k = tid & 127;
    const float* xr = x + n * NZ;
    int s = 0;
    float best = xr[0];
#pragma unroll
    for (int z = 1; z < NZ; z++) {
        float v = xr[z];
        if (v > best) { best = v; s = z; }
    }
    if (k == 0) {
        d_species[n] = s;
        atomicAdd(&d_scount[s], 1);
    }
    d_nfA[tid] = W_embed[s * CH + k] * 0.31622776601683794f;
}

// ---------------- edge geometry: SH + radial basis ----------------
__global__ void k_edge_geom(const float* __restrict__ pos,
                            const int* __restrict__ edge_index) {
    int e = blockIdx.x * blockDim.x + threadIdx.x;
    if (e >= NE) return;
    int j = edge_index[e];
    int i = edge_index[NE + e];
    float dx = pos[j * 3 + 0] - pos[i * 3 + 0];
    float dy = pos[j * 3 + 1] - pos[i * 3 + 1];
    float dz = pos[j * 3 + 2] - pos[i * 3 + 2];
    float r2 = dx * dx + dy * dy + dz * dz + 1e-12f;
    float r = sqrtf(r2);
    float inv = 1.f / r;
    float X = dx * inv, Y = dy * inv, Z = dz * inv;
    float x2 = X * X, y2 = Y * Y, z2 = Z * Z;

    const float s3 = 1.7320508075688772f;
    const float s15 = 3.872983346207417f;
    const float s5 = 2.23606797749979f;
    const float s35_8 = 2.091650066335189f;
    const float s105 = 10.246950765959598f;
    const float s21_8 = 1.6201851746019651f;
    const float s7 = 2.6457513110645907f;

    float sh[16];
    sh[0] = 1.f;
    sh[1] = s3 * X; sh[2] = s3 * Y; sh[3] = s3 * Z;
    sh[4] = s15 * X * Y;
    sh[5] = s15 * Y * Z;
    sh[6] = 0.5f * s5 * (3.f * z2 - 1.f);
    sh[7] = s15 * X * Z;
    sh[8] = 0.5f * s15 * (x2 - y2);
    sh[9] = s35_8 * Y * (3.f * x2 - y2);
    sh[10] = s105 * X * Y * Z;
    sh[11] = s21_8 * Y * (5.f * z2 - 1.f);
    sh[12] = 0.5f * s7 * Z * (5.f * z2 - 3.f);
    sh[13] = s21_8 * X * (5.f * z2 - 1.f);
    sh[14] = 0.5f * s105 * Z * (x2 - y2);
    sh[15] = s35_8 * X * (x2 - 3.f * y2);
#pragma unroll
    for (int q = 0; q < 4; q++)
        *(float4*)&d_sh[e * 16 + q * 4] = *(float4*)&sh[q * 4];

    float u = r * 0.2f;
    float u2 = u * u;
    float u5 = u2 * u2 * u;
    float f = 1.f - 21.f * u5 + 35.f * u5 * u - 15.f * u5 * u2;
    if (u >= 1.f) f = 0.f;
    float coef = 0.6324555320336759f * inv * f;
    float rad[8];
#pragma unroll
    for (int nb = 1; nb <= 8; nb++)
        rad[nb - 1] = coef * sinpif((float)nb * u);
    *(float4*)&d_rad[e * 8] = *(float4*)&rad[0];
    *(float4*)&d_rad[e * 8 + 4] = *(float4*)&rad[4];
}

// ---------------- CSR build ----------------
__global__ void k_hist(const int* __restrict__ edge_index) {
    int e = blockIdx.x * blockDim.x + threadIdx.x;
    if (e >= NE) return;
    atomicAdd(&d_count[edge_index[NE + e]], 1);
}

__global__ void k_scan() {
    __shared__ int sh[1024];
    int T = threadIdx.x;
    int base = T * 16;
    int loc[16];
    int s = 0;
#pragma unroll
    for (int q = 0; q < 16; q++) { loc[q] = d_count[base + q]; s += loc[q]; }
    sh[T] = s;
    __syncthreads();
    for (int off = 1; off < 1024; off <<= 1) {
        int v = (T >= off) ? sh[T - off] : 0;
        __syncthreads();
        sh[T] += v;
        __syncthreads();
    }
    int excl = sh[T] - s;
#pragma unroll
    for (int q = 0; q < 16; q++) {
        d_offsets[base + q] = excl;
        d_cursor[base + q] = excl;
        excl += loc[q];
    }
    if (T == 1023) d_offsets[NN] = sh[1023];
    if (T == 0) {
        int a = 0;
        for (int z = 0; z < NZ; z++) {
            d_soff[z] = a; d_scursor[z] = a; a += d_scount[z];
        }
        d_soff[NZ] = a;
    }
}

__global__ void k_scatter(const int* __restrict__ edge_index) {
    int e = blockIdx.x * blockDim.x + threadIdx.x;
    if (e >= NE) return;
    int i = edge_index[NE + e];
    int p = atomicAdd(&d_cursor[i], 1);
    d_perm[p] = e;
}

__global__ void k_sscatter() {
    int n = blockIdx.x * blockDim.x + threadIdx.x;
    if (n >= NN) return;
    int s = d_species[n];
    int p = atomicAdd(&d_scursor[s], 1);
    d_sperm[p] = n;
}

// ---------------- up = nf @ W_up / sqrt(128) ----------------
__global__ void __launch_bounds__(256) k_up(int t, const float* __restrict__ W_up) {
    extern __shared__ float sm[];
    float* Wsh = sm;           // 16384 pair-interleaved
    float* msh = sm + 16384;   // 32 rows x 128
    int tid = threadIdx.x;
    int k = tid & 127, h = tid >> 7;
    load_w_pairs(Wsh, W_up + t * CH * CH, tid, 256);
    const float* nf = t ? d_nfB : d_nfA;
    int n0 = blockIdx.x * 32;
    for (int i = tid; i < 1024; i += 256)
        ((float4*)msh)[i] = ((const float4*)nf)[n0 * 32 + i];
    __syncthreads();
    u64 acc[16];
#pragma unroll
    for (int q = 0; q < 16; q++) acc[q] = 0ull;
    for (int pp = 0; pp < 64; pp += 2) {
        u64 w01 = *(const u64*)&Wsh[pp * 256 + 2 * k];
        u64 w23 = *(const u64*)&Wsh[(pp + 1) * 256 + 2 * k];
#pragma unroll
        for (int q = 0; q < 16; q++) {
            ulonglong2 mv = *(const ulonglong2*)&msh[(h * 16 + q) * CH + 2 * pp];
            fma2(acc[q], mv.x, w01);
            fma2(acc[q], mv.y, w23);
        }
    }
#pragma unroll
    for (int q = 0; q < 16; q++)
        d_up[(n0 + h * 16 + q) * CH + k] = hsum2(acc[q]) * 0.08838834764831845f;
}

// ---------------- sc (species-bucketed skip) ----------------
__global__ void __launch_bounds__(128) k_sc(int t, const float* __restrict__ W_skip) {
    int z = blockIdx.y;
    int lo = d_soff[z], hi = d_soff[z + 1];
    int n0 = lo + blockIdx.x * 16;
    if (n0 >= hi) return;
    extern __shared__ float sm[];
    float* Wsh = sm;
    float* msh = sm + 16384;
    __shared__ int offs[16];
    int k = threadIdx.x;
    load_w_pairs(Wsh, W_skip + ((size_t)t * NZ + z) * CH * CH, k, 128);
    int cnt = min(16, hi - n0);
    if (k < cnt) offs[k] = d_sperm[n0 + k] * CH;
    __syncthreads();
    const float* nf = t ? d_nfB : d_nfA;
    for (int i = k; i < cnt * 32; i += 128) {
        int r = i >> 5;
        ((float4*)msh)[i] = *(const float4*)(nf + offs[r] + ((i & 31) << 2));
    }
    __syncthreads();
    u64 acc[16];
#pragma unroll
    for (int q = 0; q < 16; q++) acc[q] = 0ull;
    for (int pp = 0; pp < 64; pp += 2) {
        u64 w01 = *(const u64*)&Wsh[pp * 256 + 2 * k];
        u64 w23 = *(const u64*)&Wsh[(pp + 1) * 256 + 2 * k];
#pragma unroll
        for (int q = 0; q < 16; q++) {
            ulonglong2 mv = *(const ulonglong2*)&msh[q * CH + 2 * pp];
            fma2(acc[q], mv.x, w01);
            fma2(acc[q], mv.y, w23);
        }
    }
    for (int q = 0; q < cnt; q++)
        d_scb[offs[q] + k] = hsum2(acc[q]) * 0.027950849718747372f;
}

// ---------------- radial MLP (reverted to measured-239us variant) ----------
// 512 threads, 16-edge tiles.
// smem floats: w0p 512 | w1p 4096 | w2p 4096 | w3 32768 | radsh 128 |
//              hA 1024 | hB 1024 | hAT 1280 (stride 20)  total 44928
__global__ void __launch_bounds__(512) k_radial(
    int t, const float* __restrict__ Wr0, const float* __restrict__ Wr1,
    const float* __restrict__ Wr2, const float* __restrict__ Wr3) {
    extern __shared__ float sm[];
    float* w0p = sm;             // 512
    float* w1p = w0p + 512;      // 4096
    float* w2p = w1p + 4096;     // 4096
    float* w3  = w2p + 4096;     // 32768
    float* radT = w3 + 32768;    // 128
    float* hA  = radT + 128;     // 1024
    float* hB  = hA + 1024;      // 1024
    float* hAT = hB + 1024;      // 64*20 = 1280

    const float* W0 = Wr0 + t * 8 * 64;
    const float* W1 = Wr1 + t * 64 * 64;
    const float* W2 = Wr2 + t * 64 * 64;
    const float* W3 = Wr3 + t * 64 * 512;
    int tid = threadIdx.x;

    load_w_pairs64(w0p, W0, 128, tid, 512);
    load_w_pairs64(w1p, W1, 1024, tid, 512);
    load_w_pairs64(w2p, W2, 1024, tid, 512);
    for (int i = tid; i < 8192; i += 512)
        ((float4*)w3)[i] = ((const float4*)W3)[i];

    int o  = tid & 63;           // layers 0-2: output column
    int ep = tid >> 6;           // 0..7 -> local edges 2ep, 2ep+1
    int e0 = 2 * ep, e1 = 2 * ep + 1;
    int og = tid & 127;          // layer 3: output group (4 outs)
    int eq = tid >> 7;           // 0..3  -> local edges 4eq..4eq+3
    const u64 scale2 = pk2(0.125f, 0.125f);

    for (int tile = 0; tile < 8; tile++) {
        int ebase = blockIdx.x * 128 + tile * 16;
        if (tid < 32)
            ((float4*)radT)[tid] = ((const float4*)(d_rad + (size_t)ebase * 8))[tid];
        __syncthreads();
        // layer 0: 8 -> 64
        {
            u64 a = 0ull, b = 0ull;
#pragma unroll
            for (int cp = 0; cp < 4; cp++) {
                u64 w = *(const u64*)&w0p[cp * 128 + 2 * o];
                fma2(a, *(const u64*)&radT[e0 * 8 + 2 * cp], w);
                fma2(b, *(const u64*)&radT[e1 * 8 + 2 * cp], w);
            }
            hA[e0 * 64 + o] = silu(hsum2(a) * 0.3535533905932738f);
            hA[e1 * 64 + o] = silu(hsum2(b) * 0.3535533905932738f);
        }
        __syncthreads();
        // layer 1: 64 -> 64
        {
            u64 a = 0ull, b = 0ull;
#pragma unroll 8
            for (int cp = 0; cp < 32; cp++) {
                u64 w = *(const u64*)&w1p[cp * 128 + 2 * o];
                fma2(a, *(const u64*)&hA[e0 * 64 + 2 * cp], w);
                fma2(b, *(const u64*)&hA[e1 * 64 + 2 * cp], w);
            }
            hB[e0 * 64 + o] = silu(hsum2(a) * 0.125f);
            hB[e1 * 64 + o] = silu(hsum2(b) * 0.125f);
        }
        __syncthreads();
        // layer 2: 64 -> 64, output transposed into hAT[c][edge] (stride 20)
        {
            u64 a = 0ull, b = 0ull;
#pragma unroll 8
            for (int cp = 0; cp < 32; cp++) {
                u64 w = *(const u64*)&w2p[cp * 128 + 2 * o];
                fma2(a, *(const u64*)&hB[e0 * 64 + 2 * cp], w);
                fma2(b, *(const u64*)&hB[e1 * 64 + 2 * cp], w);
            }
            hAT[o * 20 + e0] = silu(hsum2(a) * 0.125f);
            hAT[o * 20 + e1] = silu(hsum2(b) * 0.125f);
        }
        __syncthreads();
        // layer 3: 64 -> 512; thread owns 4 outputs (og*4..+3) x 4 edges
        {
            u64 a01[4], a23[4];
#pragma unroll
            for (int q = 0; q < 4; q++) { a01[q] = 0ull; a23[q] = 0ull; }
#pragma unroll 4
            for (int c = 0; c < 64; c++) {
                ulonglong2 w = *(const ulonglong2*)&w3[c * 512 + og * 4];
                float4 hv = *(const float4*)&hAT[c * 20 + eq * 4];
                u64 h0 = pk2(hv.x, hv.x);
                u64 h1 = pk2(hv.y, hv.y);
                u64 h2 = pk2(hv.z, hv.z);
                u64 h3 = pk2(hv.w, hv.w);
                fma2(a01[0], h0, w.x); fma2(a23[0], h0, w.y);
                fma2(a01[1], h1, w.x); fma2(a23[1], h1, w.y);
                fma2(a01[2], h2, w.x); fma2(a23[2], h2, w.y);
                fma2(a01[3], h3, w.x); fma2(a23[3], h3, w.y);
            }
#pragma unroll
            for (int q = 0; q < 4; q++) {
                size_t ge = (size_t)(ebase + eq * 4 + q);
                ulonglong2 ov;
                ov.x = mul2(a01[q], scale2);
                ov.y = mul2(a23[q], scale2);
                *(ulonglong2*)&d_tpw[ge * 512 + og * 4] = ov;
            }
        }
        __syncthreads();
    }
}

// ---------------- fused gather + wlin + final ----------------
// 256 threads, 4 nodes per block. smem (floats):
//   msgS 4*16*128 = 8192  (msg, overwritten in place by A)
//   Wbuf 16384            (W_lin[l] pair-interleaved, restaged per l; then Wprod)
//   bS   512
// total 25088 floats = 100352 B -> 2 blocks/SM
template<int NM, int MS>
__device__ __forceinline__ void wlin_group(float* msgS, const float* Wbuf,
                                           int k, int h) {
    const int MY = 2 * NM;  // rows per h-half (rows = 4*NM)
    u64 acc[MY];
    int roff[MY];
#pragma unroll
    for (int q = 0; q < MY; q++) {
        int r = h * MY + q;
        roff[q] = (r / NM) * 2048 + (MS + r % NM) * 128;
        acc[q] = 0ull;
    }
    for (int pp = 0; pp < 64; pp += 2) {
        u64 w01 = *(const u64*)&Wbuf[pp * 256 + 2 * k];
        u64 w23 = *(const u64*)&Wbuf[(pp + 1) * 256 + 2 * k];
#pragma unroll
        for (int q = 0; q < MY; q++) {
            ulonglong2 mv = *(const ulonglong2*)&msgS[roff[q] + 2 * pp];
            fma2(acc[q], mv.x, w01);
            fma2(acc[q], mv.y, w23);
        }
    }
    __syncthreads();  // all reads of these rows complete before in-place write
#pragma unroll
    for (int q = 0; q < MY; q++)
        msgS[roff[q] + k] = hsum2(acc[q]) * 0.08838834764831845f;
}

__global__ void __launch_bounds__(256) k_fused(
    int t, const float* __restrict__ W_lin,
    const float* __restrict__ Wp1, const float* __restrict__ Wp2,
    const float* __restrict__ Wp3, const float* __restrict__ W_prodlin,
    const int* __restrict__ edge_index) {
    extern __shared__ float sm[];
    float* msgS = sm;            // 8192
    float* Wbuf = sm + 8192;     // 16384
    float* bS   = sm + 24576;    // 512
    int tid = threadIdx.x;
    int k = tid & 127, h = tid >> 7, lane = tid & 31;
    int nb = blockIdx.x * 4;

    // ---- phase 1: gather (node = nb + 2*step + h), no block syncs inside ----
    for (int step = 0; step < 2; step++) {
        int nl = 2 * step + h;
        int n = nb + nl;
        int lo = d_offsets[n], hi = d_offsets[n + 1];
        float acc[16];
#pragma unroll
        for (int m = 0; m < 16; m++) acc[m] = 0.f;
        for (int p = lo; p < hi; p++) {
            int e = d_perm[p];
            float shl = (lane < 16) ? d_sh[e * 16 + lane] : 0.f;
            int j = edge_index[e];
            float u = d_up[j * CH + k];
            const float* tp = d_tpw + (size_t)e * 512;
            float v0 = u * tp[k];
            float v1 = u * tp[CH + k];
            float v2 = u * tp[2 * CH + k];
            float v3 = u * tp[3 * CH + k];
            acc[0] += __shfl_sync(0xffffffffu, shl, 0) * v0;
#pragma unroll
            for (int m = 1; m < 4; m++) acc[m] += __shfl_sync(0xffffffffu, shl, m) * v1;
#pragma unroll
            for (int m = 4; m < 9; m++) acc[m] += __shfl_sync(0xffffffffu, shl, m) * v2;
#pragma unroll
            for (int m = 9; m < 16; m++) acc[m] += __shfl_sync(0xffffffffu, shl, m) * v3;
        }
#pragma unroll
        for (int m = 0; m < 16; m++)
            msgS[nl * 2048 + m * 128 + k] = acc[m] * 0.1f;
    }
    __syncthreads();

    // ---- phase 2: A = msg @ W_lin[l], in place (msgS becomes A) ----
    const float* WL = W_lin + (size_t)t * 4 * CH * CH;
    load_w_pairs(Wbuf, WL, tid, 256);
    __syncthreads();
    wlin_group<1, 0>(msgS, Wbuf, k, h);

    load_w_pairs(Wbuf, WL + 1 * CH * CH, tid, 256);
    __syncthreads();
    wlin_group<3, 1>(msgS, Wbuf, k, h);

    load_w_pairs(Wbuf, WL + 2 * CH * CH, tid, 256);
    __syncthreads();
    wlin_group<5, 4>(msgS, Wbuf, k, h);

    load_w_pairs(Wbuf, WL + 3 * CH * CH, tid, 256);
    __syncthreads();
    wlin_group<7, 9>(msgS, Wbuf, k, h);
    __syncthreads();  // A fully written, visible to all

    // ---- phase 3a: nonlinearity -> b (per node, thread owns column k) ----
    for (int nn = 0; nn < 2; nn++) {
        int nl = 2 * h + nn;
        int n = nb + nl;
        const float* Ar = msgS + nl * 2048;
        float A0 = Ar[k];
        float i0 = A0 * A0, i1 = 0.f, i2 = 0.f, i3 = 0.f;
#pragma unroll
        for (int m = 1; m < 4; m++) { float a = Ar[m * 128 + k]; i1 += a * a; }
#pragma unroll
        for (int m = 4; m < 9; m++) { float a = Ar[m * 128 + k]; i2 += a * a; }
#pragma unroll
        for (int m = 9; m < 16; m++) { float a = Ar[m * 128 + k]; i3 += a * a; }
        int s = d_species[n];
        const float* p1 = Wp1 + ((size_t)t * NZ + s) * CH;
        const float* p2 = Wp2 + ((size_t)t * NZ + s) * 4 * CH;
        const float* p3 = Wp3 + ((size_t)t * NZ + s) * 4 * CH;
        float s2 = p2[k] * i0 + p2[CH + k] * i1 + p2[2 * CH + k] * i2 + p2[3 * CH + k] * i3;
        float s3v = p3[k] * i0 + p3[CH + k] * i1 + p3[2 * CH + k] * i2 + p3[3 * CH + k] * i3;
        bS[nl * 128 + k] = p1[k] * A0 + s2 + s3v * A0;
    }
    // restage Wbuf with prodlin weights (safe: all Wbuf reads done pre-sync above)
    load_w_pairs(Wbuf, W_prodlin + t * CH * CH, tid, 256);
    __syncthreads();

    // ---- phase 3b: nf = b @ Wprod / sqrt(128) + scb ----
    float* nfo = (t == 0) ? d_nfB : d_nfA;
    {
        int nl0 = 2 * h, nl1 = 2 * h + 1;
        u64 a0 = 0ull, a1 = 0ull;
        for (int pp = 0; pp < 64; pp += 2) {
            u64 w01 = *(const u64*)&Wbuf[pp * 256 + 2 * k];
            u64 w23 = *(const u64*)&Wbuf[(pp + 1) * 256 + 2 * k];
            ulonglong2 b0 = *(const ulonglong2*)&bS[nl0 * 128 + 2 * pp];
            ulonglong2 b1 = *(const ulonglong2*)&bS[nl1 * 128 + 2 * pp];
            fma2(a0, b0.x, w01); fma2(a0, b0.y, w23);
            fma2(a1, b1.x, w01); fma2(a1, b1.y, w23);
        }
        nfo[(nb + nl0) * CH + k] = hsum2(a0) * 0.08838834764831845f +
                                   d_scb[(nb + nl0) * CH + k];
        nfo[(nb + nl1) * CH + k] = hsum2(a1) * 0.08838834764831845f +
                                   d_scb[(nb + nl1) * CH + k];
    }
}

// ---------------- graph mean pooling ----------------
__global__ void k_env(const int* __restrict__ batch_idx, float* __restrict__ out) {
    int tid = blockIdx.x * blockDim.x + threadIdx.x;
    if (tid >= NN * CH) return;
    int n = tid >> 7, k = tid & 127;
    int g = batch_idx[n];
    atomicAdd(&out[g * CH + k], d_nfA[tid]);
    if (k == 0) atomicAdd(&d_gcnt[g], 1.f);
}

__global__ void k_div(float* __restrict__ out) {
    int i = blockIdx.x * blockDim.x + threadIdx.x;
    if (i >= NG * CH) return;
    int g = i >> 7;
    out[i] /= fmaxf(d_gcnt[g], 1.f);
}

// ---------------- launcher ----------------
extern "C" void kernel_launch(void* const* d_in, const int* in_sizes, int n_in,
                              void* d_out, int out_size) {
    const float* x        = (const float*)d_in[0];
    const float* pos      = (const float*)d_in[1];
    const float* W_embed  = (const float*)d_in[2];
    const float* W_up     = (const float*)d_in[3];
    const float* Wr0      = (const float*)d_in[4];
    const float* Wr1      = (const float*)d_in[5];
    const float* Wr2      = (const float*)d_in[6];
    const float* Wr3      = (const float*)d_in[7];
    const float* W_lin    = (const float*)d_in[8];
    const float* W_skip   = (const float*)d_in[9];
    const float* Wp1      = (const float*)d_in[10];
    const float* Wp2      = (const float*)d_in[11];
    const float* Wp3      = (const float*)d_in[12];
    const float* W_prodlin= (const float*)d_in[13];
    const int*   edge_index = (const int*)d_in[14];
    const int*   batch_idx  = (const int*)d_in[15];
    float* out = (float*)d_out;

    const int SM_UP    = (16384 + 4096) * 4;
    const int SM_SC    = (16384 + 2048) * 4;
    const int SM_RAD   = 44928 * 4;
    const int SM_FUSED = 25088 * 4;
    cudaFuncSetAttribute(k_up,     cudaFuncAttributeMaxDynamicSharedMemorySize, SM_UP);
    cudaFuncSetAttribute(k_sc,     cudaFuncAttributeMaxDynamicSharedMemorySize, SM_SC);
    cudaFuncSetAttribute(k_radial, cudaFuncAttributeMaxDynamicSharedMemorySize, SM_RAD);
    cudaFuncSetAttribute(k_fused,  cudaFuncAttributeMaxDynamicSharedMemorySize, SM_FUSED);

    k_zero<<<(NN + 255) / 256, 256>>>();
    k_node_init<<<(NN * CH) / 256, 256>>>(x, W_embed);
    k_edge_geom<<<NE / 256, 256>>>(pos, edge_index);
    // radial t=0 at launch slot 4 so ncu profiles it (validate the revert)
    k_radial<<<NE / 128, 512, SM_RAD>>>(0, Wr0, Wr1, Wr2, Wr3);
    k_hist<<<NE / 256, 256>>>(edge_index);
    k_scan<<<1, 1024>>>();
    k_scatter<<<NE / 256, 256>>>(edge_index);
    k_sscatter<<<NN / 256, 256>>>();

    for (int t = 0; t < 2; t++) {
        k_up<<<NN / 32, 256, SM_UP>>>(t, W_up);
        k_sc<<<dim3(NN / 16, NZ), 128, SM_SC>>>(t, W_skip);
        if (t == 1)
            k_radial<<<NE / 128, 512, SM_RAD>>>(t, Wr0, Wr1, Wr2, Wr3);
        k_fused<<<NN / 4, 256, SM_FUSED>>>(t, W_lin, Wp1, Wp2, Wp3,
                                           W_prodlin, edge_index);
    }

    cudaMemsetAsync(d_out, 0, (size_t)out_size * sizeof(float));
    k_env<<<(NN * CH) / 256, 256>>>(batch_idx, out);
    k_div<<<(NG * CH + 255) / 256, 256>>>(out);
}

// round 11
// speedup vs baseline: 1.0602x; 1.0198x over previous
#include <cuda_runtime.h>

#define NN 16384
#define NE 65536
#define NG 64
#define NZ 10
#define CH 128

typedef unsigned long long u64;

// ---------------- scratch (device globals; no allocations) ----------------
__device__ __align__(16) float d_sh[NE * 16];
__device__ __align__(16) float d_rad[NE * 8];
__device__ __align__(16) float d_tpw[(size_t)NE * 512];
__device__ __align__(16) float d_up[NN * CH];
__device__ __align__(16) float d_scb[NN * CH];
__device__ __align__(16) float d_nfA[NN * CH];
__device__ __align__(16) float d_nfB[NN * CH];
__device__ int   d_species[NN];
__device__ int   d_count[NN];
__device__ int   d_offsets[NN + 1];
__device__ int   d_cursor[NN];
__device__ int   d_perm[NE];
__device__ int   d_scount[NZ];
__device__ int   d_soff[NZ + 1];
__device__ int   d_scursor[NZ];
__device__ int   d_sperm[NN];
__device__ float d_gcnt[NG];

__device__ __forceinline__ float silu(float x) {
    return x / (1.f + __expf(-x));
}

// ---- f32x2 packed math helpers ----
__device__ __forceinline__ u64 pk2(float a, float b) {
    u64 r; asm("mov.b64 %0, {%1, %2};" : "=l"(r) : "f"(a), "f"(b)); return r;
}
__device__ __forceinline__ void fma2(u64 &d, u64 a, u64 b) {
    asm("fma.rn.f32x2 %0, %1, %2, %0;" : "+l"(d) : "l"(a), "l"(b));
}
__device__ __forceinline__ u64 mul2(u64 a, u64 b) {
    u64 r; asm("mul.rn.f32x2 %0, %1, %2;" : "=l"(r) : "l"(a), "l"(b)); return r;
}
__device__ __forceinline__ float2 unpk(u64 v) {
    float2 r; asm("mov.b64 {%0, %1}, %2;" : "=f"(r.x), "=f"(r.y) : "l"(v)); return r;
}
__device__ __forceinline__ float hsum2(u64 v) {
    float2 s = unpk(v); return s.x + s.y;
}

// Conflict-free pair-interleave staging of a 128x128 weight matrix:
// Wp[pp*256 + 2k + c01] = W[2pp + c01][k]
__device__ __forceinline__ void load_w_pairs(float* Wp, const float* W, int tid, int nthr) {
    for (int op = tid; op < 4096; op += nthr) {
        int pp = op >> 6, j = op & 63;
        float2 a = *(const float2*)&W[(2 * pp) * CH + 2 * j];
        float2 b = *(const float2*)&W[(2 * pp + 1) * CH + 2 * j];
        ((float4*)Wp)[op] = make_float4(a.x, b.x, a.y, b.y);
    }
}

// same for 64-wide matrices (rows x 64), nfl4 = rows*64/4
__device__ __forceinline__ void load_w_pairs64(float* Wp, const float* W, int nfl4,
                                               int tid, int nthr) {
    for (int op = tid; op < nfl4; op += nthr) {
        int pp = op >> 5, j = op & 31;
        float2 a = *(const float2*)&W[(2 * pp) * 64 + 2 * j];
        float2 b = *(const float2*)&W[(2 * pp + 1) * 64 + 2 * j];
        ((float4*)Wp)[op] = make_float4(a.x, b.x, a.y, b.y);
    }
}

// ---------------- init / zero ----------------
__global__ void k_zero() {
    int i = blockIdx.x * blockDim.x + threadIdx.x;
    if (i < NN) d_count[i] = 0;
    if (i < NZ) d_scount[i] = 0;
    if (i < NG) d_gcnt[i] = 0.f;
}

__global__ void k_node_init(const float* __restrict__ x,
                            const float* __restrict__ W_embed) {
    int tid = blockIdx.x * blockDim.x + threadIdx.x;
    if (tid >= NN * CH) return;
    int n = tid >> 7, k = tid & 127;
    const float* xr = x + n * NZ;
    int s = 0;
    float best = xr[0];
#pragma unroll
    for (int z = 1; z < NZ; z++) {
        float v = xr[z];
        if (v > best) { best = v; s = z; }
    }
    if (k == 0) {
        d_species[n] = s;
        atomicAdd(&d_scount[s], 1);
    }
    d_nfA[tid] = W_embed[s * CH + k] * 0.31622776601683794f;
}

// ---------------- edge geometry: SH + radial basis ----------------
__global__ void k_edge_geom(const float* __restrict__ pos,
                            const int* __restrict__ edge_index) {
    int e = blockIdx.x * blockDim.x + threadIdx.x;
    if (e >= NE) return;
    int j = edge_index[e];
    int i = edge_index[NE + e];
    float dx = pos[j * 3 + 0] - pos[i * 3 + 0];
    float dy = pos[j * 3 + 1] - pos[i * 3 + 1];
    float dz = pos[j * 3 + 2] - pos[i * 3 + 2];
    float r2 = dx * dx + dy * dy + dz * dz + 1e-12f;
    float r = sqrtf(r2);
    float inv = 1.f / r;
    float X = dx * inv, Y = dy * inv, Z = dz * inv;
    float x2 = X * X, y2 = Y * Y, z2 = Z * Z;

    const float s3 = 1.7320508075688772f;
    const float s15 = 3.872983346207417f;
    const float s5 = 2.23606797749979f;
    const float s35_8 = 2.091650066335189f;
    const float s105 = 10.246950765959598f;
    const float s21_8 = 1.6201851746019651f;
    const float s7 = 2.6457513110645907f;

    float sh[16];
    sh[0] = 1.f;
    sh[1] = s3 * X; sh[2] = s3 * Y; sh[3] = s3 * Z;
    sh[4] = s15 * X * Y;
    sh[5] = s15 * Y * Z;
    sh[6] = 0.5f * s5 * (3.f * z2 - 1.f);
    sh[7] = s15 * X * Z;
    sh[8] = 0.5f * s15 * (x2 - y2);
    sh[9] = s35_8 * Y * (3.f * x2 - y2);
    sh[10] = s105 * X * Y * Z;
    sh[11] = s21_8 * Y * (5.f * z2 - 1.f);
    sh[12] = 0.5f * s7 * Z * (5.f * z2 - 3.f);
    sh[13] = s21_8 * X * (5.f * z2 - 1.f);
    sh[14] = 0.5f * s105 * Z * (x2 - y2);
    sh[15] = s35_8 * X * (x2 - 3.f * y2);
#pragma unroll
    for (int q = 0; q < 4; q++)
        *(float4*)&d_sh[e * 16 + q * 4] = *(float4*)&sh[q * 4];

    float u = r * 0.2f;
    float u2 = u * u;
    float u5 = u2 * u2 * u;
    float f = 1.f - 21.f * u5 + 35.f * u5 * u - 15.f * u5 * u2;
    if (u >= 1.f) f = 0.f;
    float coef = 0.6324555320336759f * inv * f;
    float rad[8];
#pragma unroll
    for (int nb = 1; nb <= 8; nb++)
        rad[nb - 1] = coef * sinpif((float)nb * u);
    *(float4*)&d_rad[e * 8] = *(float4*)&rad[0];
    *(float4*)&d_rad[e * 8 + 4] = *(float4*)&rad[4];
}

// ---------------- CSR build ----------------
__global__ void k_hist(const int* __restrict__ edge_index) {
    int e = blockIdx.x * blockDim.x + threadIdx.x;
    if (e >= NE) return;
    atomicAdd(&d_count[edge_index[NE + e]], 1);
}

__global__ void k_scan() {
    __shared__ int sh[1024];
    int T = threadIdx.x;
    int base = T * 16;
    int loc[16];
    int s = 0;
#pragma unroll
    for (int q = 0; q < 16; q++) { loc[q] = d_count[base + q]; s += loc[q]; }
    sh[T] = s;
    __syncthreads();
    for (int off = 1; off < 1024; off <<= 1) {
        int v = (T >= off) ? sh[T - off] : 0;
        __syncthreads();
        sh[T] += v;
        __syncthreads();
    }
    int excl = sh[T] - s;
#pragma unroll
    for (int q = 0; q < 16; q++) {
        d_offsets[base + q] = excl;
        d_cursor[base + q] = excl;
        excl += loc[q];
    }
    if (T == 1023) d_offsets[NN] = sh[1023];
    if (T == 0) {
        int a = 0;
        for (int z = 0; z < NZ; z++) {
            d_soff[z] = a; d_scursor[z] = a; a += d_scount[z];
        }
        d_soff[NZ] = a;
    }
}

__global__ void k_scatter(const int* __restrict__ edge_index) {
    int e = blockIdx.x * blockDim.x + threadIdx.x;
    if (e >= NE) return;
    int i = edge_index[NE + e];
    int p = atomicAdd(&d_cursor[i], 1);
    d_perm[p] = e;
}

__global__ void k_sscatter() {
    int n = blockIdx.x * blockDim.x + threadIdx.x;
    if (n >= NN) return;
    int s = d_species[n];
    int p = atomicAdd(&d_scursor[s], 1);
    d_sperm[p] = n;
}

// ---------------- up = nf @ W_up / sqrt(128) ----------------
__global__ void __launch_bounds__(256) k_up(int t, const float* __restrict__ W_up) {
    extern __shared__ float sm[];
    float* Wsh = sm;           // 16384 pair-interleaved
    float* msh = sm + 16384;   // 32 rows x 128
    int tid = threadIdx.x;
    int k = tid & 127, h = tid >> 7;
    load_w_pairs(Wsh, W_up + t * CH * CH, tid, 256);
    const float* nf = t ? d_nfB : d_nfA;
    int n0 = blockIdx.x * 32;
    for (int i = tid; i < 1024; i += 256)
        ((float4*)msh)[i] = ((const float4*)nf)[n0 * 32 + i];
    __syncthreads();
    u64 acc[16];
#pragma unroll
    for (int q = 0; q < 16; q++) acc[q] = 0ull;
    for (int pp = 0; pp < 64; pp += 2) {
        u64 w01 = *(const u64*)&Wsh[pp * 256 + 2 * k];
        u64 w23 = *(const u64*)&Wsh[(pp + 1) * 256 + 2 * k];
#pragma unroll
        for (int q = 0; q < 16; q++) {
            ulonglong2 mv = *(const ulonglong2*)&msh[(h * 16 + q) * CH + 2 * pp];
            fma2(acc[q], mv.x, w01);
            fma2(acc[q], mv.y, w23);
        }
    }
#pragma unroll
    for (int q = 0; q < 16; q++)
        d_up[(n0 + h * 16 + q) * CH + k] = hsum2(acc[q]) * 0.08838834764831845f;
}

// ---------------- sc (species-bucketed skip) ----------------
__global__ void __launch_bounds__(128) k_sc(int t, const float* __restrict__ W_skip) {
    int z = blockIdx.y;
    int lo = d_soff[z], hi = d_soff[z + 1];
    int n0 = lo + blockIdx.x * 16;
    if (n0 >= hi) return;
    extern __shared__ float sm[];
    float* Wsh = sm;
    float* msh = sm + 16384;
    __shared__ int offs[16];
    int k = threadIdx.x;
    load_w_pairs(Wsh, W_skip + ((size_t)t * NZ + z) * CH * CH, k, 128);
    int cnt = min(16, hi - n0);
    if (k < cnt) offs[k] = d_sperm[n0 + k] * CH;
    __syncthreads();
    const float* nf = t ? d_nfB : d_nfA;
    for (int i = k; i < cnt * 32; i += 128) {
        int r = i >> 5;
        ((float4*)msh)[i] = *(const float4*)(nf + offs[r] + ((i & 31) << 2));
    }
    __syncthreads();
    u64 acc[16];
#pragma unroll
    for (int q = 0; q < 16; q++) acc[q] = 0ull;
    for (int pp = 0; pp < 64; pp += 2) {
        u64 w01 = *(const u64*)&Wsh[pp * 256 + 2 * k];
        u64 w23 = *(const u64*)&Wsh[(pp + 1) * 256 + 2 * k];
#pragma unroll
        for (int q = 0; q < 16; q++) {
            ulonglong2 mv = *(const ulonglong2*)&msh[q * CH + 2 * pp];
            fma2(acc[q], mv.x, w01);
            fma2(acc[q], mv.y, w23);
        }
    }
    for (int q = 0; q < cnt; q++)
        d_scb[offs[q] + k] = hsum2(acc[q]) * 0.027950849718747372f;
}

// ---------------- radial MLP: 512 threads, 16-edge tiles ----------------
// Layers 0-2 unchanged from the measured-239us variant.
// Layer 3 remapped: thread = 2 adjacent outputs (oh) x 8 edges (eh).
// smem floats: w0p 512 | w1p 4096 | w2p 4096 | w3 32768 | radsh 128 |
//              hA 1024 | hB 1024 | hAT 1280 (stride 20)  total 44928
__global__ void __launch_bounds__(512) k_radial(
    int t, const float* __restrict__ Wr0, const float* __restrict__ Wr1,
    const float* __restrict__ Wr2, const float* __restrict__ Wr3) {
    extern __shared__ float sm[];
    float* w0p = sm;             // 512
    float* w1p = w0p + 512;      // 4096
    float* w2p = w1p + 4096;     // 4096
    float* w3  = w2p + 4096;     // 32768
    float* radT = w3 + 32768;    // 128
    float* hA  = radT + 128;     // 1024
    float* hB  = hA + 1024;      // 1024
    float* hAT = hB + 1024;      // 64*20 = 1280

    const float* W0 = Wr0 + t * 8 * 64;
    const float* W1 = Wr1 + t * 64 * 64;
    const float* W2 = Wr2 + t * 64 * 64;
    const float* W3 = Wr3 + t * 64 * 512;
    int tid = threadIdx.x;

    load_w_pairs64(w0p, W0, 128, tid, 512);
    load_w_pairs64(w1p, W1, 1024, tid, 512);
    load_w_pairs64(w2p, W2, 1024, tid, 512);
    for (int i = tid; i < 8192; i += 512)
        ((float4*)w3)[i] = ((const float4*)W3)[i];

    int o  = tid & 63;           // layers 0-2: output column
    int ep = tid >> 6;           // 0..7 -> local edges 2ep, 2ep+1
    int e0 = 2 * ep, e1 = 2 * ep + 1;
    int oh = tid & 255;          // layer 3: outputs 2oh, 2oh+1
    int eh = tid >> 8;           // 0..1 -> local edges 8eh..8eh+7
    const u64 scale2 = pk2(0.125f, 0.125f);

    for (int tile = 0; tile < 8; tile++) {
        int ebase = blockIdx.x * 128 + tile * 16;
        if (tid < 32)
            ((float4*)radT)[tid] = ((const float4*)(d_rad + (size_t)ebase * 8))[tid];
        __syncthreads();
        // layer 0: 8 -> 64
        {
            u64 a = 0ull, b = 0ull;
#pragma unroll
            for (int cp = 0; cp < 4; cp++) {
                u64 w = *(const u64*)&w0p[cp * 128 + 2 * o];
                fma2(a, *(const u64*)&radT[e0 * 8 + 2 * cp], w);
                fma2(b, *(const u64*)&radT[e1 * 8 + 2 * cp], w);
            }
            hA[e0 * 64 + o] = silu(hsum2(a) * 0.3535533905932738f);
            hA[e1 * 64 + o] = silu(hsum2(b) * 0.3535533905932738f);
        }
        __syncthreads();
        // layer 1: 64 -> 64
        {
            u64 a = 0ull, b = 0ull;
#pragma unroll 8
            for (int cp = 0; cp < 32; cp++) {
                u64 w = *(const u64*)&w1p[cp * 128 + 2 * o];
                fma2(a, *(const u64*)&hA[e0 * 64 + 2 * cp], w);
                fma2(b, *(const u64*)&hA[e1 * 64 + 2 * cp], w);
            }
            hB[e0 * 64 + o] = silu(hsum2(a) * 0.125f);
            hB[e1 * 64 + o] = silu(hsum2(b) * 0.125f);
        }
        __syncthreads();
        // layer 2: 64 -> 64, output transposed into hAT[c][edge] (stride 20)
        {
            u64 a = 0ull, b = 0ull;
#pragma unroll 8
            for (int cp = 0; cp < 32; cp++) {
                u64 w = *(const u64*)&w2p[cp * 128 + 2 * o];
                fma2(a, *(const u64*)&hB[e0 * 64 + 2 * cp], w);
                fma2(b, *(const u64*)&hB[e1 * 64 + 2 * cp], w);
            }
            hAT[o * 20 + e0] = silu(hsum2(a) * 0.125f);
            hAT[o * 20 + e1] = silu(hsum2(b) * 0.125f);
        }
        __syncthreads();
        // layer 3: 64 -> 512; thread = 2 adjacent outputs x 8 edges.
        // w3 read once per c per warp (LDS.64, 256B contiguous); hAT broadcast.
        {
            u64 acc[8];
#pragma unroll
            for (int q = 0; q < 8; q++) acc[q] = 0ull;
#pragma unroll 4
            for (int c = 0; c < 64; c++) {
                u64 w = *(const u64*)&w3[c * 512 + 2 * oh];
                float4 hv0 = *(const float4*)&hAT[c * 20 + 8 * eh];
                float4 hv1 = *(const float4*)&hAT[c * 20 + 8 * eh + 4];
                fma2(acc[0], pk2(hv0.x, hv0.x), w);
                fma2(acc[1], pk2(hv0.y, hv0.y), w);
                fma2(acc[2], pk2(hv0.z, hv0.z), w);
                fma2(acc[3], pk2(hv0.w, hv0.w), w);
                fma2(acc[4], pk2(hv1.x, hv1.x), w);
                fma2(acc[5], pk2(hv1.y, hv1.y), w);
                fma2(acc[6], pk2(hv1.z, hv1.z), w);
                fma2(acc[7], pk2(hv1.w, hv1.w), w);
            }
#pragma unroll
            for (int q = 0; q < 8; q++) {
                size_t ge = (size_t)(ebase + 8 * eh + q);
                *(u64*)&d_tpw[ge * 512 + 2 * oh] = mul2(acc[q], scale2);
            }
        }
        __syncthreads();
    }
}

// ---------------- fused gather + wlin + final ----------------
// 512 threads, 8 nodes per block. smem (floats):
//   msgS 8*16*128 = 16384  (msg, overwritten in place by A)
//   Wbuf 16384             (pair-interleaved weights, restaged per matrix)
//   bS   1024
// total 33792 floats = 135168 B -> 1 block/SM (16 warps)
template<int NM, int MS>
__device__ __forceinline__ void wlin_group(float* msgS, const float* Wbuf,
                                           int k, int h) {
    const int MY = 2 * NM;  // rows per quarter (rows = 8*NM)
    u64 acc[MY];
    int roff[MY];
#pragma unroll
    for (int q = 0; q < MY; q++) {
        int r = h * MY + q;
        roff[q] = (r / NM) * 2048 + (MS + r % NM) * 128;
        acc[q] = 0ull;
    }
    for (int pp = 0; pp < 64; pp += 2) {
        u64 w01 = *(const u64*)&Wbuf[pp * 256 + 2 * k];
        u64 w23 = *(const u64*)&Wbuf[(pp + 1) * 256 + 2 * k];
#pragma unroll
        for (int q = 0; q < MY; q++) {
            ulonglong2 mv = *(const ulonglong2*)&msgS[roff[q] + 2 * pp];
            fma2(acc[q], mv.x, w01);
            fma2(acc[q], mv.y, w23);
        }
    }
    __syncthreads();  // all reads of these rows complete before in-place write
#pragma unroll
    for (int q = 0; q < MY; q++)
        msgS[roff[q] + k] = hsum2(acc[q]) * 0.08838834764831845f;
}

__global__ void __launch_bounds__(512) k_fused(
    int t, const float* __restrict__ W_lin,
    const float* __restrict__ Wp1, const float* __restrict__ Wp2,
    const float* __restrict__ Wp3, const float* __restrict__ W_prodlin,
    const int* __restrict__ edge_index) {
    extern __shared__ float sm[];
    float* msgS = sm;            // 16384
    float* Wbuf = sm + 16384;    // 16384
    float* bS   = sm + 32768;    // 1024
    int tid = threadIdx.x;
    int k = tid & 127, h = tid >> 7, lane = tid & 31;
    int nb = blockIdx.x * 8;

    // ---- phase 1: gather (quarter h handles nodes 2h, 2h+1) ----
    for (int step = 0; step < 2; step++) {
        int nl = 2 * h + step;
        int n = nb + nl;
        int lo = d_offsets[n], hi = d_offsets[n + 1];
        float acc[16];
#pragma unroll
        for (int m = 0; m < 16; m++) acc[m] = 0.f;
        for (int p = lo; p < hi; p++) {
            int e = d_perm[p];
            float shl = (lane < 16) ? d_sh[e * 16 + lane] : 0.f;
            int j = edge_index[e];
            float u = d_up[j * CH + k];
            const float* tp = d_tpw + (size_t)e * 512;
            float v0 = u * tp[k];
            float v1 = u * tp[CH + k];
            float v2 = u * tp[2 * CH + k];
            float v3 = u * tp[3 * CH + k];
            acc[0] += __shfl_sync(0xffffffffu, shl, 0) * v0;
#pragma unroll
            for (int m = 1; m < 4; m++) acc[m] += __shfl_sync(0xffffffffu, shl, m) * v1;
#pragma unroll
            for (int m = 4; m < 9; m++) acc[m] += __shfl_sync(0xffffffffu, shl, m) * v2;
#pragma unroll
            for (int m = 9; m < 16; m++) acc[m] += __shfl_sync(0xffffffffu, shl, m) * v3;
        }
#pragma unroll
        for (int m = 0; m < 16; m++)
            msgS[nl * 2048 + m * 128 + k] = acc[m] * 0.1f;
    }
    __syncthreads();

    // ---- phase 2: A = msg @ W_lin[l], in place (msgS becomes A) ----
    const float* WL = W_lin + (size_t)t * 4 * CH * CH;
    load_w_pairs(Wbuf, WL, tid, 512);
    __syncthreads();
    wlin_group<1, 0>(msgS, Wbuf, k, h);

    load_w_pairs(Wbuf, WL + 1 * CH * CH, tid, 512);
    __syncthreads();
    wlin_group<3, 1>(msgS, Wbuf, k, h);

    load_w_pairs(Wbuf, WL + 2 * CH * CH, tid, 512);
    __syncthreads();
    wlin_group<5, 4>(msgS, Wbuf, k, h);

    load_w_pairs(Wbuf, WL + 3 * CH * CH, tid, 512);
    __syncthreads();
    wlin_group<7, 9>(msgS, Wbuf, k, h);
    __syncthreads();  // A fully written, visible to all

    // ---- phase 3a: nonlinearity -> b (quarter h owns nodes 2h, 2h+1) ----
    for (int nn = 0; nn < 2; nn++) {
        int nl = 2 * h + nn;
        int n = nb + nl;
        const float* Ar = msgS + nl * 2048;
        float A0 = Ar[k];
        float i0 = A0 * A0, i1 = 0.f, i2 = 0.f, i3 = 0.f;
#pragma unroll
        for (int m = 1; m < 4; m++) { float a = Ar[m * 128 + k]; i1 += a * a; }
#pragma unroll
        for (int m = 4; m < 9; m++) { float a = Ar[m * 128 + k]; i2 += a * a; }
#pragma unroll
        for (int m = 9; m < 16; m++) { float a = Ar[m * 128 + k]; i3 += a * a; }
        int s = d_species[n];
        const float* p1 = Wp1 + ((size_t)t * NZ + s) * CH;
        const float* p2 = Wp2 + ((size_t)t * NZ + s) * 4 * CH;
        const float* p3 = Wp3 + ((size_t)t * NZ + s) * 4 * CH;
        float s2 = p2[k] * i0 + p2[CH + k] * i1 + p2[2 * CH + k] * i2 + p2[3 * CH + k] * i3;
        float s3v = p3[k] * i0 + p3[CH + k] * i1 + p3[2 * CH + k] * i2 + p3[3 * CH + k] * i3;
        bS[nl * 128 + k] = p1[k] * A0 + s2 + s3v * A0;
    }
    // restage Wbuf with prodlin weights (safe: all Wbuf reads done pre-sync above)
    load_w_pairs(Wbuf, W_prodlin + t * CH * CH, tid, 512);
    __syncthreads();

    // ---- phase 3b: nf = b @ Wprod / sqrt(128) + scb ----
    float* nfo = (t == 0) ? d_nfB : d_nfA;
    {
        int nl0 = 2 * h, nl1 = 2 * h + 1;
        u64 a0 = 0ull, a1 = 0ull;
        for (int pp = 0; pp < 64; pp += 2) {
            u64 w01 = *(const u64*)&Wbuf[pp * 256 + 2 * k];
            u64 w23 = *(const u64*)&Wbuf[(pp + 1) * 256 + 2 * k];
            ulonglong2 b0 = *(const ulonglong2*)&bS[nl0 * 128 + 2 * pp];
            ulonglong2 b1 = *(const ulonglong2*)&bS[nl1 * 128 + 2 * pp];
            fma2(a0, b0.x, w01); fma2(a0, b0.y, w23);
            fma2(a1, b1.x, w01); fma2(a1, b1.y, w23);
        }
        nfo[(nb + nl0) * CH + k] = hsum2(a0) * 0.08838834764831845f +
                                   d_scb[(nb + nl0) * CH + k];
        nfo[(nb + nl1) * CH + k] = hsum2(a1) * 0.08838834764831845f +
                                   d_scb[(nb + nl1) * CH + k];
    }
}

// ---------------- graph mean pooling ----------------
__global__ void k_env(const int* __restrict__ batch_idx, float* __restrict__ out) {
    int tid = blockIdx.x * blockDim.x + threadIdx.x;
    if (tid >= NN * CH) return;
    int n = tid >> 7, k = tid & 127;
    int g = batch_idx[n];
    atomicAdd(&out[g * CH + k], d_nfA[tid]);
    if (k == 0) atomicAdd(&d_gcnt[g], 1.f);
}

__global__ void k_div(float* __restrict__ out) {
    int i = blockIdx.x * blockDim.x + threadIdx.x;
    if (i >= NG * CH) return;
    int g = i >> 7;
    out[i] /= fmaxf(d_gcnt[g], 1.f);
}

// ---------------- launcher ----------------
extern "C" void kernel_launch(void* const* d_in, const int* in_sizes, int n_in,
                              void* d_out, int out_size) {
    const float* x        = (const float*)d_in[0];
    const float* pos      = (const float*)d_in[1];
    const float* W_embed  = (const float*)d_in[2];
    const float* W_up     = (const float*)d_in[3];
    const float* Wr0      = (const float*)d_in[4];
    const float* Wr1      = (const float*)d_in[5];
    const float* Wr2      = (const float*)d_in[6];
    const float* Wr3      = (const float*)d_in[7];
    const float* W_lin    = (const float*)d_in[8];
    const float* W_skip   = (const float*)d_in[9];
    const float* Wp1      = (const float*)d_in[10];
    const float* Wp2      = (const float*)d_in[11];
    const float* Wp3      = (const float*)d_in[12];
    const float* W_prodlin= (const float*)d_in[13];
    const int*   edge_index = (const int*)d_in[14];
    const int*   batch_idx  = (const int*)d_in[15];
    float* out = (float*)d_out;

    const int SM_UP    = (16384 + 4096) * 4;
    const int SM_SC    = (16384 + 2048) * 4;
    const int SM_RAD   = 44928 * 4;
    const int SM_FUSED = 33792 * 4;  // 132 KB
    cudaFuncSetAttribute(k_up,     cudaFuncAttributeMaxDynamicSharedMemorySize, SM_UP);
    cudaFuncSetAttribute(k_sc,     cudaFuncAttributeMaxDynamicSharedMemorySize, SM_SC);
    cudaFuncSetAttribute(k_radial, cudaFuncAttributeMaxDynamicSharedMemorySize, SM_RAD);
    cudaFuncSetAttribute(k_fused,  cudaFuncAttributeMaxDynamicSharedMemorySize, SM_FUSED);

    k_zero<<<(NN + 255) / 256, 256>>>();
    k_node_init<<<(NN * CH) / 256, 256>>>(x, W_embed);
    k_edge_geom<<<NE / 256, 256>>>(pos, edge_index);
    // radial t=0 at launch slot 4 so ncu profiles it (validate L3 remap)
    k_radial<<<NE / 128, 512, SM_RAD>>>(0, Wr0, Wr1, Wr2, Wr3);
    k_hist<<<NE / 256, 256>>>(edge_index);
    k_scan<<<1, 1024>>>();
    k_scatter<<<NE / 256, 256>>>(edge_index);
    k_sscatter<<<NN / 256, 256>>>();

    for (int t = 0; t < 2; t++) {
        k_up<<<NN / 32, 256, SM_UP>>>(t, W_up);
        k_sc<<<dim3(NN / 16, NZ), 128, SM_SC>>>(t, W_skip);
        if (t == 1)
            k_radial<<<NE / 128, 512, SM_RAD>>>(t, Wr0, Wr1, Wr2, Wr3);
        k_fused<<<NN / 8, 512, SM_FUSED>>>(t, W_lin, Wp1, Wp2, Wp3,
                                           W_prodlin, edge_index);
    }

    cudaMemsetAsync(d_out, 0, (size_t)out_size * sizeof(float));
    k_env<<<(NN * CH) / 256, 256>>>(batch_idx, out);
    k_div<<<(NG * CH + 255) / 256, 256>>>(out);
}

// round 13
// speedup vs baseline: 1.1132x; 1.0500x over previous
#include <cuda_runtime.h>

#define NN 16384
#define NE 65536
#define NG 64
#define NZ 10
#define CH 128

typedef unsigned long long u64;

// ---------------- scratch (device globals; no allocations) ----------------
__device__ __align__(16) float d_sh[NE * 16];
__device__ __align__(16) float d_rad[NE * 8];
__device__ __align__(16) float d_tpw[(size_t)NE * 512];
__device__ __align__(16) float d_up[NN * CH];
__device__ __align__(16) float d_scb[NN * CH];
__device__ __align__(16) float d_nfA[NN * CH];
__device__ __align__(16) float d_nfB[NN * CH];
__device__ int   d_species[NN];
__device__ int   d_count[NN];
__device__ int   d_offsets[NN + 1];
__device__ int   d_cursor[NN];
__device__ int   d_perm[NE];
__device__ int   d_scount[NZ];
__device__ int   d_soff[NZ + 1];
__device__ int   d_scursor[NZ];
__device__ int   d_sperm[NN];
__device__ float d_gcnt[NG];

__device__ __forceinline__ float silu(float x) {
    return x / (1.f + __expf(-x));
}

// ---- f32x2 packed math helpers ----
__device__ __forceinline__ u64 pk2(float a, float b) {
    u64 r; asm("mov.b64 %0, {%1, %2};" : "=l"(r) : "f"(a), "f"(b)); return r;
}
__device__ __forceinline__ void fma2(u64 &d, u64 a, u64 b) {
    asm("fma.rn.f32x2 %0, %1, %2, %0;" : "+l"(d) : "l"(a), "l"(b));
}
__device__ __forceinline__ u64 mul2(u64 a, u64 b) {
    u64 r; asm("mul.rn.f32x2 %0, %1, %2;" : "=l"(r) : "l"(a), "l"(b)); return r;
}
__device__ __forceinline__ float2 unpk(u64 v) {
    float2 r; asm("mov.b64 {%0, %1}, %2;" : "=f"(r.x), "=f"(r.y) : "l"(v)); return r;
}
__device__ __forceinline__ float hsum2(u64 v) {
    float2 s = unpk(v); return s.x + s.y;
}

// Conflict-free pair-interleave staging of a 128x128 weight matrix:
// Wp[pp*256 + 2k + c01] = W[2pp + c01][k]
__device__ __forceinline__ void load_w_pairs(float* Wp, const float* W, int tid, int nthr) {
    for (int op = tid; op < 4096; op += nthr) {
        int pp = op >> 6, j = op & 63;
        float2 a = *(const float2*)&W[(2 * pp) * CH + 2 * j];
        float2 b = *(const float2*)&W[(2 * pp + 1) * CH + 2 * j];
        ((float4*)Wp)[op] = make_float4(a.x, b.x, a.y, b.y);
    }
}

// same for 64-wide matrices (rows x 64), nfl4 = rows*64/4
__device__ __forceinline__ void load_w_pairs64(float* Wp, const float* W, int nfl4,
                                               int tid, int nthr) {
    for (int op = tid; op < nfl4; op += nthr) {
        int pp = op >> 5, j = op & 31;
        float2 a = *(const float2*)&W[(2 * pp) * 64 + 2 * j];
        float2 b = *(const float2*)&W[(2 * pp + 1) * 64 + 2 * j];
        ((float4*)Wp)[op] = make_float4(a.x, b.x, a.y, b.y);
    }
}

// ---------------- init / zero ----------------
__global__ void k_zero() {
    int i = blockIdx.x * blockDim.x + threadIdx.x;
    if (i < NN) d_count[i] = 0;
    if (i < NZ) d_scount[i] = 0;
    if (i < NG) d_gcnt[i] = 0.f;
}

__global__ void k_node_init(const float* __restrict__ x,
                            const float* __restrict__ W_embed) {
    int tid = blockIdx.x * blockDim.x + threadIdx.x;
    if (tid >= NN * CH) return;
    int n = tid >> 7, k = tid & 127;
    const float* xr = x + n * NZ;
    int s = 0;
    float best = xr[0];
#pragma unroll
    for (int z = 1; z < NZ; z++) {
        float v = xr[z];
        if (v > best) { best = v; s = z; }
    }
    if (k == 0) {
        d_species[n] = s;
        atomicAdd(&d_scount[s], 1);
    }
    d_nfA[tid] = W_embed[s * CH + k] * 0.31622776601683794f;
}

// ---------------- edge geometry: SH + radial basis ----------------
__global__ void k_edge_geom(const float* __restrict__ pos,
                            const int* __restrict__ edge_index) {
    int e = blockIdx.x * blockDim.x + threadIdx.x;
    if (e >= NE) return;
    int j = edge_index[e];
    int i = edge_index[NE + e];
    float dx = pos[j * 3 + 0] - pos[i * 3 + 0];
    float dy = pos[j * 3 + 1] - pos[i * 3 + 1];
    float dz = pos[j * 3 + 2] - pos[i * 3 + 2];
    float r2 = dx * dx + dy * dy + dz * dz + 1e-12f;
    float r = sqrtf(r2);
    float inv = 1.f / r;
    float X = dx * inv, Y = dy * inv, Z = dz * inv;
    float x2 = X * X, y2 = Y * Y, z2 = Z * Z;

    const float s3 = 1.7320508075688772f;
    const float s15 = 3.872983346207417f;
    const float s5 = 2.23606797749979f;
    const float s35_8 = 2.091650066335189f;
    const float s105 = 10.246950765959598f;
    const float s21_8 = 1.6201851746019651f;
    const float s7 = 2.6457513110645907f;

    float sh[16];
    sh[0] = 1.f;
    sh[1] = s3 * X; sh[2] = s3 * Y; sh[3] = s3 * Z;
    sh[4] = s15 * X * Y;
    sh[5] = s15 * Y * Z;
    sh[6] = 0.5f * s5 * (3.f * z2 - 1.f);
    sh[7] = s15 * X * Z;
    sh[8] = 0.5f * s15 * (x2 - y2);
    sh[9] = s35_8 * Y * (3.f * x2 - y2);
    sh[10] = s105 * X * Y * Z;
    sh[11] = s21_8 * Y * (5.f * z2 - 1.f);
    sh[12] = 0.5f * s7 * Z * (5.f * z2 - 3.f);
    sh[13] = s21_8 * X * (5.f * z2 - 1.f);
    sh[14] = 0.5f * s105 * Z * (x2 - y2);
    sh[15] = s35_8 * X * (x2 - 3.f * y2);
#pragma unroll
    for (int q = 0; q < 4; q++)
        *(float4*)&d_sh[e * 16 + q * 4] = *(float4*)&sh[q * 4];

    float u = r * 0.2f;
    float u2 = u * u;
    float u5 = u2 * u2 * u;
    float f = 1.f - 21.f * u5 + 35.f * u5 * u - 15.f * u5 * u2;
    if (u >= 1.f) f = 0.f;
    float coef = 0.6324555320336759f * inv * f;
    float rad[8];
#pragma unroll
    for (int nb = 1; nb <= 8; nb++)
        rad[nb - 1] = coef * sinpif((float)nb * u);
    *(float4*)&d_rad[e * 8] = *(float4*)&rad[0];
    *(float4*)&d_rad[e * 8 + 4] = *(float4*)&rad[4];
}

// ---------------- CSR build ----------------
__global__ void k_hist(const int* __restrict__ edge_index) {
    int e = blockIdx.x * blockDim.x + threadIdx.x;
    if (e >= NE) return;
    atomicAdd(&d_count[edge_index[NE + e]], 1);
}

__global__ void k_scan() {
    __shared__ int sh[1024];
    int T = threadIdx.x;
    int base = T * 16;
    int loc[16];
    int s = 0;
#pragma unroll
    for (int q = 0; q < 16; q++) { loc[q] = d_count[base + q]; s += loc[q]; }
    sh[T] = s;
    __syncthreads();
    for (int off = 1; off < 1024; off <<= 1) {
        int v = (T >= off) ? sh[T - off] : 0;
        __syncthreads();
        sh[T] += v;
        __syncthreads();
    }
    int excl = sh[T] - s;
#pragma unroll
    for (int q = 0; q < 16; q++) {
        d_offsets[base + q] = excl;
        d_cursor[base + q] = excl;
        excl += loc[q];
    }
    if (T == 1023) d_offsets[NN] = sh[1023];
    if (T == 0) {
        int a = 0;
        for (int z = 0; z < NZ; z++) {
            d_soff[z] = a; d_scursor[z] = a; a += d_scount[z];
        }
        d_soff[NZ] = a;
    }
}

__global__ void k_scatter(const int* __restrict__ edge_index) {
    int e = blockIdx.x * blockDim.x + threadIdx.x;
    if (e >= NE) return;
    int i = edge_index[NE + e];
    int p = atomicAdd(&d_cursor[i], 1);
    d_perm[p] = e;
}

__global__ void k_sscatter() {
    int n = blockIdx.x * blockDim.x + threadIdx.x;
    if (n >= NN) return;
    int s = d_species[n];
    int p = atomicAdd(&d_scursor[s], 1);
    d_sperm[p] = n;
}

// ---------------- up = nf @ W_up / sqrt(128) ----------------
__global__ void __launch_bounds__(256) k_up(int t, const float* __restrict__ W_up) {
    extern __shared__ float sm[];
    float* Wsh = sm;           // 16384 pair-interleaved
    float* msh = sm + 16384;   // 32 rows x 128
    int tid = threadIdx.x;
    int k = tid & 127, h = tid >> 7;
    load_w_pairs(Wsh, W_up + t * CH * CH, tid, 256);
    const float* nf = t ? d_nfB : d_nfA;
    int n0 = blockIdx.x * 32;
    for (int i = tid; i < 1024; i += 256)
        ((float4*)msh)[i] = ((const float4*)nf)[n0 * 32 + i];
    __syncthreads();
    u64 acc[16];
#pragma unroll
    for (int q = 0; q < 16; q++) acc[q] = 0ull;
    for (int pp = 0; pp < 64; pp += 2) {
        u64 w01 = *(const u64*)&Wsh[pp * 256 + 2 * k];
        u64 w23 = *(const u64*)&Wsh[(pp + 1) * 256 + 2 * k];
#pragma unroll
        for (int q = 0; q < 16; q++) {
            ulonglong2 mv = *(const ulonglong2*)&msh[(h * 16 + q) * CH + 2 * pp];
            fma2(acc[q], mv.x, w01);
            fma2(acc[q], mv.y, w23);
        }
    }
#pragma unroll
    for (int q = 0; q < 16; q++)
        d_up[(n0 + h * 16 + q) * CH + k] = hsum2(acc[q]) * 0.08838834764831845f;
}

// ---------------- sc (species-bucketed skip) ----------------
__global__ void __launch_bounds__(128) k_sc(int t, const float* __restrict__ W_skip) {
    int z = blockIdx.y;
    int lo = d_soff[z], hi = d_soff[z + 1];
    int n0 = lo + blockIdx.x * 16;
    if (n0 >= hi) return;
    extern __shared__ float sm[];
    float* Wsh = sm;
    float* msh = sm + 16384;
    __shared__ int offs[16];
    int k = threadIdx.x;
    load_w_pairs(Wsh, W_skip + ((size_t)t * NZ + z) * CH * CH, k, 128);
    int cnt = min(16, hi - n0);
    if (k < cnt) offs[k] = d_sperm[n0 + k] * CH;
    __syncthreads();
    const float* nf = t ? d_nfB : d_nfA;
    for (int i = k; i < cnt * 32; i += 128) {
        int r = i >> 5;
        ((float4*)msh)[i] = *(const float4*)(nf + offs[r] + ((i & 31) << 2));
    }
    __syncthreads();
    u64 acc[16];
#pragma unroll
    for (int q = 0; q < 16; q++) acc[q] = 0ull;
    for (int pp = 0; pp < 64; pp += 2) {
        u64 w01 = *(const u64*)&Wsh[pp * 256 + 2 * k];
        u64 w23 = *(const u64*)&Wsh[(pp + 1) * 256 + 2 * k];
#pragma unroll
        for (int q = 0; q < 16; q++) {
            ulonglong2 mv = *(const ulonglong2*)&msh[q * CH + 2 * pp];
            fma2(acc[q], mv.x, w01);
            fma2(acc[q], mv.y, w23);
        }
    }
    for (int q = 0; q < cnt; q++)
        d_scb[offs[q] + k] = hsum2(acc[q]) * 0.027950849718747372f;
}

// ---------------- radial MLP: 512 threads, ONE 128-edge tile per block ----
// Thread maps: L0-L2: (2 outputs ow) x (8 edges eg); L3: (2 outputs oh) x
// (16 edges) x 4 chunks. h loads batched as LDS.128 over 2 c-pairs.
// smem (floats): w1p[0,4096) w2p[4096,8192) w3[8192,40960)
//   hA/hAT[40960,49408)  (hA = 128x64; hAT = 64 x stride132, aliases hA)
//   hB[49408,57600)      (first 1024 = radT and next 512 = w0p during L0)
__global__ void __launch_bounds__(512) k_radial(
    int t, const float* __restrict__ Wr0, const float* __restrict__ Wr1,
    const float* __restrict__ Wr2, const float* __restrict__ Wr3) {
    extern __shared__ float sm[];
    float* w1p  = sm;            // 4096
    float* w2p  = sm + 4096;     // 4096
    float* w3   = sm + 8192;     // 32768
    float* hA   = sm + 40960;    // 8192 (L0 out / L1 in)
    float* hAT  = sm + 40960;    // 64 x 132 (L2 out / L3 in, aliases hA)
    float* hB   = sm + 49408;    // 8192 (L1 out / L2 in)
    float* radT = hB;            // 1024 (only during L0)
    float* w0p  = hB + 1024;     // 512  (only during L0)

    const float* W0 = Wr0 + t * 8 * 64;
    const float* W1 = Wr1 + t * 64 * 64;
    const float* W2 = Wr2 + t * 64 * 64;
    const float* W3 = Wr3 + t * 64 * 512;
    int tid = threadIdx.x;

    load_w_pairs64(w0p, W0, 128, tid, 512);
    load_w_pairs64(w1p, W1, 1024, tid, 512);
    load_w_pairs64(w2p, W2, 1024, tid, 512);
    for (int i = tid; i < 8192; i += 512)
        ((float4*)w3)[i] = ((const float4*)W3)[i];
    int ebase = blockIdx.x * 128;
    for (int i = tid; i < 256; i += 512)
        ((float4*)radT)[i] = ((const float4*)(d_rad + (size_t)ebase * 8))[i];
    __syncthreads();

    int ow = tid & 31;   // outputs 2ow, 2ow+1
    int eg = tid >> 5;   // edges 8eg .. 8eg+7
    const float s0 = 0.3535533905932738f;

    // ---- layer 0: 8 -> 64 ----
    {
        u64 a0[8], a1[8];
#pragma unroll
        for (int q = 0; q < 8; q++) { a0[q] = 0ull; a1[q] = 0ull; }
#pragma unroll
        for (int cph = 0; cph < 2; cph++) {
            ulonglong2 wA = *(const ulonglong2*)&w0p[(2 * cph) * 128 + 4 * ow];
            ulonglong2 wB = *(const ulonglong2*)&w0p[(2 * cph + 1) * 128 + 4 * ow];
#pragma unroll
            for (int q = 0; q < 8; q++) {
                ulonglong2 hv = *(const ulonglong2*)&radT[(8 * eg + q) * 8 + 4 * cph];
                fma2(a0[q], hv.x, wA.x); fma2(a1[q], hv.x, wA.y);
                fma2(a0[q], hv.y, wB.x); fma2(a1[q], hv.y, wB.y);
            }
        }
#pragma unroll
        for (int q = 0; q < 8; q++) {
            float v0 = silu(hsum2(a0[q]) * s0);
            float v1 = silu(hsum2(a1[q]) * s0);
            *(u64*)&hA[(8 * eg + q) * 64 + 2 * ow] = pk2(v0, v1);
        }
    }
    __syncthreads();

    // ---- layer 1: 64 -> 64 ----
    {
        u64 a0[8], a1[8];
#pragma unroll
        for (int q = 0; q < 8; q++) { a0[q] = 0ull; a1[q] = 0ull; }
#pragma unroll 4
        for (int cph = 0; cph < 16; cph++) {
            ulonglong2 wA = *(const ulonglong2*)&w1p[(2 * cph) * 128 + 4 * ow];
            ulonglong2 wB = *(const ulonglong2*)&w1p[(2 * cph + 1) * 128 + 4 * ow];
#pragma unroll
            for (int q = 0; q < 8; q++) {
                ulonglong2 hv = *(const ulonglong2*)&hA[(8 * eg + q) * 64 + 4 * cph];
                fma2(a0[q], hv.x, wA.x); fma2(a1[q], hv.x, wA.y);
                fma2(a0[q], hv.y, wB.x); fma2(a1[q], hv.y, wB.y);
            }
        }
        __syncthreads();  // hA reads done before hB write? (hB separate; but radT/w0p in hB!)
#pragma unroll
        for (int q = 0; q < 8; q++) {
            float v0 = silu(hsum2(a0[q]) * 0.125f);
            float v1 = silu(hsum2(a1[q]) * 0.125f);
            *(u64*)&hB[(8 * eg + q) * 64 + 2 * ow] = pk2(v0, v1);
        }
    }
    __syncthreads();

    // ---- layer 2: 64 -> 64, transposed out: hAT[o*132 + e] (aliases hA) ----
    {
        u64 a0[8], a1[8];
#pragma unroll
        for (int q = 0; q < 8; q++) { a0[q] = 0ull; a1[q] = 0ull; }
#pragma unroll 4
        for (int cph = 0; cph < 16; cph++) {
            ulonglong2 wA = *(const ulonglong2*)&w2p[(2 * cph) * 128 + 4 * ow];
            ulonglong2 wB = *(const ulonglong2*)&w2p[(2 * cph + 1) * 128 + 4 * ow];
#pragma unroll
            for (int q = 0; q < 8; q++) {
                ulonglong2 hv = *(const ulonglong2*)&hB[(8 * eg + q) * 64 + 4 * cph];
                fma2(a0[q], hv.x, wA.x); fma2(a1[q], hv.x, wA.y);
                fma2(a0[q], hv.y, wB.x); fma2(a1[q], hv.y, wB.y);
            }
        }
        __syncthreads();  // all hA reads (layer1) long done; ensure hB reads done before... (hAT aliases hA, safe)
#pragma unroll
        for (int q = 0; q < 8; q++) {
            int e = 8 * eg + q;
            hAT[(2 * ow) * 132 + e]     = silu(hsum2(a0[q]) * 0.125f);
            hAT[(2 * ow + 1) * 132 + e] = silu(hsum2(a1[q]) * 0.125f);
        }
    }
    __syncthreads();

    // ---- layer 3: 64 -> 512; thread = 2 outputs x 16 edges, 4 chunks ----
    {
        int oh = tid & 255;   // outputs 2oh, 2oh+1
        int eh = tid >> 8;    // 0..1
        const u64 scale2 = pk2(0.125f, 0.125f);
#pragma unroll
        for (int ch = 0; ch < 4; ch++) {
            int ebl = ch * 32 + 16 * eh;
            u64 acc[16];
#pragma unroll
            for (int q = 0; q < 16; q++) acc[q] = 0ull;
#pragma unroll 1
            for (int c = 0; c < 64; c++) {
                u64 wp = *(const u64*)&w3[c * 512 + 2 * oh];
                const float* hr = &hAT[c * 132 + ebl];
                float4 h0 = *(const float4*)&hr[0];
                float4 h1 = *(const float4*)&hr[4];
                float4 h2 = *(const float4*)&hr[8];
                float4 h3 = *(const float4*)&hr[12];
                fma2(acc[0],  pk2(h0.x, h0.x), wp);
                fma2(acc[1],  pk2(h0.y, h0.y), wp);
                fma2(acc[2],  pk2(h0.z, h0.z), wp);
                fma2(acc[3],  pk2(h0.w, h0.w), wp);
                fma2(acc[4],  pk2(h1.x, h1.x), wp);
                fma2(acc[5],  pk2(h1.y, h1.y), wp);
                fma2(acc[6],  pk2(h1.z, h1.z), wp);
                fma2(acc[7],  pk2(h1.w, h1.w), wp);
                fma2(acc[8],  pk2(h2.x, h2.x), wp);
                fma2(acc[9],  pk2(h2.y, h2.y), wp);
                fma2(acc[10], pk2(h2.z, h2.z), wp);
                fma2(acc[11], pk2(h2.w, h2.w), wp);
                fma2(acc[12], pk2(h3.x, h3.x), wp);
                fma2(acc[13], pk2(h3.y, h3.y), wp);
                fma2(acc[14], pk2(h3.z, h3.z), wp);
                fma2(acc[15], pk2(h3.w, h3.w), wp);
            }
#pragma unroll
            for (int q = 0; q < 16; q++) {
                size_t ge = (size_t)(ebase + ebl + q);
                *(u64*)&d_tpw[ge * 512 + 2 * oh] = mul2(acc[q], scale2);
            }
        }
    }
}

// ---------------- fused gather + wlin + final ----------------
// 512 threads, 8 nodes per block.
template<int NM, int MS>
__device__ __forceinline__ void wlin_group(float* msgS, const float* Wbuf,
                                           int k, int h) {
    const int MY = 2 * NM;  // rows per quarter (rows = 8*NM)
    u64 acc[MY];
    int roff[MY];
#pragma unroll
    for (int q = 0; q < MY; q++) {
        int r = h * MY + q;
        roff[q] = (r / NM) * 2048 + (MS + r % NM) * 128;
        acc[q] = 0ull;
    }
    for (int pp = 0; pp < 64; pp += 2) {
        u64 w01 = *(const u64*)&Wbuf[pp * 256 + 2 * k];
        u64 w23 = *(const u64*)&Wbuf[(pp + 1) * 256 + 2 * k];
#pragma unroll
        for (int q = 0; q < MY; q++) {
            ulonglong2 mv = *(const ulonglong2*)&msgS[roff[q] + 2 * pp];
            fma2(acc[q], mv.x, w01);
            fma2(acc[q], mv.y, w23);
        }
    }
    __syncthreads();  // all reads of these rows complete before in-place write
#pragma unroll
    for (int q = 0; q < MY; q++)
        msgS[roff[q] + k] = hsum2(acc[q]) * 0.08838834764831845f;
}

__global__ void __launch_bounds__(512) k_fused(
    int t, const float* __restrict__ W_lin,
    const float* __restrict__ Wp1, const float* __restrict__ Wp2,
    const float* __restrict__ Wp3, const float* __restrict__ W_prodlin,
    const int* __restrict__ edge_index) {
    extern __shared__ float sm[];
    float* msgS = sm;            // 16384
    float* Wbuf = sm + 16384;    // 16384
    float* bS   = sm + 32768;    // 1024
    int tid = threadIdx.x;
    int k = tid & 127, h = tid >> 7, lane = tid & 31;
    int nb = blockIdx.x * 8;

    // ---- phase 1: gather (quarter h handles nodes 2h, 2h+1) ----
    for (int step = 0; step < 2; step++) {
        int nl = 2 * h + step;
        int n = nb + nl;
        int lo = d_offsets[n], hi = d_offsets[n + 1];
        float acc[16];
#pragma unroll
        for (int m = 0; m < 16; m++) acc[m] = 0.f;
        for (int p = lo; p < hi; p++) {
            int e = d_perm[p];
            float shl = (lane < 16) ? d_sh[e * 16 + lane] : 0.f;
            int j = edge_index[e];
            float u = d_up[j * CH + k];
            const float* tp = d_tpw + (size_t)e * 512;
            float v0 = u * tp[k];
            float v1 = u * tp[CH + k];
            float v2 = u * tp[2 * CH + k];
            float v3 = u * tp[3 * CH + k];
            acc[0] += __shfl_sync(0xffffffffu, shl, 0) * v0;
#pragma unroll
            for (int m = 1; m < 4; m++) acc[m] += __shfl_sync(0xffffffffu, shl, m) * v1;
#pragma unroll
            for (int m = 4; m < 9; m++) acc[m] += __shfl_sync(0xffffffffu, shl, m) * v2;
#pragma unroll
            for (int m = 9; m < 16; m++) acc[m] += __shfl_sync(0xffffffffu, shl, m) * v3;
        }
#pragma unroll
        for (int m = 0; m < 16; m++)
            msgS[nl * 2048 + m * 128 + k] = acc[m] * 0.1f;
    }
    __syncthreads();

    // ---- phase 2: A = msg @ W_lin[l], in place (msgS becomes A) ----
    const float* WL = W_lin + (size_t)t * 4 * CH * CH;
    load_w_pairs(Wbuf, WL, tid, 512);
    __syncthreads();
    wlin_group<1, 0>(msgS, Wbuf, k, h);

    load_w_pairs(Wbuf, WL + 1 * CH * CH, tid, 512);
    __syncthreads();
    wlin_group<3, 1>(msgS, Wbuf, k, h);

    load_w_pairs(Wbuf, WL + 2 * CH * CH, tid, 512);
    __syncthreads();
    wlin_group<5, 4>(msgS, Wbuf, k, h);

    load_w_pairs(Wbuf, WL + 3 * CH * CH, tid, 512);
    __syncthreads();
    wlin_group<7, 9>(msgS, Wbuf, k, h);
    __syncthreads();  // A fully written, visible to all

    // ---- phase 3a: nonlinearity -> b (quarter h owns nodes 2h, 2h+1) ----
    for (int nn = 0; nn < 2; nn++) {
        int nl = 2 * h + nn;
        int n = nb + nl;
        const float* Ar = msgS + nl * 2048;
        float A0 = Ar[k];
        float i0 = A0 * A0, i1 = 0.f, i2 = 0.f, i3 = 0.f;
#pragma unroll
        for (int m = 1; m < 4; m++) { float a = Ar[m * 128 + k]; i1 += a * a; }
#pragma unroll
        for (int m = 4; m < 9; m++) { float a = Ar[m * 128 + k]; i2 += a * a; }
#pragma unroll
        for (int m = 9; m < 16; m++) { float a = Ar[m * 128 + k]; i3 += a * a; }
        int s = d_species[n];
        const float* p1 = Wp1 + ((size_t)t * NZ + s) * CH;
        const float* p2 = Wp2 + ((size_t)t * NZ + s) * 4 * CH;
        const float* p3 = Wp3 + ((size_t)t * NZ + s) * 4 * CH;
        float s2 = p2[k] * i0 + p2[CH + k] * i1 + p2[2 * CH + k] * i2 + p2[3 * CH + k] * i3;
        float s3v = p3[k] * i0 + p3[CH + k] * i1 + p3[2 * CH + k] * i2 + p3[3 * CH + k] * i3;
        bS[nl * 128 + k] = p1[k] * A0 + s2 + s3v * A0;
    }
    load_w_pairs(Wbuf, W_prodlin + t * CH * CH, tid, 512);
    __syncthreads();

    // ---- phase 3b: nf = b @ Wprod / sqrt(128) + scb ----
    float* nfo = (t == 0) ? d_nfB : d_nfA;
    {
        int nl0 = 2 * h, nl1 = 2 * h + 1;
        u64 a0 = 0ull, a1 = 0ull;
        for (int pp = 0; pp < 64; pp += 2) {
            u64 w01 = *(const u64*)&Wbuf[pp * 256 + 2 * k];
            u64 w23 = *(const u64*)&Wbuf[(pp + 1) * 256 + 2 * k];
            ulonglong2 b0 = *(const ulonglong2*)&bS[nl0 * 128 + 2 * pp];
            ulonglong2 b1 = *(const ulonglong2*)&bS[nl1 * 128 + 2 * pp];
            fma2(a0, b0.x, w01); fma2(a0, b0.y, w23);
            fma2(a1, b1.x, w01); fma2(a1, b1.y, w23);
        }
        nfo[(nb + nl0) * CH + k] = hsum2(a0) * 0.08838834764831845f +
                                   d_scb[(nb + nl0) * CH + k];
        nfo[(nb + nl1) * CH + k] = hsum2(a1) * 0.08838834764831845f +
                                   d_scb[(nb + nl1) * CH + k];
    }
}

// ---------------- graph mean pooling ----------------
__global__ void k_env(const int* __restrict__ batch_idx, float* __restrict__ out) {
    int tid = blockIdx.x * blockDim.x + threadIdx.x;
    if (tid >= NN * CH) return;
    int n = tid >> 7, k = tid & 127;
    int g = batch_idx[n];
    atomicAdd(&out[g * CH + k], d_nfA[tid]);
    if (k == 0) atomicAdd(&d_gcnt[g], 1.f);
}

__global__ void k_div(float* __restrict__ out) {
    int i = blockIdx.x * blockDim.x + threadIdx.x;
    if (i >= NG * CH) return;
    int g = i >> 7;
    out[i] /= fmaxf(d_gcnt[g], 1.f);
}

// ---------------- launcher ----------------
extern "C" void kernel_launch(void* const* d_in, const int* in_sizes, int n_in,
                              void* d_out, int out_size) {
    const float* x        = (const float*)d_in[0];
    const float* pos      = (const float*)d_in[1];
    const float* W_embed  = (const float*)d_in[2];
    const float* W_up     = (const float*)d_in[3];
    const float* Wr0      = (const float*)d_in[4];
    const float* Wr1      = (const float*)d_in[5];
    const float* Wr2      = (const float*)d_in[6];
    const float* Wr3      = (const float*)d_in[7];
    const float* W_lin    = (const float*)d_in[8];
    const float* W_skip   = (const float*)d_in[9];
    const float* Wp1      = (const float*)d_in[10];
    const float* Wp2      = (const float*)d_in[11];
    const float* Wp3      = (const float*)d_in[12];
    const float* W_prodlin= (const float*)d_in[13];
    const int*   edge_index = (const int*)d_in[14];
    const int*   batch_idx  = (const int*)d_in[15];
    float* out = (float*)d_out;

    const int SM_UP    = (16384 + 4096) * 4;
    const int SM_SC    = (16384 + 2048) * 4;
    const int SM_RAD   = 57600 * 4;   // 230400 B
    const int SM_FUSED = 33792 * 4;   // 132 KB
    cudaFuncSetAttribute(k_up,     cudaFuncAttributeMaxDynamicSharedMemorySize, SM_UP);
    cudaFuncSetAttribute(k_sc,     cudaFuncAttributeMaxDynamicSharedMemorySize, SM_SC);
    cudaFuncSetAttribute(k_radial, cudaFuncAttributeMaxDynamicSharedMemorySize, SM_RAD);
    cudaFuncSetAttribute(k_fused,  cudaFuncAttributeMaxDynamicSharedMemorySize, SM_FUSED);

    k_zero<<<(NN + 255) / 256, 256>>>();
    k_node_init<<<(NN * CH) / 256, 256>>>(x, W_embed);
    k_edge_geom<<<NE / 256, 256>>>(pos, edge_index);
    // radial t=0 at launch slot 4 so ncu profiles it (validate wf rework)
    k_radial<<<NE / 128, 512, SM_RAD>>>(0, Wr0, Wr1, Wr2, Wr3);
    k_hist<<<NE / 256, 256>>>(edge_index);
    k_scan<<<1, 1024>>>();
    k_scatter<<<NE / 256, 256>>>(edge_index);
    k_sscatter<<<NN / 256, 256>>>();

    for (int t = 0; t < 2; t++) {
        k_up<<<NN / 32, 256, SM_UP>>>(t, W_up);
        k_sc<<<dim3(NN / 16, NZ), 128, SM_SC>>>(t, W_skip);
        if (t == 1)
            k_radial<<<NE / 128, 512, SM_RAD>>>(t, Wr0, Wr1, Wr2, Wr3);
        k_fused<<<NN / 8, 512, SM_FUSED>>>(t, W_lin, Wp1, Wp2, Wp3,
                                           W_prodlin, edge_index);
    }

    cudaMemsetAsync(d_out, 0, (size_t)out_size * sizeof(float));
    k_env<<<(NN * CH) / 256, 256>>>(batch_idx, out);
    k_div<<<(NG * CH + 255) / 256, 256>>>(out);
}

// round 15
// speedup vs baseline: 1.1712x; 1.0521x over previous
#include <cuda_runtime.h>

#define NN 16384
#define NE 65536
#define NG 64
#define NZ 10
#define CH 128

typedef unsigned long long u64;

// ---------------- scratch (device globals; no allocations) ----------------
__device__ __align__(16) float d_sh[NE * 16];
__device__ __align__(16) float d_rad[NE * 8];
__device__ __align__(16) float d_tpw[(size_t)NE * 512];
__device__ __align__(16) float d_up[NN * CH];
__device__ __align__(16) float d_scb[NN * CH];
__device__ __align__(16) float d_nfA[NN * CH];
__device__ __align__(16) float d_nfB[NN * CH];
__device__ int   d_species[NN];
__device__ int   d_count[NN];
__device__ int   d_offsets[NN + 1];
__device__ int   d_cursor[NN];
__device__ int   d_perm[NE];
__device__ int   d_scount[NZ];
__device__ int   d_soff[NZ + 1];
__device__ int   d_scursor[NZ];
__device__ int   d_sperm[NN];
__device__ float d_gcnt[NG];

__device__ __forceinline__ float silu(float x) {
    return x / (1.f + __expf(-x));
}

// ---- f32x2 packed math helpers ----
__device__ __forceinline__ u64 pk2(float a, float b) {
    u64 r; asm("mov.b64 %0, {%1, %2};" : "=l"(r) : "f"(a), "f"(b)); return r;
}
__device__ __forceinline__ void fma2(u64 &d, u64 a, u64 b) {
    asm("fma.rn.f32x2 %0, %1, %2, %0;" : "+l"(d) : "l"(a), "l"(b));
}
__device__ __forceinline__ u64 mul2(u64 a, u64 b) {
    u64 r; asm("mul.rn.f32x2 %0, %1, %2;" : "=l"(r) : "l"(a), "l"(b)); return r;
}
__device__ __forceinline__ float2 unpk(u64 v) {
    float2 r; asm("mov.b64 {%0, %1}, %2;" : "=f"(r.x), "=f"(r.y) : "l"(v)); return r;
}
__device__ __forceinline__ float hsum2(u64 v) {
    float2 s = unpk(v); return s.x + s.y;
}

// Conflict-free pair-interleave staging of a 128x128 weight matrix:
// Wp[pp*256 + 2k + c01] = W[2pp + c01][k]
__device__ __forceinline__ void load_w_pairs(float* Wp, const float* W, int tid, int nthr) {
    for (int op = tid; op < 4096; op += nthr) {
        int pp = op >> 6, j = op & 63;
        float2 a = *(const float2*)&W[(2 * pp) * CH + 2 * j];
        float2 b = *(const float2*)&W[(2 * pp + 1) * CH + 2 * j];
        ((float4*)Wp)[op] = make_float4(a.x, b.x, a.y, b.y);
    }
}

// same for 64-wide matrices (rows x 64), nfl4 = rows*64/4
__device__ __forceinline__ void load_w_pairs64(float* Wp, const float* W, int nfl4,
                                               int tid, int nthr) {
    for (int op = tid; op < nfl4; op += nthr) {
        int pp = op >> 5, j = op & 31;
        float2 a = *(const float2*)&W[(2 * pp) * 64 + 2 * j];
        float2 b = *(const float2*)&W[(2 * pp + 1) * 64 + 2 * j];
        ((float4*)Wp)[op] = make_float4(a.x, b.x, a.y, b.y);
    }
}

// ---------------- init / zero ----------------
__global__ void k_zero() {
    int i = blockIdx.x * blockDim.x + threadIdx.x;
    if (i < NN) d_count[i] = 0;
    if (i < NZ) d_scount[i] = 0;
    if (i < NG) d_gcnt[i] = 0.f;
}

__global__ void k_node_init(const float* __restrict__ x,
                            const float* __restrict__ W_embed) {
    int tid = blockIdx.x * blockDim.x + threadIdx.x;
    if (tid >= NN * CH) return;
    int n = tid >> 7, k = tid & 127;
    const float* xr = x + n * NZ;
    int s = 0;
    float best = xr[0];
#pragma unroll
    for (int z = 1; z < NZ; z++) {
        float v = xr[z];
        if (v > best) { best = v; s = z; }
    }
    if (k == 0) {
        d_species[n] = s;
        atomicAdd(&d_scount[s], 1);
    }
    d_nfA[tid] = W_embed[s * CH + k] * 0.31622776601683794f;
}

// ---------------- edge geometry: SH + radial basis + degree hist ----------
__global__ void k_edge_geom(const float* __restrict__ pos,
                            const int* __restrict__ edge_index) {
    int e = blockIdx.x * blockDim.x + threadIdx.x;
    if (e >= NE) return;
    int j = edge_index[e];
    int i = edge_index[NE + e];
    atomicAdd(&d_count[i], 1);  // fused CSR histogram
    float dx = pos[j * 3 + 0] - pos[i * 3 + 0];
    float dy = pos[j * 3 + 1] - pos[i * 3 + 1];
    float dz = pos[j * 3 + 2] - pos[i * 3 + 2];
    float r2 = dx * dx + dy * dy + dz * dz + 1e-12f;
    float r = sqrtf(r2);
    float inv = 1.f / r;
    float X = dx * inv, Y = dy * inv, Z = dz * inv;
    float x2 = X * X, y2 = Y * Y, z2 = Z * Z;

    const float s3 = 1.7320508075688772f;
    const float s15 = 3.872983346207417f;
    const float s5 = 2.23606797749979f;
    const float s35_8 = 2.091650066335189f;
    const float s105 = 10.246950765959598f;
    const float s21_8 = 1.6201851746019651f;
    const float s7 = 2.6457513110645907f;

    float sh[16];
    sh[0] = 1.f;
    sh[1] = s3 * X; sh[2] = s3 * Y; sh[3] = s3 * Z;
    sh[4] = s15 * X * Y;
    sh[5] = s15 * Y * Z;
    sh[6] = 0.5f * s5 * (3.f * z2 - 1.f);
    sh[7] = s15 * X * Z;
    sh[8] = 0.5f * s15 * (x2 - y2);
    sh[9] = s35_8 * Y * (3.f * x2 - y2);
    sh[10] = s105 * X * Y * Z;
    sh[11] = s21_8 * Y * (5.f * z2 - 1.f);
    sh[12] = 0.5f * s7 * Z * (5.f * z2 - 3.f);
    sh[13] = s21_8 * X * (5.f * z2 - 1.f);
    sh[14] = 0.5f * s105 * Z * (x2 - y2);
    sh[15] = s35_8 * X * (x2 - 3.f * y2);
#pragma unroll
    for (int q = 0; q < 4; q++)
        *(float4*)&d_sh[e * 16 + q * 4] = *(float4*)&sh[q * 4];

    float u = r * 0.2f;
    float u2 = u * u;
    float u5 = u2 * u2 * u;
    float f = 1.f - 21.f * u5 + 35.f * u5 * u - 15.f * u5 * u2;
    if (u >= 1.f) f = 0.f;
    float coef = 0.6324555320336759f * inv * f;
    float rad[8];
#pragma unroll
    for (int nb = 1; nb <= 8; nb++)
        rad[nb - 1] = coef * sinpif((float)nb * u);
    *(float4*)&d_rad[e * 8] = *(float4*)&rad[0];
    *(float4*)&d_rad[e * 8 + 4] = *(float4*)&rad[4];
}

// ---------------- CSR build ----------------
__global__ void k_scan() {
    __shared__ int sh[1024];
    int T = threadIdx.x;
    int base = T * 16;
    int loc[16];
    int s = 0;
#pragma unroll
    for (int q = 0; q < 16; q++) { loc[q] = d_count[base + q]; s += loc[q]; }
    sh[T] = s;
    __syncthreads();
    for (int off = 1; off < 1024; off <<= 1) {
        int v = (T >= off) ? sh[T - off] : 0;
        __syncthreads();
        sh[T] += v;
        __syncthreads();
    }
    int excl = sh[T] - s;
#pragma unroll
    for (int q = 0; q < 16; q++) {
        d_offsets[base + q] = excl;
        d_cursor[base + q] = excl;
        excl += loc[q];
    }
    if (T == 1023) d_offsets[NN] = sh[1023];
    if (T == 0) {
        int a = 0;
        for (int z = 0; z < NZ; z++) {
            d_soff[z] = a; d_scursor[z] = a; a += d_scount[z];
        }
        d_soff[NZ] = a;
    }
}

// edge scatter + species scatter fused
__global__ void k_scatter(const int* __restrict__ edge_index) {
    int e = blockIdx.x * blockDim.x + threadIdx.x;
    if (e < NN) {
        int s = d_species[e];
        int p = atomicAdd(&d_scursor[s], 1);
        d_sperm[p] = e;
    }
    if (e >= NE) return;
    int i = edge_index[NE + e];
    int p = atomicAdd(&d_cursor[i], 1);
    d_perm[p] = e;
}

// ---------------- up = nf @ W_up / sqrt(128) ----------------
__global__ void __launch_bounds__(256) k_up(int t, const float* __restrict__ W_up) {
    extern __shared__ float sm[];
    float* Wsh = sm;           // 16384 pair-interleaved
    float* msh = sm + 16384;   // 32 rows x 128
    int tid = threadIdx.x;
    int k = tid & 127, h = tid >> 7;
    load_w_pairs(Wsh, W_up + t * CH * CH, tid, 256);
    const float* nf = t ? d_nfB : d_nfA;
    int n0 = blockIdx.x * 32;
    for (int i = tid; i < 1024; i += 256)
        ((float4*)msh)[i] = ((const float4*)nf)[n0 * 32 + i];
    __syncthreads();
    u64 acc[16];
#pragma unroll
    for (int q = 0; q < 16; q++) acc[q] = 0ull;
    for (int pp = 0; pp < 64; pp += 2) {
        u64 w01 = *(const u64*)&Wsh[pp * 256 + 2 * k];
        u64 w23 = *(const u64*)&Wsh[(pp + 1) * 256 + 2 * k];
#pragma unroll
        for (int q = 0; q < 16; q++) {
            ulonglong2 mv = *(const ulonglong2*)&msh[(h * 16 + q) * CH + 2 * pp];
            fma2(acc[q], mv.x, w01);
            fma2(acc[q], mv.y, w23);
        }
    }
#pragma unroll
    for (int q = 0; q < 16; q++)
        d_up[(n0 + h * 16 + q) * CH + k] = hsum2(acc[q]) * 0.08838834764831845f;
}

// ---------------- sc (species-bucketed skip) ----------------
__global__ void __launch_bounds__(128) k_sc(int t, const float* __restrict__ W_skip) {
    int z = blockIdx.y;
    int lo = d_soff[z], hi = d_soff[z + 1];
    int n0 = lo + blockIdx.x * 16;
    if (n0 >= hi) return;
    extern __shared__ float sm[];
    float* Wsh = sm;
    float* msh = sm + 16384;
    __shared__ int offs[16];
    int k = threadIdx.x;
    load_w_pairs(Wsh, W_skip + ((size_t)t * NZ + z) * CH * CH, k, 128);
    int cnt = min(16, hi - n0);
    if (k < cnt) offs[k] = d_sperm[n0 + k] * CH;
    __syncthreads();
    const float* nf = t ? d_nfB : d_nfA;
    for (int i = k; i < cnt * 32; i += 128) {
        int r = i >> 5;
        ((float4*)msh)[i] = *(const float4*)(nf + offs[r] + ((i & 31) << 2));
    }
    __syncthreads();
    u64 acc[16];
#pragma unroll
    for (int q = 0; q < 16; q++) acc[q] = 0ull;
    for (int pp = 0; pp < 64; pp += 2) {
        u64 w01 = *(const u64*)&Wsh[pp * 256 + 2 * k];
        u64 w23 = *(const u64*)&Wsh[(pp + 1) * 256 + 2 * k];
#pragma unroll
        for (int q = 0; q < 16; q++) {
            ulonglong2 mv = *(const ulonglong2*)&msh[q * CH + 2 * pp];
            fma2(acc[q], mv.x, w01);
            fma2(acc[q], mv.y, w23);
        }
    }
    for (int q = 0; q < cnt; q++)
        d_scb[offs[q] + k] = hsum2(acc[q]) * 0.027950849718747372f;
}

// ---------------- radial MLP: 512 threads, ONE 128-edge tile per block ----
// L0-L2: (2 outputs ow) x (8 edges eg), LDS.128-batched.
// L3: thread = 2 outputs (w duped, 2 pk2/c) x 16 edges packed natively in
//     f32x2 lanes (h pairs are contiguous in hAT -> LDS.128, no dup movs).
// smem (floats): w1p[0,4096) w2p[4096,8192) w3[8192,40960)
//   hA/hAT[40960,49408)  hB[49408,57600) (radT/w0p alias hB during L0)
__global__ void __launch_bounds__(512) k_radial(
    int t, const float* __restrict__ Wr0, const float* __restrict__ Wr1,
    const float* __restrict__ Wr2, const float* __restrict__ Wr3) {
    extern __shared__ float sm[];
    float* w1p  = sm;            // 4096
    float* w2p  = sm + 4096;     // 4096
    float* w3   = sm + 8192;     // 32768
    float* hA   = sm + 40960;    // 8192 (L0 out / L1 in)
    float* hAT  = sm + 40960;    // 64 x 132 (L2 out / L3 in, aliases hA)
    float* hB   = sm + 49408;    // 8192 (L1 out / L2 in)
    float* radT = hB;            // 1024 (only during L0)
    float* w0p  = hB + 1024;     // 512  (only during L0)

    const float* W0 = Wr0 + t * 8 * 64;
    const float* W1 = Wr1 + t * 64 * 64;
    const float* W2 = Wr2 + t * 64 * 64;
    const float* W3 = Wr3 + t * 64 * 512;
    int tid = threadIdx.x;

    load_w_pairs64(w0p, W0, 128, tid, 512);
    load_w_pairs64(w1p, W1, 1024, tid, 512);
    load_w_pairs64(w2p, W2, 1024, tid, 512);
    for (int i = tid; i < 8192; i += 512)
        ((float4*)w3)[i] = ((const float4*)W3)[i];
    int ebase = blockIdx.x * 128;
    for (int i = tid; i < 256; i += 512)
        ((float4*)radT)[i] = ((const float4*)(d_rad + (size_t)ebase * 8))[i];
    __syncthreads();

    int ow = tid & 31;   // outputs 2ow, 2ow+1
    int eg = tid >> 5;   // edges 8eg .. 8eg+7
    const float s0 = 0.3535533905932738f;

    // ---- layer 0: 8 -> 64 ----
    {
        u64 a0[8], a1[8];
#pragma unroll
        for (int q = 0; q < 8; q++) { a0[q] = 0ull; a1[q] = 0ull; }
#pragma unroll
        for (int cph = 0; cph < 2; cph++) {
            ulonglong2 wA = *(const ulonglong2*)&w0p[(2 * cph) * 128 + 4 * ow];
            ulonglong2 wB = *(const ulonglong2*)&w0p[(2 * cph + 1) * 128 + 4 * ow];
#pragma unroll
            for (int q = 0; q < 8; q++) {
                ulonglong2 hv = *(const ulonglong2*)&radT[(8 * eg + q) * 8 + 4 * cph];
                fma2(a0[q], hv.x, wA.x); fma2(a1[q], hv.x, wA.y);
                fma2(a0[q], hv.y, wB.x); fma2(a1[q], hv.y, wB.y);
            }
        }
#pragma unroll
        for (int q = 0; q < 8; q++) {
            float v0 = silu(hsum2(a0[q]) * s0);
            float v1 = silu(hsum2(a1[q]) * s0);
            *(u64*)&hA[(8 * eg + q) * 64 + 2 * ow] = pk2(v0, v1);
        }
    }
    __syncthreads();

    // ---- layer 1: 64 -> 64 ----
    {
        u64 a0[8], a1[8];
#pragma unroll
        for (int q = 0; q < 8; q++) { a0[q] = 0ull; a1[q] = 0ull; }
#pragma unroll 4
        for (int cph = 0; cph < 16; cph++) {
            ulonglong2 wA = *(const ulonglong2*)&w1p[(2 * cph) * 128 + 4 * ow];
            ulonglong2 wB = *(const ulonglong2*)&w1p[(2 * cph + 1) * 128 + 4 * ow];
#pragma unroll
            for (int q = 0; q < 8; q++) {
                ulonglong2 hv = *(const ulonglong2*)&hA[(8 * eg + q) * 64 + 4 * cph];
                fma2(a0[q], hv.x, wA.x); fma2(a1[q], hv.x, wA.y);
                fma2(a0[q], hv.y, wB.x); fma2(a1[q], hv.y, wB.y);
            }
        }
        __syncthreads();
#pragma unroll
        for (int q = 0; q < 8; q++) {
            float v0 = silu(hsum2(a0[q]) * 0.125f);
            float v1 = silu(hsum2(a1[q]) * 0.125f);
            *(u64*)&hB[(8 * eg + q) * 64 + 2 * ow] = pk2(v0, v1);
        }
    }
    __syncthreads();

    // ---- layer 2: 64 -> 64, transposed out: hAT[o*132 + e] (aliases hA) ----
    {
        u64 a0[8], a1[8];
#pragma unroll
        for (int q = 0; q < 8; q++) { a0[q] = 0ull; a1[q] = 0ull; }
#pragma unroll 4
        for (int cph = 0; cph < 16; cph++) {
            ulonglong2 wA = *(const ulonglong2*)&w2p[(2 * cph) * 128 + 4 * ow];
            ulonglong2 wB = *(const ulonglong2*)&w2p[(2 * cph + 1) * 128 + 4 * ow];
#pragma unroll
            for (int q = 0; q < 8; q++) {
                ulonglong2 hv = *(const ulonglong2*)&hB[(8 * eg + q) * 64 + 4 * cph];
                fma2(a0[q], hv.x, wA.x); fma2(a1[q], hv.x, wA.y);
                fma2(a0[q], hv.y, wB.x); fma2(a1[q], hv.y, wB.y);
            }
        }
        __syncthreads();
#pragma unroll
        for (int q = 0; q < 8; q++) {
            int e = 8 * eg + q;
            hAT[(2 * ow) * 132 + e]     = silu(hsum2(a0[q]) * 0.125f);
            hAT[(2 * ow + 1) * 132 + e] = silu(hsum2(a1[q]) * 0.125f);
        }
    }
    __syncthreads();

    // ---- layer 3: 64 -> 512; thread = 2 outputs x 16 edges (edge-packed) ----
    {
        int oh = tid & 255;   // outputs 2oh, 2oh+1
        int eh = tid >> 8;    // 0..1
        const u64 scale2 = pk2(0.125f, 0.125f);
#pragma unroll
        for (int ch = 0; ch < 4; ch++) {
            int ebl = ch * 32 + 16 * eh;
            u64 a0[8], a1[8];   // a0: output 2oh, a1: output 2oh+1; 8 edge-pairs
#pragma unroll
            for (int q = 0; q < 8; q++) { a0[q] = 0ull; a1[q] = 0ull; }
#pragma unroll 2
            for (int c = 0; c < 64; c++) {
                u64 wp = *(const u64*)&w3[c * 512 + 2 * oh];
                float2 wf = unpk(wp);
                u64 w0 = pk2(wf.x, wf.x);
                u64 w1 = pk2(wf.y, wf.y);
                const float* hr = &hAT[c * 132 + ebl];
                ulonglong2 hp0 = *(const ulonglong2*)&hr[0];
                ulonglong2 hp1 = *(const ulonglong2*)&hr[4];
                ulonglong2 hp2 = *(const ulonglong2*)&hr[8];
                ulonglong2 hp3 = *(const ulonglong2*)&hr[12];
                fma2(a0[0], hp0.x, w0); fma2(a1[0], hp0.x, w1);
                fma2(a0[1], hp0.y, w0); fma2(a1[1], hp0.y, w1);
                fma2(a0[2], hp1.x, w0); fma2(a1[2], hp1.x, w1);
                fma2(a0[3], hp1.y, w0); fma2(a1[3], hp1.y, w1);
                fma2(a0[4], hp2.x, w0); fma2(a1[4], hp2.x, w1);
                fma2(a0[5], hp2.y, w0); fma2(a1[5], hp2.y, w1);
                fma2(a0[6], hp3.x, w0); fma2(a1[6], hp3.x, w1);
                fma2(a0[7], hp3.y, w0); fma2(a1[7], hp3.y, w1);
            }
#pragma unroll
            for (int q = 0; q < 8; q++) {
                float2 va = unpk(mul2(a0[q], scale2));
                float2 vb = unpk(mul2(a1[q], scale2));
                size_t ge = (size_t)(ebase + ebl + 2 * q);
                *(u64*)&d_tpw[ge * 512 + 2 * oh]       = pk2(va.x, vb.x);
                *(u64*)&d_tpw[(ge + 1) * 512 + 2 * oh] = pk2(va.y, vb.y);
            }
        }
    }
}

// ---------------- fused gather + wlin + final ----------------
// 512 threads, 8 nodes per block.
template<int NM, int MS>
__device__ __forceinline__ void wlin_group(float* msgS, const float* Wbuf,
                                           int k, int h) {
    const int MY = 2 * NM;  // rows per quarter (rows = 8*NM)
    u64 acc[MY];
    int roff[MY];
#pragma unroll
    for (int q = 0; q < MY; q++) {
        int r = h * MY + q;
        roff[q] = (r / NM) * 2048 + (MS + r % NM) * 128;
        acc[q] = 0ull;
    }
    for (int pp = 0; pp < 64; pp += 2) {
        u64 w01 = *(const u64*)&Wbuf[pp * 256 + 2 * k];
        u64 w23 = *(const u64*)&Wbuf[(pp + 1) * 256 + 2 * k];
#pragma unroll
        for (int q = 0; q < MY; q++) {
            ulonglong2 mv = *(const ulonglong2*)&msgS[roff[q] + 2 * pp];
            fma2(acc[q], mv.x, w01);
            fma2(acc[q], mv.y, w23);
        }
    }
    __syncthreads();  // all reads of these rows complete before in-place write
#pragma unroll
    for (int q = 0; q < MY; q++)
        msgS[roff[q] + k] = hsum2(acc[q]) * 0.08838834764831845f;
}

__global__ void __launch_bounds__(512) k_fused(
    int t, const float* __restrict__ W_lin,
    const float* __restrict__ Wp1, const float* __restrict__ Wp2,
    const float* __restrict__ Wp3, const float* __restrict__ W_prodlin,
    const int* __restrict__ edge_index) {
    extern __shared__ float sm[];
    float* msgS = sm;            // 16384
    float* Wbuf = sm + 16384;    // 16384
    float* bS   = sm + 32768;    // 1024
    int tid = threadIdx.x;
    int k = tid & 127, h = tid >> 7, lane = tid & 31;
    int nb = blockIdx.x * 8;

    // ---- phase 1: gather (quarter h handles nodes 2h, 2h+1), prefetched ----
    for (int step = 0; step < 2; step++) {
        int nl = 2 * h + step;
        int n = nb + nl;
        int lo = d_offsets[n], hi = d_offsets[n + 1];
        float acc[16];
#pragma unroll
        for (int m = 0; m < 16; m++) acc[m] = 0.f;
        int e = 0, j = 0;
        if (lo < hi) { e = d_perm[lo]; j = edge_index[e]; }
        for (int p = lo; p < hi; p++) {
            int e_cur = e, j_cur = j;
            if (p + 1 < hi) { e = d_perm[p + 1]; j = edge_index[e]; }
            float shl = (lane < 16) ? d_sh[e_cur * 16 + lane] : 0.f;
            float u = d_up[j_cur * CH + k];
            const float* tp = d_tpw + (size_t)e_cur * 512;
            float v0 = u * tp[k];
            float v1 = u * tp[CH + k];
            float v2 = u * tp[2 * CH + k];
            float v3 = u * tp[3 * CH + k];
            acc[0] += __shfl_sync(0xffffffffu, shl, 0) * v0;
#pragma unroll
            for (int m = 1; m < 4; m++) acc[m] += __shfl_sync(0xffffffffu, shl, m) * v1;
#pragma unroll
            for (int m = 4; m < 9; m++) acc[m] += __shfl_sync(0xffffffffu, shl, m) * v2;
#pragma unroll
            for (int m = 9; m < 16; m++) acc[m] += __shfl_sync(0xffffffffu, shl, m) * v3;
        }
#pragma unroll
        for (int m = 0; m < 16; m++)
            msgS[nl * 2048 + m * 128 + k] = acc[m] * 0.1f;
    }
    __syncthreads();

    // ---- phase 2: A = msg @ W_lin[l], in place (msgS becomes A) ----
    const float* WL = W_lin + (size_t)t * 4 * CH * CH;
    load_w_pairs(Wbuf, WL, tid, 512);
    __syncthreads();
    wlin_group<1, 0>(msgS, Wbuf, k, h);

    load_w_pairs(Wbuf, WL + 1 * CH * CH, tid, 512);
    __syncthreads();
    wlin_group<3, 1>(msgS, Wbuf, k, h);

    load_w_pairs(Wbuf, WL + 2 * CH * CH, tid, 512);
    __syncthreads();
    wlin_group<5, 4>(msgS, Wbuf, k, h);

    load_w_pairs(Wbuf, WL + 3 * CH * CH, tid, 512);
    __syncthreads();
    wlin_group<7, 9>(msgS, Wbuf, k, h);
    __syncthreads();  // A fully written, visible to all

    // ---- phase 3a: nonlinearity -> b (quarter h owns nodes 2h, 2h+1) ----
    for (int nn = 0; nn < 2; nn++) {
        int nl = 2 * h + nn;
        int n = nb + nl;
        const float* Ar = msgS + nl * 2048;
        float A0 = Ar[k];
        float i0 = A0 * A0, i1 = 0.f, i2 = 0.f, i3 = 0.f;
#pragma unroll
        for (int m = 1; m < 4; m++) { float a = Ar[m * 128 + k]; i1 += a * a; }
#pragma unroll
        for (int m = 4; m < 9; m++) { float a = Ar[m * 128 + k]; i2 += a * a; }
#pragma unroll
        for (int m = 9; m < 16; m++) { float a = Ar[m * 128 + k]; i3 += a * a; }
        int s = d_species[n];
        const float* p1 = Wp1 + ((size_t)t * NZ + s) * CH;
        const float* p2 = Wp2 + ((size_t)t * NZ + s) * 4 * CH;
        const float* p3 = Wp3 + ((size_t)t * NZ + s) * 4 * CH;
        float s2 = p2[k] * i0 + p2[CH + k] * i1 + p2[2 * CH + k] * i2 + p2[3 * CH + k] * i3;
        float s3v = p3[k] * i0 + p3[CH + k] * i1 + p3[2 * CH + k] * i2 + p3[3 * CH + k] * i3;
        bS[nl * 128 + k] = p1[k] * A0 + s2 + s3v * A0;
    }
    load_w_pairs(Wbuf, W_prodlin + t * CH * CH, tid, 512);
    __syncthreads();

    // ---- phase 3b: nf = b @ Wprod / sqrt(128) + scb ----
    float* nfo = (t == 0) ? d_nfB : d_nfA;
    {
        int nl0 = 2 * h, nl1 = 2 * h + 1;
        u64 a0 = 0ull, a1 = 0ull;
        for (int pp = 0; pp < 64; pp += 2) {
            u64 w01 = *(const u64*)&Wbuf[pp * 256 + 2 * k];
            u64 w23 = *(const u64*)&Wbuf[(pp + 1) * 256 + 2 * k];
            ulonglong2 b0 = *(const ulonglong2*)&bS[nl0 * 128 + 2 * pp];
            ulonglong2 b1 = *(const ulonglong2*)&bS[nl1 * 128 + 2 * pp];
            fma2(a0, b0.x, w01); fma2(a0, b0.y, w23);
            fma2(a1, b1.x, w01); fma2(a1, b1.y, w23);
        }
        nfo[(nb + nl0) * CH + k] = hsum2(a0) * 0.08838834764831845f +
                                   d_scb[(nb + nl0) * CH + k];
        nfo[(nb + nl1) * CH + k] = hsum2(a1) * 0.08838834764831845f +
                                   d_scb[(nb + nl1) * CH + k];
    }
}

// ---------------- graph mean pooling ----------------
__global__ void k_env(const int* __restrict__ batch_idx, float* __restrict__ out) {
    int tid = blockIdx.x * blockDim.x + threadIdx.x;
    if (tid >= NN * CH) return;
    int n = tid >> 7, k = tid & 127;
    int g = batch_idx[n];
    atomicAdd(&out[g * CH + k], d_nfA[tid]);
    if (k == 0) atomicAdd(&d_gcnt[g], 1.f);
}

__global__ void k_div(float* __restrict__ out) {
    int i = blockIdx.x * blockDim.x + threadIdx.x;
    if (i >= NG * CH) return;
    int g = i >> 7;
    out[i] /= fmaxf(d_gcnt[g], 1.f);
}

// ---------------- launcher ----------------
extern "C" void kernel_launch(void* const* d_in, const int* in_sizes, int n_in,
                              void* d_out, int out_size) {
    const float* x        = (const float*)d_in[0];
    const float* pos      = (const float*)d_in[1];
    const float* W_embed  = (const float*)d_in[2];
    const float* W_up     = (const float*)d_in[3];
    const float* Wr0      = (const float*)d_in[4];
    const float* Wr1      = (const float*)d_in[5];
    const float* Wr2      = (const float*)d_in[6];
    const float* Wr3      = (const float*)d_in[7];
    const float* W_lin    = (const float*)d_in[8];
    const float* W_skip   = (const float*)d_in[9];
    const float* Wp1      = (const float*)d_in[10];
    const float* Wp2      = (const float*)d_in[11];
    const float* Wp3      = (const float*)d_in[12];
    const float* W_prodlin= (const float*)d_in[13];
    const int*   edge_index = (const int*)d_in[14];
    const int*   batch_idx  = (const int*)d_in[15];
    float* out = (float*)d_out;

    const int SM_UP    = (16384 + 4096) * 4;
    const int SM_SC    = (16384 + 2048) * 4;
    const int SM_RAD   = 57600 * 4;   // 230400 B
    const int SM_FUSED = 33792 * 4;   // 132 KB
    cudaFuncSetAttribute(k_up,     cudaFuncAttributeMaxDynamicSharedMemorySize, SM_UP);
    cudaFuncSetAttribute(k_sc,     cudaFuncAttributeMaxDynamicSharedMemorySize, SM_SC);
    cudaFuncSetAttribute(k_radial, cudaFuncAttributeMaxDynamicSharedMemorySize, SM_RAD);
    cudaFuncSetAttribute(k_fused,  cudaFuncAttributeMaxDynamicSharedMemorySize, SM_FUSED);

    k_zero<<<(NN + 255) / 256, 256>>>();
    k_node_init<<<(NN * CH) / 256, 256>>>(x, W_embed);
    k_edge_geom<<<NE / 256, 256>>>(pos, edge_index);
    // radial t=0 at launch slot 4 so ncu profiles it (validate L3 edge-pack)
    k_radial<<<NE / 128, 512, SM_RAD>>>(0, Wr0, Wr1, Wr2, Wr3);
    k_scan<<<1, 1024>>>();
    k_scatter<<<NE / 256, 256>>>(edge_index);

    for (int t = 0; t < 2; t++) {
        k_up<<<NN / 32, 256, SM_UP>>>(t, W_up);
        k_sc<<<dim3(NN / 16, NZ), 128, SM_SC>>>(t, W_skip);
        if (t == 1)
            k_radial<<<NE / 128, 512, SM_RAD>>>(t, Wr0, Wr1, Wr2, Wr3);
        k_fused<<<NN / 8, 512, SM_FUSED>>>(t, W_lin, Wp1, Wp2, Wp3,
                                           W_prodlin, edge_index);
    }

    cudaMemsetAsync(d_out, 0, (size_t)out_size * sizeof(float));
    k_env<<<(NN * CH) / 256, 256>>>(batch_idx, out);
    k_div<<<(NG * CH + 255) / 256, 256>>>(out);
}

// round 16
// speedup vs baseline: 1.1721x; 1.0008x over previous
#include <cuda_runtime.h>

#define NN 16384
#define NE 65536
#define NG 64
#define NZ 10
#define CH 128

typedef unsigned long long u64;

// ---------------- scratch (device globals; no allocations) ----------------
__device__ __align__(16) float d_sh[NE * 16];
__device__ __align__(16) float d_rad[NE * 8];
__device__ __align__(16) float d_tpw[(size_t)NE * 512];
__device__ __align__(16) float d_up[NN * CH];
__device__ __align__(16) float d_scb[NN * CH];
__device__ __align__(16) float d_nfA[NN * CH];
__device__ __align__(16) float d_nfB[NN * CH];
__device__ int   d_species[NN];
__device__ int   d_count[NN];
__device__ int   d_offsets[NN + 1];
__device__ int   d_cursor[NN];
__device__ int   d_perm[NE];
__device__ int   d_scount[NZ];
__device__ int   d_soff[NZ + 1];
__device__ int   d_scursor[NZ];
__device__ int   d_sperm[NN];
__device__ float d_gcnt[NG];

__device__ __forceinline__ float silu(float x) {
    return x / (1.f + __expf(-x));
}

// ---- f32x2 packed math helpers ----
__device__ __forceinline__ u64 pk2(float a, float b) {
    u64 r; asm("mov.b64 %0, {%1, %2};" : "=l"(r) : "f"(a), "f"(b)); return r;
}
__device__ __forceinline__ void fma2(u64 &d, u64 a, u64 b) {
    asm("fma.rn.f32x2 %0, %1, %2, %0;" : "+l"(d) : "l"(a), "l"(b));
}
__device__ __forceinline__ u64 mul2(u64 a, u64 b) {
    u64 r; asm("mul.rn.f32x2 %0, %1, %2;" : "=l"(r) : "l"(a), "l"(b)); return r;
}
__device__ __forceinline__ float2 unpk(u64 v) {
    float2 r; asm("mov.b64 {%0, %1}, %2;" : "=f"(r.x), "=f"(r.y) : "l"(v)); return r;
}
__device__ __forceinline__ float hsum2(u64 v) {
    float2 s = unpk(v); return s.x + s.y;
}

// Conflict-free pair-interleave staging of a 128x128 weight matrix:
// Wp[pp*256 + 2k + c01] = W[2pp + c01][k]
__device__ __forceinline__ void load_w_pairs(float* Wp, const float* W, int tid, int nthr) {
    for (int op = tid; op < 4096; op += nthr) {
        int pp = op >> 6, j = op & 63;
        float2 a = *(const float2*)&W[(2 * pp) * CH + 2 * j];
        float2 b = *(const float2*)&W[(2 * pp + 1) * CH + 2 * j];
        ((float4*)Wp)[op] = make_float4(a.x, b.x, a.y, b.y);
    }
}

// same for 64-wide matrices (rows x 64), nfl4 = rows*64/4
__device__ __forceinline__ void load_w_pairs64(float* Wp, const float* W, int nfl4,
                                               int tid, int nthr) {
    for (int op = tid; op < nfl4; op += nthr) {
        int pp = op >> 5, j = op & 31;
        float2 a = *(const float2*)&W[(2 * pp) * 64 + 2 * j];
        float2 b = *(const float2*)&W[(2 * pp + 1) * 64 + 2 * j];
        ((float4*)Wp)[op] = make_float4(a.x, b.x, a.y, b.y);
    }
}

// ---------------- init / zero ----------------
__global__ void k_zero() {
    int i = blockIdx.x * blockDim.x + threadIdx.x;
    if (i < NN) d_count[i] = 0;
    if (i < NZ) d_scount[i] = 0;
    if (i < NG) d_gcnt[i] = 0.f;
}

__global__ void k_node_init(const float* __restrict__ x,
                            const float* __restrict__ W_embed) {
    int tid = blockIdx.x * blockDim.x + threadIdx.x;
    if (tid >= NN * CH) return;
    int n = tid >> 7, k = tid & 127;
    const float* xr = x + n * NZ;
    int s = 0;
    float best = xr[0];
#pragma unroll
    for (int z = 1; z < NZ; z++) {
        float v = xr[z];
        if (v > best) { best = v; s = z; }
    }
    if (k == 0) {
        d_species[n] = s;
        atomicAdd(&d_scount[s], 1);
    }
    d_nfA[tid] = W_embed[s * CH + k] * 0.31622776601683794f;
}

// ---------------- edge geometry: SH + radial basis + degree hist ----------
__global__ void k_edge_geom(const float* __restrict__ pos,
                            const int* __restrict__ edge_index) {
    int e = blockIdx.x * blockDim.x + threadIdx.x;
    if (e >= NE) return;
    int j = edge_index[e];
    int i = edge_index[NE + e];
    atomicAdd(&d_count[i], 1);  // fused CSR histogram
    float dx = pos[j * 3 + 0] - pos[i * 3 + 0];
    float dy = pos[j * 3 + 1] - pos[i * 3 + 1];
    float dz = pos[j * 3 + 2] - pos[i * 3 + 2];
    float r2 = dx * dx + dy * dy + dz * dz + 1e-12f;
    float r = sqrtf(r2);
    float inv = 1.f / r;
    float X = dx * inv, Y = dy * inv, Z = dz * inv;
    float x2 = X * X, y2 = Y * Y, z2 = Z * Z;

    const float s3 = 1.7320508075688772f;
    const float s15 = 3.872983346207417f;
    const float s5 = 2.23606797749979f;
    const float s35_8 = 2.091650066335189f;
    const float s105 = 10.246950765959598f;
    const float s21_8 = 1.6201851746019651f;
    const float s7 = 2.6457513110645907f;

    float sh[16];
    sh[0] = 1.f;
    sh[1] = s3 * X; sh[2] = s3 * Y; sh[3] = s3 * Z;
    sh[4] = s15 * X * Y;
    sh[5] = s15 * Y * Z;
    sh[6] = 0.5f * s5 * (3.f * z2 - 1.f);
    sh[7] = s15 * X * Z;
    sh[8] = 0.5f * s15 * (x2 - y2);
    sh[9] = s35_8 * Y * (3.f * x2 - y2);
    sh[10] = s105 * X * Y * Z;
    sh[11] = s21_8 * Y * (5.f * z2 - 1.f);
    sh[12] = 0.5f * s7 * Z * (5.f * z2 - 3.f);
    sh[13] = s21_8 * X * (5.f * z2 - 1.f);
    sh[14] = 0.5f * s105 * Z * (x2 - y2);
    sh[15] = s35_8 * X * (x2 - 3.f * y2);
#pragma unroll
    for (int q = 0; q < 4; q++)
        *(float4*)&d_sh[e * 16 + q * 4] = *(float4*)&sh[q * 4];

    float u = r * 0.2f;
    float u2 = u * u;
    float u5 = u2 * u2 * u;
    float f = 1.f - 21.f * u5 + 35.f * u5 * u - 15.f * u5 * u2;
    if (u >= 1.f) f = 0.f;
    float coef = 0.6324555320336759f * inv * f;
    float rad[8];
#pragma unroll
    for (int nb = 1; nb <= 8; nb++)
        rad[nb - 1] = coef * sinpif((float)nb * u);
    *(float4*)&d_rad[e * 8] = *(float4*)&rad[0];
    *(float4*)&d_rad[e * 8 + 4] = *(float4*)&rad[4];
}

// ---------------- CSR build ----------------
__global__ void k_scan() {
    __shared__ int sh[1024];
    int T = threadIdx.x;
    int base = T * 16;
    int loc[16];
    int s = 0;
#pragma unroll
    for (int q = 0; q < 16; q++) { loc[q] = d_count[base + q]; s += loc[q]; }
    sh[T] = s;
    __syncthreads();
    for (int off = 1; off < 1024; off <<= 1) {
        int v = (T >= off) ? sh[T - off] : 0;
        __syncthreads();
        sh[T] += v;
        __syncthreads();
    }
    int excl = sh[T] - s;
#pragma unroll
    for (int q = 0; q < 16; q++) {
        d_offsets[base + q] = excl;
        d_cursor[base + q] = excl;
        excl += loc[q];
    }
    if (T == 1023) d_offsets[NN] = sh[1023];
    if (T == 0) {
        int a = 0;
        for (int z = 0; z < NZ; z++) {
            d_soff[z] = a; d_scursor[z] = a; a += d_scount[z];
        }
        d_soff[NZ] = a;
    }
}

// edge scatter + species scatter fused
__global__ void k_scatter(const int* __restrict__ edge_index) {
    int e = blockIdx.x * blockDim.x + threadIdx.x;
    if (e < NN) {
        int s = d_species[e];
        int p = atomicAdd(&d_scursor[s], 1);
        d_sperm[p] = e;
    }
    if (e >= NE) return;
    int i = edge_index[NE + e];
    int p = atomicAdd(&d_cursor[i], 1);
    d_perm[p] = e;
}

// ---------------- up = nf @ W_up / sqrt(128) ----------------
__global__ void __launch_bounds__(256) k_up(int t, const float* __restrict__ W_up) {
    extern __shared__ float sm[];
    float* Wsh = sm;           // 16384 pair-interleaved
    float* msh = sm + 16384;   // 32 rows x 128
    int tid = threadIdx.x;
    int k = tid & 127, h = tid >> 7;
    load_w_pairs(Wsh, W_up + t * CH * CH, tid, 256);
    const float* nf = t ? d_nfB : d_nfA;
    int n0 = blockIdx.x * 32;
    for (int i = tid; i < 1024; i += 256)
        ((float4*)msh)[i] = ((const float4*)nf)[n0 * 32 + i];
    __syncthreads();
    u64 acc[16];
#pragma unroll
    for (int q = 0; q < 16; q++) acc[q] = 0ull;
    for (int pp = 0; pp < 64; pp += 2) {
        u64 w01 = *(const u64*)&Wsh[pp * 256 + 2 * k];
        u64 w23 = *(const u64*)&Wsh[(pp + 1) * 256 + 2 * k];
#pragma unroll
        for (int q = 0; q < 16; q++) {
            ulonglong2 mv = *(const ulonglong2*)&msh[(h * 16 + q) * CH + 2 * pp];
            fma2(acc[q], mv.x, w01);
            fma2(acc[q], mv.y, w23);
        }
    }
#pragma unroll
    for (int q = 0; q < 16; q++)
        d_up[(n0 + h * 16 + q) * CH + k] = hsum2(acc[q]) * 0.08838834764831845f;
}

// ---------------- sc (species-bucketed skip) ----------------
__global__ void __launch_bounds__(128) k_sc(int t, const float* __restrict__ W_skip) {
    int z = blockIdx.y;
    int lo = d_soff[z], hi = d_soff[z + 1];
    int n0 = lo + blockIdx.x * 16;
    if (n0 >= hi) return;
    extern __shared__ float sm[];
    float* Wsh = sm;
    float* msh = sm + 16384;
    __shared__ int offs[16];
    int k = threadIdx.x;
    load_w_pairs(Wsh, W_skip + ((size_t)t * NZ + z) * CH * CH, k, 128);
    int cnt = min(16, hi - n0);
    if (k < cnt) offs[k] = d_sperm[n0 + k] * CH;
    __syncthreads();
    const float* nf = t ? d_nfB : d_nfA;
    for (int i = k; i < cnt * 32; i += 128) {
        int r = i >> 5;
        ((float4*)msh)[i] = *(const float4*)(nf + offs[r] + ((i & 31) << 2));
    }
    __syncthreads();
    u64 acc[16];
#pragma unroll
    for (int q = 0; q < 16; q++) acc[q] = 0ull;
    for (int pp = 0; pp < 64; pp += 2) {
        u64 w01 = *(const u64*)&Wsh[pp * 256 + 2 * k];
        u64 w23 = *(const u64*)&Wsh[(pp + 1) * 256 + 2 * k];
#pragma unroll
        for (int q = 0; q < 16; q++) {
            ulonglong2 mv = *(const ulonglong2*)&msh[q * CH + 2 * pp];
            fma2(acc[q], mv.x, w01);
            fma2(acc[q], mv.y, w23);
        }
    }
    for (int q = 0; q < cnt; q++)
        d_scb[offs[q] + k] = hsum2(acc[q]) * 0.027950849718747372f;
}

// ---------------- radial MLP: 512 threads, ONE 128-edge tile per block ----
// L0-L2: (2 outputs ow) x (8 edges eg), LDS.128-batched.
// L3: thread = 2 outputs (w duped, 2 pk2/c) x 16 edges packed natively in
//     f32x2 lanes (h pairs are contiguous in hAT -> LDS.128, no dup movs).
// smem (floats): w1p[0,4096) w2p[4096,8192) w3[8192,40960)
//   hA/hAT[40960,49408)  hB[49408,57600) (radT/w0p alias hB during L0)
__global__ void __launch_bounds__(512) k_radial(
    int t, const float* __restrict__ Wr0, const float* __restrict__ Wr1,
    const float* __restrict__ Wr2, const float* __restrict__ Wr3) {
    extern __shared__ float sm[];
    float* w1p  = sm;            // 4096
    float* w2p  = sm + 4096;     // 4096
    float* w3   = sm + 8192;     // 32768
    float* hA   = sm + 40960;    // 8192 (L0 out / L1 in)
    float* hAT  = sm + 40960;    // 64 x 132 (L2 out / L3 in, aliases hA)
    float* hB   = sm + 49408;    // 8192 (L1 out / L2 in)
    float* radT = hB;            // 1024 (only during L0)
    float* w0p  = hB + 1024;     // 512  (only during L0)

    const float* W0 = Wr0 + t * 8 * 64;
    const float* W1 = Wr1 + t * 64 * 64;
    const float* W2 = Wr2 + t * 64 * 64;
    const float* W3 = Wr3 + t * 64 * 512;
    int tid = threadIdx.x;

    load_w_pairs64(w0p, W0, 128, tid, 512);
    load_w_pairs64(w1p, W1, 1024, tid, 512);
    load_w_pairs64(w2p, W2, 1024, tid, 512);
    for (int i = tid; i < 8192; i += 512)
        ((float4*)w3)[i] = ((const float4*)W3)[i];
    int ebase = blockIdx.x * 128;
    for (int i = tid; i < 256; i += 512)
        ((float4*)radT)[i] = ((const float4*)(d_rad + (size_t)ebase * 8))[i];
    __syncthreads();

    int ow = tid & 31;   // outputs 2ow, 2ow+1
    int eg = tid >> 5;   // edges 8eg .. 8eg+7
    const float s0 = 0.3535533905932738f;

    // ---- layer 0: 8 -> 64 ----
    {
        u64 a0[8], a1[8];
#pragma unroll
        for (int q = 0; q < 8; q++) { a0[q] = 0ull; a1[q] = 0ull; }
#pragma unroll
        for (int cph = 0; cph < 2; cph++) {
            ulonglong2 wA = *(const ulonglong2*)&w0p[(2 * cph) * 128 + 4 * ow];
            ulonglong2 wB = *(const ulonglong2*)&w0p[(2 * cph + 1) * 128 + 4 * ow];
#pragma unroll
            for (int q = 0; q < 8; q++) {
                ulonglong2 hv = *(const ulonglong2*)&radT[(8 * eg + q) * 8 + 4 * cph];
                fma2(a0[q], hv.x, wA.x); fma2(a1[q], hv.x, wA.y);
                fma2(a0[q], hv.y, wB.x); fma2(a1[q], hv.y, wB.y);
            }
        }
#pragma unroll
        for (int q = 0; q < 8; q++) {
            float v0 = silu(hsum2(a0[q]) * s0);
            float v1 = silu(hsum2(a1[q]) * s0);
            *(u64*)&hA[(8 * eg + q) * 64 + 2 * ow] = pk2(v0, v1);
        }
    }
    __syncthreads();

    // ---- layer 1: 64 -> 64 ----
    {
        u64 a0[8], a1[8];
#pragma unroll
        for (int q = 0; q < 8; q++) { a0[q] = 0ull; a1[q] = 0ull; }
#pragma unroll 4
        for (int cph = 0; cph < 16; cph++) {
            ulonglong2 wA = *(const ulonglong2*)&w1p[(2 * cph) * 128 + 4 * ow];
            ulonglong2 wB = *(const ulonglong2*)&w1p[(2 * cph + 1) * 128 + 4 * ow];
#pragma unroll
            for (int q = 0; q < 8; q++) {
                ulonglong2 hv = *(const ulonglong2*)&hA[(8 * eg + q) * 64 + 4 * cph];
                fma2(a0[q], hv.x, wA.x); fma2(a1[q], hv.x, wA.y);
                fma2(a0[q], hv.y, wB.x); fma2(a1[q], hv.y, wB.y);
            }
        }
        __syncthreads();
#pragma unroll
        for (int q = 0; q < 8; q++) {
            float v0 = silu(hsum2(a0[q]) * 0.125f);
            float v1 = silu(hsum2(a1[q]) * 0.125f);
            *(u64*)&hB[(8 * eg + q) * 64 + 2 * ow] = pk2(v0, v1);
        }
    }
    __syncthreads();

    // ---- layer 2: 64 -> 64, transposed out: hAT[o*132 + e] (aliases hA) ----
    {
        u64 a0[8], a1[8];
#pragma unroll
        for (int q = 0; q < 8; q++) { a0[q] = 0ull; a1[q] = 0ull; }
#pragma unroll 4
        for (int cph = 0; cph < 16; cph++) {
            ulonglong2 wA = *(const ulonglong2*)&w2p[(2 * cph) * 128 + 4 * ow];
            ulonglong2 wB = *(const ulonglong2*)&w2p[(2 * cph + 1) * 128 + 4 * ow];
#pragma unroll
            for (int q = 0; q < 8; q++) {
                ulonglong2 hv = *(const ulonglong2*)&hB[(8 * eg + q) * 64 + 4 * cph];
                fma2(a0[q], hv.x, wA.x); fma2(a1[q], hv.x, wA.y);
                fma2(a0[q], hv.y, wB.x); fma2(a1[q], hv.y, wB.y);
            }
        }
        __syncthreads();
#pragma unroll
        for (int q = 0; q < 8; q++) {
            int e = 8 * eg + q;
            hAT[(2 * ow) * 132 + e]     = silu(hsum2(a0[q]) * 0.125f);
            hAT[(2 * ow + 1) * 132 + e] = silu(hsum2(a1[q]) * 0.125f);
        }
    }
    __syncthreads();

    // ---- layer 3: 64 -> 512; thread = 2 outputs x 16 edges (edge-packed) ----
    {
        int oh = tid & 255;   // outputs 2oh, 2oh+1
        int eh = tid >> 8;    // 0..1
        const u64 scale2 = pk2(0.125f, 0.125f);
#pragma unroll
        for (int ch = 0; ch < 4; ch++) {
            int ebl = ch * 32 + 16 * eh;
            u64 a0[8], a1[8];   // a0: output 2oh, a1: output 2oh+1; 8 edge-pairs
#pragma unroll
            for (int q = 0; q < 8; q++) { a0[q] = 0ull; a1[q] = 0ull; }
#pragma unroll 2
            for (int c = 0; c < 64; c++) {
                u64 wp = *(const u64*)&w3[c * 512 + 2 * oh];
                float2 wf = unpk(wp);
                u64 w0 = pk2(wf.x, wf.x);
                u64 w1 = pk2(wf.y, wf.y);
                const float* hr = &hAT[c * 132 + ebl];
                ulonglong2 hp0 = *(const ulonglong2*)&hr[0];
                ulonglong2 hp1 = *(const ulonglong2*)&hr[4];
                ulonglong2 hp2 = *(const ulonglong2*)&hr[8];
                ulonglong2 hp3 = *(const ulonglong2*)&hr[12];
                fma2(a0[0], hp0.x, w0); fma2(a1[0], hp0.x, w1);
                fma2(a0[1], hp0.y, w0); fma2(a1[1], hp0.y, w1);
                fma2(a0[2], hp1.x, w0); fma2(a1[2], hp1.x, w1);
                fma2(a0[3], hp1.y, w0); fma2(a1[3], hp1.y, w1);
                fma2(a0[4], hp2.x, w0); fma2(a1[4], hp2.x, w1);
                fma2(a0[5], hp2.y, w0); fma2(a1[5], hp2.y, w1);
                fma2(a0[6], hp3.x, w0); fma2(a1[6], hp3.x, w1);
                fma2(a0[7], hp3.y, w0); fma2(a1[7], hp3.y, w1);
            }
#pragma unroll
            for (int q = 0; q < 8; q++) {
                float2 va = unpk(mul2(a0[q], scale2));
                float2 vb = unpk(mul2(a1[q], scale2));
                size_t ge = (size_t)(ebase + ebl + 2 * q);
                *(u64*)&d_tpw[ge * 512 + 2 * oh]       = pk2(va.x, vb.x);
                *(u64*)&d_tpw[(ge + 1) * 512 + 2 * oh] = pk2(va.y, vb.y);
            }
        }
    }
}

// ---------------- fused gather + wlin + final ----------------
// 512 threads, 8 nodes per block.
template<int NM, int MS>
__device__ __forceinline__ void wlin_group(float* msgS, const float* Wbuf,
                                           int k, int h) {
    const int MY = 2 * NM;  // rows per quarter (rows = 8*NM)
    u64 acc[MY];
    int roff[MY];
#pragma unroll
    for (int q = 0; q < MY; q++) {
        int r = h * MY + q;
        roff[q] = (r / NM) * 2048 + (MS + r % NM) * 128;
        acc[q] = 0ull;
    }
    for (int pp = 0; pp < 64; pp += 2) {
        u64 w01 = *(const u64*)&Wbuf[pp * 256 + 2 * k];
        u64 w23 = *(const u64*)&Wbuf[(pp + 1) * 256 + 2 * k];
#pragma unroll
        for (int q = 0; q < MY; q++) {
            ulonglong2 mv = *(const ulonglong2*)&msgS[roff[q] + 2 * pp];
            fma2(acc[q], mv.x, w01);
            fma2(acc[q], mv.y, w23);
        }
    }
    __syncthreads();  // all reads of these rows complete before in-place write
#pragma unroll
    for (int q = 0; q < MY; q++)
        msgS[roff[q] + k] = hsum2(acc[q]) * 0.08838834764831845f;
}

__global__ void __launch_bounds__(512) k_fused(
    int t, const float* __restrict__ W_lin,
    const float* __restrict__ Wp1, const float* __restrict__ Wp2,
    const float* __restrict__ Wp3, const float* __restrict__ W_prodlin,
    const int* __restrict__ edge_index) {
    extern __shared__ float sm[];
    float* msgS = sm;            // 16384
    float* Wbuf = sm + 16384;    // 16384
    float* bS   = sm + 32768;    // 1024
    int tid = threadIdx.x;
    int k = tid & 127, h = tid >> 7, lane = tid & 31;
    int nb = blockIdx.x * 8;

    // ---- phase 1: gather (quarter h handles nodes 2h, 2h+1), prefetched ----
    for (int step = 0; step < 2; step++) {
        int nl = 2 * h + step;
        int n = nb + nl;
        int lo = d_offsets[n], hi = d_offsets[n + 1];
        float acc[16];
#pragma unroll
        for (int m = 0; m < 16; m++) acc[m] = 0.f;
        int e = 0, j = 0;
        if (lo < hi) { e = d_perm[lo]; j = edge_index[e]; }
        for (int p = lo; p < hi; p++) {
            int e_cur = e, j_cur = j;
            if (p + 1 < hi) { e = d_perm[p + 1]; j = edge_index[e]; }
            float shl = (lane < 16) ? d_sh[e_cur * 16 + lane] : 0.f;
            float u = d_up[j_cur * CH + k];
            const float* tp = d_tpw + (size_t)e_cur * 512;
            float v0 = u * tp[k];
            float v1 = u * tp[CH + k];
            float v2 = u * tp[2 * CH + k];
            float v3 = u * tp[3 * CH + k];
            acc[0] += __shfl_sync(0xffffffffu, shl, 0) * v0;
#pragma unroll
            for (int m = 1; m < 4; m++) acc[m] += __shfl_sync(0xffffffffu, shl, m) * v1;
#pragma unroll
            for (int m = 4; m < 9; m++) acc[m] += __shfl_sync(0xffffffffu, shl, m) * v2;
#pragma unroll
            for (int m = 9; m < 16; m++) acc[m] += __shfl_sync(0xffffffffu, shl, m) * v3;
        }
#pragma unroll
        for (int m = 0; m < 16; m++)
            msgS[nl * 2048 + m * 128 + k] = acc[m] * 0.1f;
    }
    __syncthreads();

    // ---- phase 2: A = msg @ W_lin[l], in place (msgS becomes A) ----
    const float* WL = W_lin + (size_t)t * 4 * CH * CH;
    load_w_pairs(Wbuf, WL, tid, 512);
    __syncthreads();
    wlin_group<1, 0>(msgS, Wbuf, k, h);

    load_w_pairs(Wbuf, WL + 1 * CH * CH, tid, 512);
    __syncthreads();
    wlin_group<3, 1>(msgS, Wbuf, k, h);

    load_w_pairs(Wbuf, WL + 2 * CH * CH, tid, 512);
    __syncthreads();
    wlin_group<5, 4>(msgS, Wbuf, k, h);

    load_w_pairs(Wbuf, WL + 3 * CH * CH, tid, 512);
    __syncthreads();
    wlin_group<7, 9>(msgS, Wbuf, k, h);
    __syncthreads();  // A fully written, visible to all

    // ---- phase 3a: nonlinearity -> b (quarter h owns nodes 2h, 2h+1) ----
    for (int nn = 0; nn < 2; nn++) {
        int nl = 2 * h + nn;
        int n = nb + nl;
        const float* Ar = msgS + nl * 2048;
        float A0 = Ar[k];
        float i0 = A0 * A0, i1 = 0.f, i2 = 0.f, i3 = 0.f;
#pragma unroll
        for (int m = 1; m < 4; m++) { float a = Ar[m * 128 + k]; i1 += a * a; }
#pragma unroll
        for (int m = 4; m < 9; m++) { float a = Ar[m * 128 + k]; i2 += a * a; }
#pragma unroll
        for (int m = 9; m < 16; m++) { float a = Ar[m * 128 + k]; i3 += a * a; }
        int s = d_species[n];
        const float* p1 = Wp1 + ((size_t)t * NZ + s) * CH;
        const float* p2 = Wp2 + ((size_t)t * NZ + s) * 4 * CH;
        const float* p3 = Wp3 + ((size_t)t * NZ + s) * 4 * CH;
        float s2 = p2[k] * i0 + p2[CH + k] * i1 + p2[2 * CH + k] * i2 + p2[3 * CH + k] * i3;
        float s3v = p3[k] * i0 + p3[CH + k] * i1 + p3[2 * CH + k] * i2 + p3[3 * CH + k] * i3;
        bS[nl * 128 + k] = p1[k] * A0 + s2 + s3v * A0;
    }
    load_w_pairs(Wbuf, W_prodlin + t * CH * CH, tid, 512);
    __syncthreads();

    // ---- phase 3b: nf = b @ Wprod / sqrt(128) + scb ----
    float* nfo = (t == 0) ? d_nfB : d_nfA;
    {
        int nl0 = 2 * h, nl1 = 2 * h + 1;
        u64 a0 = 0ull, a1 = 0ull;
        for (int pp = 0; pp < 64; pp += 2) {
            u64 w01 = *(const u64*)&Wbuf[pp * 256 + 2 * k];
            u64 w23 = *(const u64*)&Wbuf[(pp + 1) * 256 + 2 * k];
            ulonglong2 b0 = *(const ulonglong2*)&bS[nl0 * 128 + 2 * pp];
            ulonglong2 b1 = *(const ulonglong2*)&bS[nl1 * 128 + 2 * pp];
            fma2(a0, b0.x, w01); fma2(a0, b0.y, w23);
            fma2(a1, b1.x, w01); fma2(a1, b1.y, w23);
        }
        nfo[(nb + nl0) * CH + k] = hsum2(a0) * 0.08838834764831845f +
                                   d_scb[(nb + nl0) * CH + k];
        nfo[(nb + nl1) * CH + k] = hsum2(a1) * 0.08838834764831845f +
                                   d_scb[(nb + nl1) * CH + k];
    }
}

// ---------------- graph mean pooling ----------------
__global__ void k_env(const int* __restrict__ batch_idx, float* __restrict__ out) {
    int tid = blockIdx.x * blockDim.x + threadIdx.x;
    if (tid >= NN * CH) return;
    int n = tid >> 7, k = tid & 127;
    int g = batch_idx[n];
    atomicAdd(&out[g * CH + k], d_nfA[tid]);
    if (k == 0) atomicAdd(&d_gcnt[g], 1.f);
}

__global__ void k_div(float* __restrict__ out) {
    int i = blockIdx.x * blockDim.x + threadIdx.x;
    if (i >= NG * CH) return;
    int g = i >> 7;
    out[i] /= fmaxf(d_gcnt[g], 1.f);
}

// ---------------- launcher ----------------
extern "C" void kernel_launch(void* const* d_in, const int* in_sizes, int n_in,
                              void* d_out, int out_size) {
    const float* x        = (const float*)d_in[0];
    const float* pos      = (const float*)d_in[1];
    const float* W_embed  = (const float*)d_in[2];
    const float* W_up     = (const float*)d_in[3];
    const float* Wr0      = (const float*)d_in[4];
    const float* Wr1      = (const float*)d_in[5];
    const float* Wr2      = (const float*)d_in[6];
    const float* Wr3      = (const float*)d_in[7];
    const float* W_lin    = (const float*)d_in[8];
    const float* W_skip   = (const float*)d_in[9];
    const float* Wp1      = (const float*)d_in[10];
    const float* Wp2      = (const float*)d_in[11];
    const float* Wp3      = (const float*)d_in[12];
    const float* W_prodlin= (const float*)d_in[13];
    const int*   edge_index = (const int*)d_in[14];
    const int*   batch_idx  = (const int*)d_in[15];
    float* out = (float*)d_out;

    const int SM_UP    = (16384 + 4096) * 4;
    const int SM_SC    = (16384 + 2048) * 4;
    const int SM_RAD   = 57600 * 4;   // 230400 B
    const int SM_FUSED = 33792 * 4;   // 132 KB
    cudaFuncSetAttribute(k_up,     cudaFuncAttributeMaxDynamicSharedMemorySize, SM_UP);
    cudaFuncSetAttribute(k_sc,     cudaFuncAttributeMaxDynamicSharedMemorySize, SM_SC);
    cudaFuncSetAttribute(k_radial, cudaFuncAttributeMaxDynamicSharedMemorySize, SM_RAD);
    cudaFuncSetAttribute(k_fused,  cudaFuncAttributeMaxDynamicSharedMemorySize, SM_FUSED);

    k_zero<<<(NN + 255) / 256, 256>>>();
    k_node_init<<<(NN * CH) / 256, 256>>>(x, W_embed);
    k_edge_geom<<<NE / 256, 256>>>(pos, edge_index);
    // radial t=0 at launch slot 4 so ncu profiles it (validate L3 edge-pack)
    k_radial<<<NE / 128, 512, SM_RAD>>>(0, Wr0, Wr1, Wr2, Wr3);
    k_scan<<<1, 1024>>>();
    k_scatter<<<NE / 256, 256>>>(edge_index);

    for (int t = 0; t < 2; t++) {
        k_up<<<NN / 32, 256, SM_UP>>>(t, W_up);
        k_sc<<<dim3(NN / 16, NZ), 128, SM_SC>>>(t, W_skip);
        if (t == 1)
            k_radial<<<NE / 128, 512, SM_RAD>>>(t, Wr0, Wr1, Wr2, Wr3);
        k_fused<<<NN / 8, 512, SM_FUSED>>>(t, W_lin, Wp1, Wp2, Wp3,
                                           W_prodlin, edge_index);
    }

    cudaMemsetAsync(d_out, 0, (size_t)out_size * sizeof(float));
    k_env<<<(NN * CH) / 256, 256>>>(batch_idx, out);
    k_div<<<(NG * CH + 255) / 256, 256>>>(out);
}

// round 17
// speedup vs baseline: 1.1723x; 1.0002x over previous
#include <cuda_runtime.h>

#define NN 16384
#define NE 65536
#define NG 64
#define NZ 10
#define CH 128

typedef unsigned long long u64;

// ---------------- scratch (device globals; no allocations) ----------------
__device__ __align__(16) float d_sh[NE * 16];
__device__ __align__(16) float d_rad[NE * 8];
__device__ __align__(16) float d_tpw[(size_t)NE * 512];
__device__ __align__(16) float d_up[NN * CH];
__device__ __align__(16) float d_scb[NN * CH];
__device__ __align__(16) float d_nfA[NN * CH];
__device__ __align__(16) float d_nfB[NN * CH];
__device__ int   d_species[NN];
__device__ int   d_count[NN];
__device__ int   d_offsets[NN + 1];
__device__ int   d_cursor[NN];
__device__ int   d_perm[NE];
__device__ int   d_scount[NZ];
__device__ int   d_soff[NZ + 1];
__device__ int   d_scursor[NZ];
__device__ int   d_sperm[NN];
__device__ float d_gcnt[NG];

__device__ __forceinline__ float silu(float x) {
    return x / (1.f + __expf(-x));
}

// ---- f32x2 packed math helpers ----
__device__ __forceinline__ u64 pk2(float a, float b) {
    u64 r; asm("mov.b64 %0, {%1, %2};" : "=l"(r) : "f"(a), "f"(b)); return r;
}
__device__ __forceinline__ void fma2(u64 &d, u64 a, u64 b) {
    asm("fma.rn.f32x2 %0, %1, %2, %0;" : "+l"(d) : "l"(a), "l"(b));
}
__device__ __forceinline__ u64 mul2(u64 a, u64 b) {
    u64 r; asm("mul.rn.f32x2 %0, %1, %2;" : "=l"(r) : "l"(a), "l"(b)); return r;
}
__device__ __forceinline__ float2 unpk(u64 v) {
    float2 r; asm("mov.b64 {%0, %1}, %2;" : "=f"(r.x), "=f"(r.y) : "l"(v)); return r;
}
__device__ __forceinline__ float hsum2(u64 v) {
    float2 s = unpk(v); return s.x + s.y;
}

// Conflict-free pair-interleave staging of a 128x128 weight matrix:
// Wp[pp*256 + 2k + c01] = W[2pp + c01][k]
__device__ __forceinline__ void load_w_pairs(float* Wp, const float* W, int tid, int nthr) {
    for (int op = tid; op < 4096; op += nthr) {
        int pp = op >> 6, j = op & 63;
        float2 a = *(const float2*)&W[(2 * pp) * CH + 2 * j];
        float2 b = *(const float2*)&W[(2 * pp + 1) * CH + 2 * j];
        ((float4*)Wp)[op] = make_float4(a.x, b.x, a.y, b.y);
    }
}

// same for 64-wide matrices (rows x 64), nfl4 = rows*64/4
__device__ __forceinline__ void load_w_pairs64(float* Wp, const float* W, int nfl4,
                                               int tid, int nthr) {
    for (int op = tid; op < nfl4; op += nthr) {
        int pp = op >> 5, j = op & 31;
        float2 a = *(const float2*)&W[(2 * pp) * 64 + 2 * j];
        float2 b = *(const float2*)&W[(2 * pp + 1) * 64 + 2 * j];
        ((float4*)Wp)[op] = make_float4(a.x, b.x, a.y, b.y);
    }
}

// ---------------- init / zero ----------------
__global__ void k_zero() {
    int i = blockIdx.x * blockDim.x + threadIdx.x;
    if (i < NN) d_count[i] = 0;
    if (i < NZ) d_scount[i] = 0;
    if (i < NG) d_gcnt[i] = 0.f;
}

__global__ void k_node_init(const float* __restrict__ x,
                            const float* __restrict__ W_embed) {
    int tid = blockIdx.x * blockDim.x + threadIdx.x;
    if (tid >= NN * CH) return;
    int n = tid >> 7, k = tid & 127;
    const float* xr = x + n * NZ;
    int s = 0;
    float best = xr[0];
#pragma unroll
    for (int z = 1; z < NZ; z++) {
        float v = xr[z];
        if (v > best) { best = v; s = z; }
    }
    if (k == 0) {
        d_species[n] = s;
        atomicAdd(&d_scount[s], 1);
    }
    d_nfA[tid] = W_embed[s * CH + k] * 0.31622776601683794f;
}

// ---------------- edge geometry: SH + radial basis + degree hist ----------
__global__ void k_edge_geom(const float* __restrict__ pos,
                            const int* __restrict__ edge_index) {
    int e = blockIdx.x * blockDim.x + threadIdx.x;
    if (e >= NE) return;
    int j = edge_index[e];
    int i = edge_index[NE + e];
    atomicAdd(&d_count[i], 1);  // fused CSR histogram
    float dx = pos[j * 3 + 0] - pos[i * 3 + 0];
    float dy = pos[j * 3 + 1] - pos[i * 3 + 1];
    float dz = pos[j * 3 + 2] - pos[i * 3 + 2];
    float r2 = dx * dx + dy * dy + dz * dz + 1e-12f;
    float r = sqrtf(r2);
    float inv = 1.f / r;
    float X = dx * inv, Y = dy * inv, Z = dz * inv;
    float x2 = X * X, y2 = Y * Y, z2 = Z * Z;

    const float s3 = 1.7320508075688772f;
    const float s15 = 3.872983346207417f;
    const float s5 = 2.23606797749979f;
    const float s35_8 = 2.091650066335189f;
    const float s105 = 10.246950765959598f;
    const float s21_8 = 1.6201851746019651f;
    const float s7 = 2.6457513110645907f;

    float sh[16];
    sh[0] = 1.f;
    sh[1] = s3 * X; sh[2] = s3 * Y; sh[3] = s3 * Z;
    sh[4] = s15 * X * Y;
    sh[5] = s15 * Y * Z;
    sh[6] = 0.5f * s5 * (3.f * z2 - 1.f);
    sh[7] = s15 * X * Z;
    sh[8] = 0.5f * s15 * (x2 - y2);
    sh[9] = s35_8 * Y * (3.f * x2 - y2);
    sh[10] = s105 * X * Y * Z;
    sh[11] = s21_8 * Y * (5.f * z2 - 1.f);
    sh[12] = 0.5f * s7 * Z * (5.f * z2 - 3.f);
    sh[13] = s21_8 * X * (5.f * z2 - 1.f);
    sh[14] = 0.5f * s105 * Z * (x2 - y2);
    sh[15] = s35_8 * X * (x2 - 3.f * y2);
#pragma unroll
    for (int q = 0; q < 4; q++)
        *(float4*)&d_sh[e * 16 + q * 4] = *(float4*)&sh[q * 4];

    float u = r * 0.2f;
    float u2 = u * u;
    float u5 = u2 * u2 * u;
    float f = 1.f - 21.f * u5 + 35.f * u5 * u - 15.f * u5 * u2;
    if (u >= 1.f) f = 0.f;
    float coef = 0.6324555320336759f * inv * f;
    float rad[8];
#pragma unroll
    for (int nb = 1; nb <= 8; nb++)
        rad[nb - 1] = coef * sinpif((float)nb * u);
    *(float4*)&d_rad[e * 8] = *(float4*)&rad[0];
    *(float4*)&d_rad[e * 8 + 4] = *(float4*)&rad[4];
}

// ---------------- CSR build ----------------
__global__ void k_scan() {
    __shared__ int sh[1024];
    int T = threadIdx.x;
    int base = T * 16;
    int loc[16];
    int s = 0;
#pragma unroll
    for (int q = 0; q < 16; q++) { loc[q] = d_count[base + q]; s += loc[q]; }
    sh[T] = s;
    __syncthreads();
    for (int off = 1; off < 1024; off <<= 1) {
        int v = (T >= off) ? sh[T - off] : 0;
        __syncthreads();
        sh[T] += v;
        __syncthreads();
    }
    int excl = sh[T] - s;
#pragma unroll
    for (int q = 0; q < 16; q++) {
        d_offsets[base + q] = excl;
        d_cursor[base + q] = excl;
        excl += loc[q];
    }
    if (T == 1023) d_offsets[NN] = sh[1023];
    if (T == 0) {
        int a = 0;
        for (int z = 0; z < NZ; z++) {
            d_soff[z] = a; d_scursor[z] = a; a += d_scount[z];
        }
        d_soff[NZ] = a;
    }
}

// edge scatter + species scatter fused
__global__ void k_scatter(const int* __restrict__ edge_index) {
    int e = blockIdx.x * blockDim.x + threadIdx.x;
    if (e < NN) {
        int s = d_species[e];
        int p = atomicAdd(&d_scursor[s], 1);
        d_sperm[p] = e;
    }
    if (e >= NE) return;
    int i = edge_index[NE + e];
    int p = atomicAdd(&d_cursor[i], 1);
    d_perm[p] = e;
}

// ---------------- up = nf @ W_up / sqrt(128) ----------------
__global__ void __launch_bounds__(256) k_up(int t, const float* __restrict__ W_up) {
    extern __shared__ float sm[];
    float* Wsh = sm;           // 16384 pair-interleaved
    float* msh = sm + 16384;   // 32 rows x 128
    int tid = threadIdx.x;
    int k = tid & 127, h = tid >> 7;
    load_w_pairs(Wsh, W_up + t * CH * CH, tid, 256);
    const float* nf = t ? d_nfB : d_nfA;
    int n0 = blockIdx.x * 32;
    for (int i = tid; i < 1024; i += 256)
        ((float4*)msh)[i] = ((const float4*)nf)[n0 * 32 + i];
    __syncthreads();
    u64 acc[16];
#pragma unroll
    for (int q = 0; q < 16; q++) acc[q] = 0ull;
    for (int pp = 0; pp < 64; pp += 2) {
        u64 w01 = *(const u64*)&Wsh[pp * 256 + 2 * k];
        u64 w23 = *(const u64*)&Wsh[(pp + 1) * 256 + 2 * k];
#pragma unroll
        for (int q = 0; q < 16; q++) {
            ulonglong2 mv = *(const ulonglong2*)&msh[(h * 16 + q) * CH + 2 * pp];
            fma2(acc[q], mv.x, w01);
            fma2(acc[q], mv.y, w23);
        }
    }
#pragma unroll
    for (int q = 0; q < 16; q++)
        d_up[(n0 + h * 16 + q) * CH + k] = hsum2(acc[q]) * 0.08838834764831845f;
}

// ---------------- sc (species-bucketed skip) ----------------
__global__ void __launch_bounds__(128) k_sc(int t, const float* __restrict__ W_skip) {
    int z = blockIdx.y;
    int lo = d_soff[z], hi = d_soff[z + 1];
    int n0 = lo + blockIdx.x * 16;
    if (n0 >= hi) return;
    extern __shared__ float sm[];
    float* Wsh = sm;
    float* msh = sm + 16384;
    __shared__ int offs[16];
    int k = threadIdx.x;
    load_w_pairs(Wsh, W_skip + ((size_t)t * NZ + z) * CH * CH, k, 128);
    int cnt = min(16, hi - n0);
    if (k < cnt) offs[k] = d_sperm[n0 + k] * CH;
    __syncthreads();
    const float* nf = t ? d_nfB : d_nfA;
    for (int i = k; i < cnt * 32; i += 128) {
        int r = i >> 5;
        ((float4*)msh)[i] = *(const float4*)(nf + offs[r] + ((i & 31) << 2));
    }
    __syncthreads();
    u64 acc[16];
#pragma unroll
    for (int q = 0; q < 16; q++) acc[q] = 0ull;
    for (int pp = 0; pp < 64; pp += 2) {
        u64 w01 = *(const u64*)&Wsh[pp * 256 + 2 * k];
        u64 w23 = *(const u64*)&Wsh[(pp + 1) * 256 + 2 * k];
#pragma unroll
        for (int q = 0; q < 16; q++) {
            ulonglong2 mv = *(const ulonglong2*)&msh[q * CH + 2 * pp];
            fma2(acc[q], mv.x, w01);
            fma2(acc[q], mv.y, w23);
        }
    }
    for (int q = 0; q < cnt; q++)
        d_scb[offs[q] + k] = hsum2(acc[q]) * 0.027950849718747372f;
}

// ---------------- radial MLP: 512 threads, ONE 128-edge tile per block ----
// L0-L2: (2 outputs ow) x (8 edges eg), LDS.128-batched.
// L3: thread = 2 outputs (w duped, 2 pk2/c) x 16 edges packed natively in
//     f32x2 lanes (h pairs are contiguous in hAT -> LDS.128, no dup movs).
// smem (floats): w1p[0,4096) w2p[4096,8192) w3[8192,40960)
//   hA/hAT[40960,49408)  hB[49408,57600) (radT/w0p alias hB during L0)
__global__ void __launch_bounds__(512) k_radial(
    int t, const float* __restrict__ Wr0, const float* __restrict__ Wr1,
    const float* __restrict__ Wr2, const float* __restrict__ Wr3) {
    extern __shared__ float sm[];
    float* w1p  = sm;            // 4096
    float* w2p  = sm + 4096;     // 4096
    float* w3   = sm + 8192;     // 32768
    float* hA   = sm + 40960;    // 8192 (L0 out / L1 in)
    float* hAT  = sm + 40960;    // 64 x 132 (L2 out / L3 in, aliases hA)
    float* hB   = sm + 49408;    // 8192 (L1 out / L2 in)
    float* radT = hB;            // 1024 (only during L0)
    float* w0p  = hB + 1024;     // 512  (only during L0)

    const float* W0 = Wr0 + t * 8 * 64;
    const float* W1 = Wr1 + t * 64 * 64;
    const float* W2 = Wr2 + t * 64 * 64;
    const float* W3 = Wr3 + t * 64 * 512;
    int tid = threadIdx.x;

    load_w_pairs64(w0p, W0, 128, tid, 512);
    load_w_pairs64(w1p, W1, 1024, tid, 512);
    load_w_pairs64(w2p, W2, 1024, tid, 512);
    for (int i = tid; i < 8192; i += 512)
        ((float4*)w3)[i] = ((const float4*)W3)[i];
    int ebase = blockIdx.x * 128;
    for (int i = tid; i < 256; i += 512)
        ((float4*)radT)[i] = ((const float4*)(d_rad + (size_t)ebase * 8))[i];
    __syncthreads();

    int ow = tid & 31;   // outputs 2ow, 2ow+1
    int eg = tid >> 5;   // edges 8eg .. 8eg+7
    const float s0 = 0.3535533905932738f;

    // ---- layer 0: 8 -> 64 ----
    {
        u64 a0[8], a1[8];
#pragma unroll
        for (int q = 0; q < 8; q++) { a0[q] = 0ull; a1[q] = 0ull; }
#pragma unroll
        for (int cph = 0; cph < 2; cph++) {
            ulonglong2 wA = *(const ulonglong2*)&w0p[(2 * cph) * 128 + 4 * ow];
            ulonglong2 wB = *(const ulonglong2*)&w0p[(2 * cph + 1) * 128 + 4 * ow];
#pragma unroll
            for (int q = 0; q < 8; q++) {
                ulonglong2 hv = *(const ulonglong2*)&radT[(8 * eg + q) * 8 + 4 * cph];
                fma2(a0[q], hv.x, wA.x); fma2(a1[q], hv.x, wA.y);
                fma2(a0[q], hv.y, wB.x); fma2(a1[q], hv.y, wB.y);
            }
        }
#pragma unroll
        for (int q = 0; q < 8; q++) {
            float v0 = silu(hsum2(a0[q]) * s0);
            float v1 = silu(hsum2(a1[q]) * s0);
            *(u64*)&hA[(8 * eg + q) * 64 + 2 * ow] = pk2(v0, v1);
        }
    }
    __syncthreads();

    // ---- layer 1: 64 -> 64 ----
    {
        u64 a0[8], a1[8];
#pragma unroll
        for (int q = 0; q < 8; q++) { a0[q] = 0ull; a1[q] = 0ull; }
#pragma unroll 4
        for (int cph = 0; cph < 16; cph++) {
            ulonglong2 wA = *(const ulonglong2*)&w1p[(2 * cph) * 128 + 4 * ow];
            ulonglong2 wB = *(const ulonglong2*)&w1p[(2 * cph + 1) * 128 + 4 * ow];
#pragma unroll
            for (int q = 0; q < 8; q++) {
                ulonglong2 hv = *(const ulonglong2*)&hA[(8 * eg + q) * 64 + 4 * cph];
                fma2(a0[q], hv.x, wA.x); fma2(a1[q], hv.x, wA.y);
                fma2(a0[q], hv.y, wB.x); fma2(a1[q], hv.y, wB.y);
            }
        }
        __syncthreads();
#pragma unroll
        for (int q = 0; q < 8; q++) {
            float v0 = silu(hsum2(a0[q]) * 0.125f);
            float v1 = silu(hsum2(a1[q]) * 0.125f);
            *(u64*)&hB[(8 * eg + q) * 64 + 2 * ow] = pk2(v0, v1);
        }
    }
    __syncthreads();

    // ---- layer 2: 64 -> 64, transposed out: hAT[o*132 + e] (aliases hA) ----
    {
        u64 a0[8], a1[8];
#pragma unroll
        for (int q = 0; q < 8; q++) { a0[q] = 0ull; a1[q] = 0ull; }
#pragma unroll 4
        for (int cph = 0; cph < 16; cph++) {
            ulonglong2 wA = *(const ulonglong2*)&w2p[(2 * cph) * 128 + 4 * ow];
            ulonglong2 wB = *(const ulonglong2*)&w2p[(2 * cph + 1) * 128 + 4 * ow];
#pragma unroll
            for (int q = 0; q < 8; q++) {
                ulonglong2 hv = *(const ulonglong2*)&hB[(8 * eg + q) * 64 + 4 * cph];
                fma2(a0[q], hv.x, wA.x); fma2(a1[q], hv.x, wA.y);
                fma2(a0[q], hv.y, wB.x); fma2(a1[q], hv.y, wB.y);
            }
        }
        __syncthreads();
#pragma unroll
        for (int q = 0; q < 8; q++) {
            int e = 8 * eg + q;
            hAT[(2 * ow) * 132 + e]     = silu(hsum2(a0[q]) * 0.125f);
            hAT[(2 * ow + 1) * 132 + e] = silu(hsum2(a1[q]) * 0.125f);
        }
    }
    __syncthreads();

    // ---- layer 3: 64 -> 512; thread = 2 outputs x 16 edges (edge-packed) ----
    {
        int oh = tid & 255;   // outputs 2oh, 2oh+1
        int eh = tid >> 8;    // 0..1
        const u64 scale2 = pk2(0.125f, 0.125f);
#pragma unroll
        for (int ch = 0; ch < 4; ch++) {
            int ebl = ch * 32 + 16 * eh;
            u64 a0[8], a1[8];   // a0: output 2oh, a1: output 2oh+1; 8 edge-pairs
#pragma unroll
            for (int q = 0; q < 8; q++) { a0[q] = 0ull; a1[q] = 0ull; }
#pragma unroll 2
            for (int c = 0; c < 64; c++) {
                u64 wp = *(const u64*)&w3[c * 512 + 2 * oh];
                float2 wf = unpk(wp);
                u64 w0 = pk2(wf.x, wf.x);
                u64 w1 = pk2(wf.y, wf.y);
                const float* hr = &hAT[c * 132 + ebl];
                ulonglong2 hp0 = *(const ulonglong2*)&hr[0];
                ulonglong2 hp1 = *(const ulonglong2*)&hr[4];
                ulonglong2 hp2 = *(const ulonglong2*)&hr[8];
                ulonglong2 hp3 = *(const ulonglong2*)&hr[12];
                fma2(a0[0], hp0.x, w0); fma2(a1[0], hp0.x, w1);
                fma2(a0[1], hp0.y, w0); fma2(a1[1], hp0.y, w1);
                fma2(a0[2], hp1.x, w0); fma2(a1[2], hp1.x, w1);
                fma2(a0[3], hp1.y, w0); fma2(a1[3], hp1.y, w1);
                fma2(a0[4], hp2.x, w0); fma2(a1[4], hp2.x, w1);
                fma2(a0[5], hp2.y, w0); fma2(a1[5], hp2.y, w1);
                fma2(a0[6], hp3.x, w0); fma2(a1[6], hp3.x, w1);
                fma2(a0[7], hp3.y, w0); fma2(a1[7], hp3.y, w1);
            }
#pragma unroll
            for (int q = 0; q < 8; q++) {
                float2 va = unpk(mul2(a0[q], scale2));
                float2 vb = unpk(mul2(a1[q], scale2));
                size_t ge = (size_t)(ebase + ebl + 2 * q);
                *(u64*)&d_tpw[ge * 512 + 2 * oh]       = pk2(va.x, vb.x);
                *(u64*)&d_tpw[(ge + 1) * 512 + 2 * oh] = pk2(va.y, vb.y);
            }
        }
    }
}

// ---------------- fused gather + wlin + final ----------------
// 512 threads, 8 nodes per block.
template<int NM, int MS>
__device__ __forceinline__ void wlin_group(float* msgS, const float* Wbuf,
                                           int k, int h) {
    const int MY = 2 * NM;  // rows per quarter (rows = 8*NM)
    u64 acc[MY];
    int roff[MY];
#pragma unroll
    for (int q = 0; q < MY; q++) {
        int r = h * MY + q;
        roff[q] = (r / NM) * 2048 + (MS + r % NM) * 128;
        acc[q] = 0ull;
    }
    for (int pp = 0; pp < 64; pp += 2) {
        u64 w01 = *(const u64*)&Wbuf[pp * 256 + 2 * k];
        u64 w23 = *(const u64*)&Wbuf[(pp + 1) * 256 + 2 * k];
#pragma unroll
        for (int q = 0; q < MY; q++) {
            ulonglong2 mv = *(const ulonglong2*)&msgS[roff[q] + 2 * pp];
            fma2(acc[q], mv.x, w01);
            fma2(acc[q], mv.y, w23);
        }
    }
    __syncthreads();  // all reads of these rows complete before in-place write
#pragma unroll
    for (int q = 0; q < MY; q++)
        msgS[roff[q] + k] = hsum2(acc[q]) * 0.08838834764831845f;
}

__global__ void __launch_bounds__(512) k_fused(
    int t, const float* __restrict__ W_lin,
    const float* __restrict__ Wp1, const float* __restrict__ Wp2,
    const float* __restrict__ Wp3, const float* __restrict__ W_prodlin,
    const int* __restrict__ edge_index) {
    extern __shared__ float sm[];
    float* msgS = sm;            // 16384
    float* Wbuf = sm + 16384;    // 16384
    float* bS   = sm + 32768;    // 1024
    int tid = threadIdx.x;
    int k = tid & 127, h = tid >> 7, lane = tid & 31;
    int nb = blockIdx.x * 8;

    // ---- phase 1: gather (quarter h handles nodes 2h, 2h+1), prefetched ----
    for (int step = 0; step < 2; step++) {
        int nl = 2 * h + step;
        int n = nb + nl;
        int lo = d_offsets[n], hi = d_offsets[n + 1];
        float acc[16];
#pragma unroll
        for (int m = 0; m < 16; m++) acc[m] = 0.f;
        int e = 0, j = 0;
        if (lo < hi) { e = d_perm[lo]; j = edge_index[e]; }
        for (int p = lo; p < hi; p++) {
            int e_cur = e, j_cur = j;
            if (p + 1 < hi) { e = d_perm[p + 1]; j = edge_index[e]; }
            float shl = (lane < 16) ? d_sh[e_cur * 16 + lane] : 0.f;
            float u = d_up[j_cur * CH + k];
            const float* tp = d_tpw + (size_t)e_cur * 512;
            float v0 = u * tp[k];
            float v1 = u * tp[CH + k];
            float v2 = u * tp[2 * CH + k];
            float v3 = u * tp[3 * CH + k];
            acc[0] += __shfl_sync(0xffffffffu, shl, 0) * v0;
#pragma unroll
            for (int m = 1; m < 4; m++) acc[m] += __shfl_sync(0xffffffffu, shl, m) * v1;
#pragma unroll
            for (int m = 4; m < 9; m++) acc[m] += __shfl_sync(0xffffffffu, shl, m) * v2;
#pragma unroll
            for (int m = 9; m < 16; m++) acc[m] += __shfl_sync(0xffffffffu, shl, m) * v3;
        }
#pragma unroll
        for (int m = 0; m < 16; m++)
            msgS[nl * 2048 + m * 128 + k] = acc[m] * 0.1f;
    }
    __syncthreads();

    // ---- phase 2: A = msg @ W_lin[l], in place (msgS becomes A) ----
    const float* WL = W_lin + (size_t)t * 4 * CH * CH;
    load_w_pairs(Wbuf, WL, tid, 512);
    __syncthreads();
    wlin_group<1, 0>(msgS, Wbuf, k, h);

    load_w_pairs(Wbuf, WL + 1 * CH * CH, tid, 512);
    __syncthreads();
    wlin_group<3, 1>(msgS, Wbuf, k, h);

    load_w_pairs(Wbuf, WL + 2 * CH * CH, tid, 512);
    __syncthreads();
    wlin_group<5, 4>(msgS, Wbuf, k, h);

    load_w_pairs(Wbuf, WL + 3 * CH * CH, tid, 512);
    __syncthreads();
    wlin_group<7, 9>(msgS, Wbuf, k, h);
    __syncthreads();  // A fully written, visible to all

    // ---- phase 3a: nonlinearity -> b (quarter h owns nodes 2h, 2h+1) ----
    for (int nn = 0; nn < 2; nn++) {
        int nl = 2 * h + nn;
        int n = nb + nl;
        const float* Ar = msgS + nl * 2048;
        float A0 = Ar[k];
        float i0 = A0 * A0, i1 = 0.f, i2 = 0.f, i3 = 0.f;
#pragma unroll
        for (int m = 1; m < 4; m++) { float a = Ar[m * 128 + k]; i1 += a * a; }
#pragma unroll
        for (int m = 4; m < 9; m++) { float a = Ar[m * 128 + k]; i2 += a * a; }
#pragma unroll
        for (int m = 9; m < 16; m++) { float a = Ar[m * 128 + k]; i3 += a * a; }
        int s = d_species[n];
        const float* p1 = Wp1 + ((size_t)t * NZ + s) * CH;
        const float* p2 = Wp2 + ((size_t)t * NZ + s) * 4 * CH;
        const float* p3 = Wp3 + ((size_t)t * NZ + s) * 4 * CH;
        float s2 = p2[k] * i0 + p2[CH + k] * i1 + p2[2 * CH + k] * i2 + p2[3 * CH + k] * i3;
        float s3v = p3[k] * i0 + p3[CH + k] * i1 + p3[2 * CH + k] * i2 + p3[3 * CH + k] * i3;
        bS[nl * 128 + k] = p1[k] * A0 + s2 + s3v * A0;
    }
    load_w_pairs(Wbuf, W_prodlin + t * CH * CH, tid, 512);
    __syncthreads();

    // ---- phase 3b: nf = b @ Wprod / sqrt(128) + scb ----
    float* nfo = (t == 0) ? d_nfB : d_nfA;
    {
        int nl0 = 2 * h, nl1 = 2 * h + 1;
        u64 a0 = 0ull, a1 = 0ull;
        for (int pp = 0; pp < 64; pp += 2) {
            u64 w01 = *(const u64*)&Wbuf[pp * 256 + 2 * k];
            u64 w23 = *(const u64*)&Wbuf[(pp + 1) * 256 + 2 * k];
            ulonglong2 b0 = *(const ulonglong2*)&bS[nl0 * 128 + 2 * pp];
            ulonglong2 b1 = *(const ulonglong2*)&bS[nl1 * 128 + 2 * pp];
            fma2(a0, b0.x, w01); fma2(a0, b0.y, w23);
            fma2(a1, b1.x, w01); fma2(a1, b1.y, w23);
        }
        nfo[(nb + nl0) * CH + k] = hsum2(a0) * 0.08838834764831845f +
                                   d_scb[(nb + nl0) * CH + k];
        nfo[(nb + nl1) * CH + k] = hsum2(a1) * 0.08838834764831845f +
                                   d_scb[(nb + nl1) * CH + k];
    }
}

// ---------------- graph mean pooling ----------------
__global__ void k_env(const int* __restrict__ batch_idx, float* __restrict__ out) {
    int tid = blockIdx.x * blockDim.x + threadIdx.x;
    if (tid >= NN * CH) return;
    int n = tid >> 7, k = tid & 127;
    int g = batch_idx[n];
    atomicAdd(&out[g * CH + k], d_nfA[tid]);
    if (k == 0) atomicAdd(&d_gcnt[g], 1.f);
}

__global__ void k_div(float* __restrict__ out) {
    int i = blockIdx.x * blockDim.x + threadIdx.x;
    if (i >= NG * CH) return;
    int g = i >> 7;
    out[i] /= fmaxf(d_gcnt[g], 1.f);
}

// ---------------- launcher ----------------
extern "C" void kernel_launch(void* const* d_in, const int* in_sizes, int n_in,
                              void* d_out, int out_size) {
    const float* x        = (const float*)d_in[0];
    const float* pos      = (const float*)d_in[1];
    const float* W_embed  = (const float*)d_in[2];
    const float* W_up     = (const float*)d_in[3];
    const float* Wr0      = (const float*)d_in[4];
    const float* Wr1      = (const float*)d_in[5];
    const float* Wr2      = (const float*)d_in[6];
    const float* Wr3      = (const float*)d_in[7];
    const float* W_lin    = (const float*)d_in[8];
    const float* W_skip   = (const float*)d_in[9];
    const float* Wp1      = (const float*)d_in[10];
    const float* Wp2      = (const float*)d_in[11];
    const float* Wp3      = (const float*)d_in[12];
    const float* W_prodlin= (const float*)d_in[13];
    const int*   edge_index = (const int*)d_in[14];
    const int*   batch_idx  = (const int*)d_in[15];
    float* out = (float*)d_out;

    const int SM_UP    = (16384 + 4096) * 4;
    const int SM_SC    = (16384 + 2048) * 4;
    const int SM_RAD   = 57600 * 4;   // 230400 B
    const int SM_FUSED = 33792 * 4;   // 132 KB
    cudaFuncSetAttribute(k_up,     cudaFuncAttributeMaxDynamicSharedMemorySize, SM_UP);
    cudaFuncSetAttribute(k_sc,     cudaFuncAttributeMaxDynamicSharedMemorySize, SM_SC);
    cudaFuncSetAttribute(k_radial, cudaFuncAttributeMaxDynamicSharedMemorySize, SM_RAD);
    cudaFuncSetAttribute(k_fused,  cudaFuncAttributeMaxDynamicSharedMemorySize, SM_FUSED);

    k_zero<<<(NN + 255) / 256, 256>>>();
    k_node_init<<<(NN * CH) / 256, 256>>>(x, W_embed);
    k_edge_geom<<<NE / 256, 256>>>(pos, edge_index);
    // radial t=0 at launch slot 4 so ncu profiles it (validate L3 edge-pack)
    k_radial<<<NE / 128, 512, SM_RAD>>>(0, Wr0, Wr1, Wr2, Wr3);
    k_scan<<<1, 1024>>>();
    k_scatter<<<NE / 256, 256>>>(edge_index);

    for (int t = 0; t < 2; t++) {
        k_up<<<NN / 32, 256, SM_UP>>>(t, W_up);
        k_sc<<<dim3(NN / 16, NZ), 128, SM_SC>>>(t, W_skip);
        if (t == 1)
            k_radial<<<NE / 128, 512, SM_RAD>>>(t, Wr0, Wr1, Wr2, Wr3);
        k_fused<<<NN / 8, 512, SM_FUSED>>>(t, W_lin, Wp1, Wp2, Wp3,
                                           W_prodlin, edge_index);
    }

    cudaMemsetAsync(d_out, 0, (size_t)out_size * sizeof(float));
    k_env<<<(NN * CH) / 256, 256>>>(batch_idx, out);
    k_div<<<(NG * CH + 255) / 256, 256>>>(out);
}